// round 1
// baseline (speedup 1.0000x reference)
#include <cuda_runtime.h>
#include <math.h>

// Problem dims
#define BB    64
#define TT    300
#define CONDD 64
#define OUTD  72
#define HH    1024
#define H4    256
#define H2    512
#define G3    3072
#define MR    (BB*TT)          // 19200 rows
#define NB_GRU 128             // persistent CTAs for recurrence (<= 148 SMs)

// ---------------- scratch (static device globals; no allocation) ----------------
__device__ float g_h1 [MR * H4];                 // encoder hidden scratch
__device__ float g_x0 [(size_t)MR * HH];         // encoder output / layer0 input
__device__ float g_y  [(size_t)MR * 2 * HH];     // GRU layer output (reused)
__device__ float g_gif[(size_t)MR * G3];         // gi forward
__device__ float g_gib[(size_t)MR * G3];         // gi backward
__device__ float g_h  [2][2][BB * HH];           // [dir][pingpong][b*H+j]
__device__ unsigned int g_bar_count;
__device__ unsigned int g_bar_gen;

// ---------------- packed f32x2 helpers (Blackwell FFMA2) ----------------
__device__ __forceinline__ unsigned long long ffma2(unsigned long long a,
                                                    unsigned long long b,
                                                    unsigned long long c) {
    unsigned long long d;
    asm("fma.rn.f32x2 %0, %1, %2, %3;" : "=l"(d) : "l"(a), "l"(b), "l"(c));
    return d;
}
__device__ __forceinline__ unsigned long long pack2(float x, float y) {
    unsigned long long d;
    asm("mov.b64 %0, {%1, %2};" : "=l"(d) : "f"(x), "f"(y));
    return d;
}
__device__ __forceinline__ void unpack2(unsigned long long p, float& lo, float& hi) {
    asm("mov.b64 {%0, %1}, %2;" : "=f"(lo), "=f"(hi) : "l"(p));
}

// ---------------- software grid barrier (graph-capturable) ----------------
__device__ __forceinline__ void grid_barrier(unsigned int nb) {
    __syncthreads();
    if (threadIdx.x == 0) {
        __threadfence();
        unsigned int gen = *(volatile unsigned int*)&g_bar_gen;
        unsigned int arrived = atomicAdd(&g_bar_count, 1u);
        if (arrived == nb - 1u) {
            g_bar_count = 0u;
            __threadfence();
            atomicExch(&g_bar_gen, gen + 1u);
        } else {
            while (*(volatile unsigned int*)&g_bar_gen == gen) { __nanosleep(40); }
        }
        __threadfence();
    }
    __syncthreads();
}

// ---------------- generic NT GEMM: C[M,N] = A[M,K] @ W[N,K]^T + bias, opt leaky ----------------
// BM=128, BN=128, BK=8, 256 threads, 8x8 microtile with FFMA2 pairs along N.
// Requires: M % 128 == 0, N % 128 == 0, K % 8 == 0.
__global__ void __launch_bounds__(256) gemm_nt_kernel(
    const float* __restrict__ A, const float* __restrict__ W,
    const float* __restrict__ bias, float* __restrict__ C,
    int K, int ldc, int coff, int leaky)
{
    __shared__ float As[8][128];
    __shared__ float Bs[8][128];

    const int tid = threadIdx.x;
    const int bx = blockIdx.x, by = blockIdx.y;
    const int tx = tid & 15, ty = tid >> 4;
    const int r  = tid >> 1;
    const int cq = (tid & 1) * 4;

    const float* Ap = A + (size_t)(by * 128 + r) * K + cq;
    const float* Wp = W + (size_t)(bx * 128 + r) * K + cq;

    unsigned long long acc[8][4];
#pragma unroll
    for (int m = 0; m < 8; m++)
#pragma unroll
        for (int p = 0; p < 4; p++) acc[m][p] = 0ULL;

    const int nkt = K >> 3;
    for (int kt = 0; kt < nkt; kt++) {
        __syncthreads();
        float4 av = *(const float4*)(Ap + kt * 8);
        float4 wv = *(const float4*)(Wp + kt * 8);
        As[cq + 0][r] = av.x; As[cq + 1][r] = av.y; As[cq + 2][r] = av.z; As[cq + 3][r] = av.w;
        Bs[cq + 0][r] = wv.x; Bs[cq + 1][r] = wv.y; Bs[cq + 2][r] = wv.z; Bs[cq + 3][r] = wv.w;
        __syncthreads();
#pragma unroll
        for (int k = 0; k < 8; k++) {
            float4 a0 = *(const float4*)&As[k][ty * 8];
            float4 a1 = *(const float4*)&As[k][ty * 8 + 4];
            ulonglong2 bq0 = *(const ulonglong2*)&Bs[k][tx * 8];
            ulonglong2 bq1 = *(const ulonglong2*)&Bs[k][tx * 8 + 4];
            float a[8] = {a0.x, a0.y, a0.z, a0.w, a1.x, a1.y, a1.z, a1.w};
#pragma unroll
            for (int m = 0; m < 8; m++) {
                unsigned long long ap = pack2(a[m], a[m]);
                acc[m][0] = ffma2(ap, bq0.x, acc[m][0]);
                acc[m][1] = ffma2(ap, bq0.y, acc[m][1]);
                acc[m][2] = ffma2(ap, bq1.x, acc[m][2]);
                acc[m][3] = ffma2(ap, bq1.y, acc[m][3]);
            }
        }
    }

#pragma unroll
    for (int m = 0; m < 8; m++) {
        const int row = by * 128 + ty * 8 + m;
        float* crow = C + (size_t)row * ldc + coff;
#pragma unroll
        for (int p = 0; p < 4; p++) {
            float lo, hi;
            unpack2(acc[m][p], lo, hi);
            const int nn = bx * 128 + tx * 8 + p * 2;
            float v0 = lo + bias[nn];
            float v1 = hi + bias[nn + 1];
            if (leaky) {
                v0 = (v0 >= 0.f) ? v0 : 0.2f * v0;
                v1 = (v1 >= 0.f) ? v1 : 0.2f * v1;
            }
            crow[nn]     = v0;
            crow[nn + 1] = v1;
        }
    }
}

// ---------------- zero hidden state ----------------
__global__ void zero_h_kernel() {
    float* p = &g_h[0][0][0];
    for (int i = blockIdx.x * blockDim.x + threadIdx.x; i < 4 * BB * HH;
         i += gridDim.x * blockDim.x)
        p[i] = 0.f;
}

// ---------------- persistent bidirectional GRU layer ----------------
// 128 CTAs: blockIdx 0..63 = fwd (16 hidden units each), 64..127 = bwd.
// Per step: C[64b x 48gates] = H[64,1024] @ Whh_slice[48,1024]^T (FFMA2, pairs along K),
// then pointwise GRU epilogue; grid barrier between steps.
__global__ void __launch_bounds__(256, 1) gru_layer_kernel(
    const float* __restrict__ gif, const float* __restrict__ gib,
    const float* __restrict__ whhf, const float* __restrict__ bhhf,
    const float* __restrict__ whhb, const float* __restrict__ bhhb,
    float* __restrict__ y)
{
    __shared__ float Hs[64][68];   // [b][k] tile, padded
    __shared__ float Ws[48][68];   // [gate-row][k] tile, padded
    __shared__ float Cs[64][48];   // gh result

    const int tid = threadIdx.x;
    const int dir = blockIdx.x >> 6;
    const int j0  = (blockIdx.x & 63) << 4;   // 16 hidden units per CTA

    const float* gi  = dir ? gib  : gif;
    const float* whh = dir ? whhb : whhf;
    const float* bhh = dir ? bhhb : bhhf;

    const int b0 = (tid >> 3) << 1;   // 2 batches per thread
    const int n0 = (tid & 7) * 6;     // 6 gate-cols per thread (of 48)

    for (int s = 0; s < TT; s++) {
        const int t_idx = dir ? (TT - 1 - s) : s;
        const int rb = s & 1;
        const float* hprev = g_h[dir][rb];
        float*       hnext = g_h[dir][rb ^ 1];

        unsigned long long acc[2][6];
#pragma unroll
        for (int i = 0; i < 2; i++)
#pragma unroll
            for (int c = 0; c < 6; c++) acc[i][c] = 0ULL;

        for (int kt = 0; kt < 16; kt++) {
            __syncthreads();
            {   // load H tile: 64 b x 64 k, coalesced
                const int f = tid & 15, brow = tid >> 4;
#pragma unroll
                for (int i = 0; i < 4; i++) {
                    const int b = brow + (i << 4);
                    float4 v = *(const float4*)(hprev + b * HH + kt * 64 + f * 4);
                    *(float4*)&Hs[b][f * 4] = v;
                }
            }
            {   // load W tile: 48 gate-rows x 64 k
#pragma unroll
                for (int p = 0; p < 3; p++) {
                    const int fidx = tid + (p << 8);
                    const int row  = fidx >> 4;      // 0..47
                    const int kv   = fidx & 15;
                    const int grow = ((row >> 4) << 10) + j0 + (row & 15);
                    float4 v = *(const float4*)(whh + (size_t)grow * HH + kt * 64 + kv * 4);
                    *(float4*)&Ws[row][kv * 4] = v;
                }
            }
            __syncthreads();
#pragma unroll
            for (int kq = 0; kq < 32; kq++) {
                unsigned long long h0 = *(const unsigned long long*)&Hs[b0][kq * 2];
                unsigned long long h1 = *(const unsigned long long*)&Hs[b0 + 1][kq * 2];
#pragma unroll
                for (int c = 0; c < 6; c++) {
                    unsigned long long w = *(const unsigned long long*)&Ws[n0 + c][kq * 2];
                    acc[0][c] = ffma2(h0, w, acc[0][c]);
                    acc[1][c] = ffma2(h1, w, acc[1][c]);
                }
            }
        }

        // horizontal reduce packed K-pairs into Cs
#pragma unroll
        for (int i = 0; i < 2; i++)
#pragma unroll
            for (int c = 0; c < 6; c++) {
                float lo, hi;
                unpack2(acc[i][c], lo, hi);
                Cs[b0 + i][n0 + c] = lo + hi;
            }
        __syncthreads();

        // GRU pointwise epilogue: 64 b x 16 j = 1024 items
#pragma unroll
        for (int p = 0; p < 4; p++) {
            const int idx = tid + (p << 8);
            const int b = idx >> 4, jj = idx & 15;
            const int j = j0 + jj;
            const size_t gbase = (size_t)(b * TT + t_idx) * G3;
            const float cr = Cs[b][jj]      + bhh[j];
            const float cz = Cs[b][16 + jj] + bhh[HH + j];
            const float cn = Cs[b][32 + jj] + bhh[2 * HH + j];
            const float rr = 1.f / (1.f + expf(-(gi[gbase + j] + cr)));
            const float zz = 1.f / (1.f + expf(-(gi[gbase + HH + j] + cz)));
            const float nn = tanhf(gi[gbase + 2 * HH + j] + rr * cn);
            const float hp = hprev[b * HH + j];
            const float hn = (1.f - zz) * nn + zz * hp;
            hnext[b * HH + j] = hn;
            y[(size_t)(b * TT + t_idx) * (2 * HH) + dir * HH + j] = hn;
        }
        grid_barrier(NB_GRU);
    }
}

// ---------------- final mean over (T, 2H) per batch ----------------
__global__ void mean_kernel(const float* __restrict__ y, float* __restrict__ out) {
    const int b = blockIdx.x;
    const int tid = threadIdx.x;
    const size_t base = (size_t)b * TT * 2 * HH;
    float s = 0.f;
    for (int i = tid; i < TT * 2 * HH; i += 256) s += y[base + i];
    __shared__ float red[256];
    red[tid] = s;
    __syncthreads();
    for (int o = 128; o > 0; o >>= 1) {
        if (tid < o) red[tid] += red[tid + o];
        __syncthreads();
    }
    if (tid == 0) out[b] = red[0] / (float)(TT * 2 * HH);
}

// ---------------- launcher ----------------
extern "C" void kernel_launch(void* const* d_in, const int* in_sizes, int n_in,
                              void* d_out, int out_size)
{
    const float* cond     = (const float*)d_in[0];
    const float* input    = (const float*)d_in[1];
    const float* ce_w1    = (const float*)d_in[2];
    const float* ce_b1    = (const float*)d_in[3];
    const float* ce_w2    = (const float*)d_in[4];
    const float* ce_b2    = (const float*)d_in[5];
    const float* me_w1    = (const float*)d_in[6];
    const float* me_b1    = (const float*)d_in[7];
    const float* me_w2    = (const float*)d_in[8];
    const float* me_b2    = (const float*)d_in[9];
    const float* w_ih_l0f = (const float*)d_in[10];
    const float* w_hh_l0f = (const float*)d_in[11];
    const float* b_ih_l0f = (const float*)d_in[12];
    const float* b_hh_l0f = (const float*)d_in[13];
    const float* w_ih_l0b = (const float*)d_in[14];
    const float* w_hh_l0b = (const float*)d_in[15];
    const float* b_ih_l0b = (const float*)d_in[16];
    const float* b_hh_l0b = (const float*)d_in[17];
    const float* w_ih_l1f = (const float*)d_in[18];
    const float* w_hh_l1f = (const float*)d_in[19];
    const float* b_ih_l1f = (const float*)d_in[20];
    const float* b_hh_l1f = (const float*)d_in[21];
    const float* w_ih_l1b = (const float*)d_in[22];
    const float* w_hh_l1b = (const float*)d_in[23];
    const float* b_ih_l1b = (const float*)d_in[24];
    const float* b_hh_l1b = (const float*)d_in[25];
    float* out = (float*)d_out;

    void* p;
    cudaGetSymbolAddress(&p, g_h1);  float* s_h1  = (float*)p;
    cudaGetSymbolAddress(&p, g_x0);  float* s_x0  = (float*)p;
    cudaGetSymbolAddress(&p, g_y);   float* s_y   = (float*)p;
    cudaGetSymbolAddress(&p, g_gif); float* s_gif = (float*)p;
    cudaGetSymbolAddress(&p, g_gib); float* s_gib = (float*)p;

    dim3 blk(256);

    // Encoders: cond branch then input branch, concat into g_x0
    gemm_nt_kernel<<<dim3(H4 / 128, MR / 128), blk>>>(cond,  ce_w1, ce_b1, s_h1, CONDD, H4,  0,   1);
    gemm_nt_kernel<<<dim3(H2 / 128, MR / 128), blk>>>(s_h1,  ce_w2, ce_b2, s_x0, H4,    HH,  0,   0);
    gemm_nt_kernel<<<dim3(H4 / 128, MR / 128), blk>>>(input, me_w1, me_b1, s_h1, OUTD,  H4,  0,   1);
    gemm_nt_kernel<<<dim3(H2 / 128, MR / 128), blk>>>(s_h1,  me_w2, me_b2, s_x0, H4,    HH,  512, 0);

    // Layer 0: gi projections (bias = b_ih folded), then recurrence
    gemm_nt_kernel<<<dim3(G3 / 128, MR / 128), blk>>>(s_x0, w_ih_l0f, b_ih_l0f, s_gif, HH, G3, 0, 0);
    gemm_nt_kernel<<<dim3(G3 / 128, MR / 128), blk>>>(s_x0, w_ih_l0b, b_ih_l0b, s_gib, HH, G3, 0, 0);
    zero_h_kernel<<<64, 256>>>();
    gru_layer_kernel<<<NB_GRU, 256>>>(s_gif, s_gib, w_hh_l0f, b_hh_l0f, w_hh_l0b, b_hh_l0b, s_y);

    // Layer 1: gi from layer-0 output (K=2048), then recurrence (overwrites s_y in place)
    gemm_nt_kernel<<<dim3(G3 / 128, MR / 128), blk>>>(s_y, w_ih_l1f, b_ih_l1f, s_gif, 2 * HH, G3, 0, 0);
    gemm_nt_kernel<<<dim3(G3 / 128, MR / 128), blk>>>(s_y, w_ih_l1b, b_ih_l1b, s_gib, 2 * HH, G3, 0, 0);
    zero_h_kernel<<<64, 256>>>();
    gru_layer_kernel<<<NB_GRU, 256>>>(s_gif, s_gib, w_hh_l1f, b_hh_l1f, w_hh_l1b, b_hh_l1b, s_y);

    // Final mean per batch
    mean_kernel<<<BB, 256>>>(s_y, out);
}

// round 3
// speedup vs baseline: 2.9987x; 2.9987x over previous
#include <cuda_runtime.h>
#include <cuda_bf16.h>
#include <math.h>
#include <stdint.h>

#define BB    64
#define TT    300
#define CONDD 64
#define OUTD  72
#define HH    1024
#define H4    256
#define H2    512
#define G3    3072
#define MR    (BB*TT)

typedef __nv_bfloat16 bf16;

// ---------------- device globals (no allocation allowed) ----------------
__device__ float g_h1 [MR * H4];
__device__ float g_x0 [(size_t)MR * HH];
__device__ float g_y  [(size_t)MR * 2 * HH];
__device__ bf16  g_xhi[(size_t)MR * HH],     g_xlo[(size_t)MR * HH];
__device__ bf16  g_yhi[(size_t)MR * 2 * HH], g_ylo[(size_t)MR * 2 * HH];
__device__ float g_gif[(size_t)MR * G3], g_gib[(size_t)MR * G3];
__device__ float g_hf [2][2][BB * HH];
__device__ bf16  g_hhi[2][2][BB * HH], g_hlo[2][2][BB * HH];
// w_ih splits: l0f@0, l0b@G3*HH, l1f@2*G3*HH (K=2048), l1b@4*G3*HH
__device__ bf16  g_wihhi[(size_t)6 * G3 * HH], g_wihlo[(size_t)6 * G3 * HH];
// w_hh splits: l0f@0, l0b@1, l1f@2, l1b@3 (each G3*HH)
__device__ bf16  g_whhhi[(size_t)4 * G3 * HH], g_whhlo[(size_t)4 * G3 * HH];
__device__ unsigned int g_barc[2];
__device__ unsigned int g_barg[2];

// ---------------- small helpers ----------------
__device__ __forceinline__ uint32_t saddr(const void* p) {
    return (uint32_t)__cvta_generic_to_shared(p);
}
__device__ __forceinline__ void cpa16(uint32_t s, const void* g) {
    asm volatile("cp.async.cg.shared.global [%0], [%1], 16;" :: "r"(s), "l"(g));
}
__device__ __forceinline__ void cpa_commit() { asm volatile("cp.async.commit_group;"); }
__device__ __forceinline__ void cpa_wait1() { asm volatile("cp.async.wait_group 1;"); }
__device__ __forceinline__ void cpa_wait0() { asm volatile("cp.async.wait_group 0;"); }

__device__ __forceinline__ void ldmx4(uint32_t* r, uint32_t a) {
    asm volatile("ldmatrix.sync.aligned.m8n8.x4.shared.b16 {%0,%1,%2,%3}, [%4];"
                 : "=r"(r[0]), "=r"(r[1]), "=r"(r[2]), "=r"(r[3]) : "r"(a));
}
__device__ __forceinline__ void ldmx2(uint32_t* r, uint32_t a) {
    asm volatile("ldmatrix.sync.aligned.m8n8.x2.shared.b16 {%0,%1}, [%2];"
                 : "=r"(r[0]), "=r"(r[1]) : "r"(a));
}
__device__ __forceinline__ void mma_bf16(float* c, const uint32_t* a, const uint32_t* b) {
    asm volatile("mma.sync.aligned.m16n8k16.row.col.f32.bf16.bf16.f32 "
                 "{%0,%1,%2,%3}, {%4,%5,%6,%7}, {%8,%9}, {%0,%1,%2,%3};"
                 : "+f"(c[0]), "+f"(c[1]), "+f"(c[2]), "+f"(c[3])
                 : "r"(a[0]), "r"(a[1]), "r"(a[2]), "r"(a[3]), "r"(b[0]), "r"(b[1]));
}

// FFMA2 helpers for small encoder GEMMs
__device__ __forceinline__ unsigned long long ffma2(unsigned long long a,
                                                    unsigned long long b,
                                                    unsigned long long c) {
    unsigned long long d;
    asm("fma.rn.f32x2 %0, %1, %2, %3;" : "=l"(d) : "l"(a), "l"(b), "l"(c));
    return d;
}
__device__ __forceinline__ unsigned long long pack2(float x, float y) {
    unsigned long long d;
    asm("mov.b64 %0, {%1, %2};" : "=l"(d) : "f"(x), "f"(y));
    return d;
}
__device__ __forceinline__ void unpack2(unsigned long long p, float& lo, float& hi) {
    asm("mov.b64 {%0, %1}, %2;" : "=f"(lo), "=f"(hi) : "l"(p));
}

// per-direction software grid barrier (graph-capturable)
__device__ __forceinline__ void dir_barrier(int dir, unsigned int nb) {
    __syncthreads();
    if (threadIdx.x == 0) {
        __threadfence();
        unsigned int gen = *(volatile unsigned int*)&g_barg[dir];
        unsigned int arrived = atomicAdd(&g_barc[dir], 1u);
        if (arrived == nb - 1u) {
            g_barc[dir] = 0u;
            __threadfence();
            atomicExch(&g_barg[dir], gen + 1u);
        } else {
            while (*(volatile unsigned int*)&g_barg[dir] == gen) { __nanosleep(40); }
        }
        __threadfence();
    }
    __syncthreads();
}

// ---------------- split f32 -> bf16 hi/lo ----------------
__global__ void split_kernel(const float* __restrict__ s, bf16* __restrict__ hi,
                             bf16* __restrict__ lo, size_t n) {
    for (size_t i = blockIdx.x * (size_t)blockDim.x + threadIdx.x; i < n;
         i += (size_t)gridDim.x * blockDim.x) {
        float v = s[i];
        bf16 h = __float2bfloat16(v);
        hi[i] = h;
        lo[i] = __float2bfloat16(v - __bfloat162float(h));
    }
}

// ---------------- encoder FFMA2 GEMM (small K) ----------------
__global__ void __launch_bounds__(256) gemm_nt_kernel(
    const float* __restrict__ A, const float* __restrict__ W,
    const float* __restrict__ bias, float* __restrict__ C,
    int K, int ldc, int coff, int leaky)
{
    __shared__ float As[8][128];
    __shared__ float Bs[8][128];
    const int tid = threadIdx.x;
    const int bx = blockIdx.x, by = blockIdx.y;
    const int tx = tid & 15, ty = tid >> 4;
    const int r  = tid >> 1;
    const int cq = (tid & 1) * 4;
    const float* Ap = A + (size_t)(by * 128 + r) * K + cq;
    const float* Wp = W + (size_t)(bx * 128 + r) * K + cq;

    unsigned long long acc[8][4];
#pragma unroll
    for (int m = 0; m < 8; m++)
#pragma unroll
        for (int p = 0; p < 4; p++) acc[m][p] = 0ULL;

    const int nkt = K >> 3;
    for (int kt = 0; kt < nkt; kt++) {
        __syncthreads();
        float4 av = *(const float4*)(Ap + kt * 8);
        float4 wv = *(const float4*)(Wp + kt * 8);
        As[cq + 0][r] = av.x; As[cq + 1][r] = av.y; As[cq + 2][r] = av.z; As[cq + 3][r] = av.w;
        Bs[cq + 0][r] = wv.x; Bs[cq + 1][r] = wv.y; Bs[cq + 2][r] = wv.z; Bs[cq + 3][r] = wv.w;
        __syncthreads();
#pragma unroll
        for (int k = 0; k < 8; k++) {
            float4 a0 = *(const float4*)&As[k][ty * 8];
            float4 a1 = *(const float4*)&As[k][ty * 8 + 4];
            ulonglong2 bq0 = *(const ulonglong2*)&Bs[k][tx * 8];
            ulonglong2 bq1 = *(const ulonglong2*)&Bs[k][tx * 8 + 4];
            float a[8] = {a0.x, a0.y, a0.z, a0.w, a1.x, a1.y, a1.z, a1.w};
#pragma unroll
            for (int m = 0; m < 8; m++) {
                unsigned long long ap = pack2(a[m], a[m]);
                acc[m][0] = ffma2(ap, bq0.x, acc[m][0]);
                acc[m][1] = ffma2(ap, bq0.y, acc[m][1]);
                acc[m][2] = ffma2(ap, bq1.x, acc[m][2]);
                acc[m][3] = ffma2(ap, bq1.y, acc[m][3]);
            }
        }
    }
#pragma unroll
    for (int m = 0; m < 8; m++) {
        const int row = by * 128 + ty * 8 + m;
        float* crow = C + (size_t)row * ldc + coff;
#pragma unroll
        for (int p = 0; p < 4; p++) {
            float lo, hi;
            unpack2(acc[m][p], lo, hi);
            const int nn = bx * 128 + tx * 8 + p * 2;
            float v0 = lo + bias[nn];
            float v1 = hi + bias[nn + 1];
            if (leaky) {
                v0 = (v0 >= 0.f) ? v0 : 0.2f * v0;
                v1 = (v1 >= 0.f) ? v1 : 0.2f * v1;
            }
            crow[nn]     = v0;
            crow[nn + 1] = v1;
        }
    }
}

// ---------------- bf16x3 tensor-core GEMM: C = A@W^T + bias ----------------
// BM=128, BN=128, BK=32, 256 thr, 8 warps (2m x 4n), warp tile 64x32.
// A,W pre-split into bf16 hi/lo. smem: 4 x [2][128][40] bf16 = 81920 B dynamic.
__global__ void __launch_bounds__(256) gemm_bf16x3(
    const bf16* __restrict__ Ahi, const bf16* __restrict__ Alo,
    const bf16* __restrict__ Whi, const bf16* __restrict__ Wlo,
    const float* __restrict__ bias, float* __restrict__ C, int K, int ldc)
{
    extern __shared__ bf16 sm_[];
    bf16* sAh = sm_;
    bf16* sAl = sm_ + 10240;
    bf16* sBh = sm_ + 20480;
    bf16* sBl = sm_ + 30720;

    const int tid = threadIdx.x, lane = tid & 31, warp = tid >> 5;
    const int wm = warp & 1, wn = warp >> 1;          // m0 = wm*64, n0 = wn*32
    const int bx = blockIdx.x, by = blockIdx.y;

    float acc[4][4][4];
#pragma unroll
    for (int mt = 0; mt < 4; mt++)
#pragma unroll
        for (int nt = 0; nt < 4; nt++)
#pragma unroll
            for (int i = 0; i < 4; i++) acc[mt][nt][i] = 0.f;

    const int nkt = K >> 5;

    // stage-load macro behavior via loop
    for (int kt = 0; kt <= 0; kt++) {  // prologue load stage 0
#pragma unroll
        for (int c0 = 0; c0 < 2; c0++) {
            int c = tid + c0 * 256;
            int row = c >> 2, kc = c & 3;
            size_t ga = (size_t)(by * 128 + row) * K + kc * 8;
            cpa16(saddr(sAh + row * 40 + kc * 8), Ahi + ga);
            cpa16(saddr(sAl + row * 40 + kc * 8), Alo + ga);
            size_t gb = (size_t)(bx * 128 + row) * K + kc * 8;
            cpa16(saddr(sBh + row * 40 + kc * 8), Whi + gb);
            cpa16(saddr(sBl + row * 40 + kc * 8), Wlo + gb);
        }
        cpa_commit();
    }

    for (int kt = 0; kt < nkt; kt++) {
        const int buf = (kt & 1) * 5120;
        if (kt + 1 < nkt) {
            const int nb = ((kt + 1) & 1) * 5120;
            const int ko = (kt + 1) * 32;
#pragma unroll
            for (int c0 = 0; c0 < 2; c0++) {
                int c = tid + c0 * 256;
                int row = c >> 2, kc = c & 3;
                size_t ga = (size_t)(by * 128 + row) * K + ko + kc * 8;
                cpa16(saddr(sAh + nb + row * 40 + kc * 8), Ahi + ga);
                cpa16(saddr(sAl + nb + row * 40 + kc * 8), Alo + ga);
                size_t gb = (size_t)(bx * 128 + row) * K + ko + kc * 8;
                cpa16(saddr(sBh + nb + row * 40 + kc * 8), Whi + gb);
                cpa16(saddr(sBl + nb + row * 40 + kc * 8), Wlo + gb);
            }
            cpa_commit();
            cpa_wait1();
        } else {
            cpa_wait0();
        }
        __syncthreads();

#pragma unroll
        for (int ks = 0; ks < 2; ks++) {
            const int kk = ks * 16;
            uint32_t ah[4][4], al[4][4];
#pragma unroll
            for (int mt = 0; mt < 4; mt++) {
                const int ar = wm * 64 + mt * 16 + (lane & 15);
                const int ac = kk + (lane >> 4) * 8;
                ldmx4(ah[mt], saddr(sAh + buf + ar * 40 + ac));
                ldmx4(al[mt], saddr(sAl + buf + ar * 40 + ac));
            }
            uint32_t bh[4][2], bl[4][2];
#pragma unroll
            for (int nt = 0; nt < 4; nt++) {
                const int br = wn * 32 + nt * 8 + (lane & 7);
                const int bc = kk + ((lane >> 3) & 1) * 8;
                ldmx2(bh[nt], saddr(sBh + buf + br * 40 + bc));
                ldmx2(bl[nt], saddr(sBl + buf + br * 40 + bc));
            }
#pragma unroll
            for (int mt = 0; mt < 4; mt++)
#pragma unroll
                for (int nt = 0; nt < 4; nt++) {
                    mma_bf16(acc[mt][nt], ah[mt], bh[nt]);
                    mma_bf16(acc[mt][nt], ah[mt], bl[nt]);
                    mma_bf16(acc[mt][nt], al[mt], bh[nt]);
                }
        }
        __syncthreads();
    }

    // epilogue: add bias, store f32
#pragma unroll
    for (int mt = 0; mt < 4; mt++) {
        const int r0 = by * 128 + wm * 64 + mt * 16 + (lane >> 2);
#pragma unroll
        for (int nt = 0; nt < 4; nt++) {
            const int c0 = bx * 128 + wn * 32 + nt * 8 + 2 * (lane & 3);
            const float b0 = bias[c0], b1 = bias[c0 + 1];
            C[(size_t)r0 * ldc + c0]           = acc[mt][nt][0] + b0;
            C[(size_t)r0 * ldc + c0 + 1]       = acc[mt][nt][1] + b1;
            C[(size_t)(r0 + 8) * ldc + c0]     = acc[mt][nt][2] + b0;
            C[(size_t)(r0 + 8) * ldc + c0 + 1] = acc[mt][nt][3] + b1;
        }
    }
}

// ---------------- zero hidden state ----------------
__global__ void zero_h_kernel() {
    const int n = 4 * BB * HH;
    float* pf = &g_hf[0][0][0];
    bf16* ph = &g_hhi[0][0][0];
    bf16* pl = &g_hlo[0][0][0];
    for (int i = blockIdx.x * blockDim.x + threadIdx.x; i < n;
         i += gridDim.x * blockDim.x) {
        pf[i] = 0.f;
        ph[i] = __float2bfloat16(0.f);
        pl[i] = __float2bfloat16(0.f);
    }
}

// ---------------- persistent bidirectional GRU layer (bf16x3 mma) ----------------
// 128 CTAs: 0..63 fwd, 64..127 bwd; each CTA owns 16 hidden units (48 gate rows).
// Per step: gh[64,48] = h[64,1024] @ Whh_slice[48,1024]^T via m16n8k16 bf16 x3.
__global__ void __launch_bounds__(256, 1) gru_mma_kernel(
    const float* __restrict__ gif, const float* __restrict__ gib,
    const bf16* __restrict__ whf_hi, const bf16* __restrict__ whf_lo,
    const bf16* __restrict__ whb_hi, const bf16* __restrict__ whb_lo,
    const float* __restrict__ bhhf, const float* __restrict__ bhhb,
    float* __restrict__ y, bf16* __restrict__ yhi, bf16* __restrict__ ylo)
{
    extern __shared__ bf16 sm_[];
    bf16* sAh = sm_;              // [2][64][72]
    bf16* sAl = sm_ + 9216;
    bf16* sWh = sm_ + 18432;      // [2][48][72]
    bf16* sWl = sm_ + 25344;
    float* Cs = (float*)(sm_ + 32256);  // [64][52]

    const int tid = threadIdx.x, lane = tid & 31, warp = tid >> 5;
    const int dir = blockIdx.x >> 6;
    const int j0  = (blockIdx.x & 63) << 4;
    const int wm = warp & 3, wn = warp >> 2;   // m0 = wm*16, n0 = wn*24 (3 n8 tiles)
    const int m0 = wm * 16, n0 = wn * 24;

    const float* gi  = dir ? gib   : gif;
    const bf16* whhh = dir ? whb_hi : whf_hi;
    const bf16* whhl = dir ? whb_lo : whf_lo;
    const float* bhh = dir ? bhhb  : bhhf;

    const float bh_r = bhh[j0 + (0)];  // per-thread epilogue biases loaded below
    (void)bh_r;

    for (int s = 0; s < TT; s++) {
        const int t_idx = dir ? (TT - 1 - s) : s;
        const int rb = s & 1;
        const bf16* hhi = g_hhi[dir][rb];
        const bf16* hlo = g_hlo[dir][rb];
        const float* hpf = g_hf[dir][rb];
        float* hnf = g_hf[dir][rb ^ 1];
        bf16* hnhi = g_hhi[dir][rb ^ 1];
        bf16* hnlo = g_hlo[dir][rb ^ 1];

        float acc[3][4];
#pragma unroll
        for (int nt = 0; nt < 3; nt++)
#pragma unroll
            for (int i = 0; i < 4; i++) acc[nt][i] = 0.f;

        // prologue: stage 0
        {
#pragma unroll
            for (int c0 = 0; c0 < 2; c0++) {
                int c = tid + c0 * 256;
                int row = c >> 3, kc = c & 7;
                size_t ga = (size_t)row * HH + kc * 8;
                cpa16(saddr(sAh + row * 72 + kc * 8), hhi + ga);
                cpa16(saddr(sAl + row * 72 + kc * 8), hlo + ga);
            }
            for (int c = tid; c < 384; c += 256) {
                int row = c >> 3, kc = c & 7;
                int grow = (row >> 4) * HH + j0 + (row & 15);
                size_t gw = (size_t)grow * HH + kc * 8;
                cpa16(saddr(sWh + row * 72 + kc * 8), whhh + gw);
                cpa16(saddr(sWl + row * 72 + kc * 8), whhl + gw);
            }
            cpa_commit();
        }

        for (int kt = 0; kt < 16; kt++) {
            const int abuf = (kt & 1) * 4608;
            const int wbuf = (kt & 1) * 3456;
            if (kt + 1 < 16) {
                const int an = ((kt + 1) & 1) * 4608;
                const int wn2 = ((kt + 1) & 1) * 3456;
                const int ko = (kt + 1) * 64;
#pragma unroll
                for (int c0 = 0; c0 < 2; c0++) {
                    int c = tid + c0 * 256;
                    int row = c >> 3, kc = c & 7;
                    size_t ga = (size_t)row * HH + ko + kc * 8;
                    cpa16(saddr(sAh + an + row * 72 + kc * 8), hhi + ga);
                    cpa16(saddr(sAl + an + row * 72 + kc * 8), hlo + ga);
                }
                for (int c = tid; c < 384; c += 256) {
                    int row = c >> 3, kc = c & 7;
                    int grow = (row >> 4) * HH + j0 + (row & 15);
                    size_t gw = (size_t)grow * HH + ko + kc * 8;
                    cpa16(saddr(sWh + wn2 + row * 72 + kc * 8), whhh + gw);
                    cpa16(saddr(sWl + wn2 + row * 72 + kc * 8), whhl + gw);
                }
                cpa_commit();
                cpa_wait1();
            } else {
                cpa_wait0();
            }
            __syncthreads();

#pragma unroll
            for (int ks = 0; ks < 4; ks++) {
                const int kk = ks * 16;
                uint32_t ah[4], al[4];
                const int ar = m0 + (lane & 15);
                const int ac = kk + (lane >> 4) * 8;
                ldmx4(ah, saddr(sAh + abuf + ar * 72 + ac));
                ldmx4(al, saddr(sAl + abuf + ar * 72 + ac));
#pragma unroll
                for (int nt = 0; nt < 3; nt++) {
                    const int br = n0 + nt * 8 + (lane & 7);
                    const int bc = kk + ((lane >> 3) & 1) * 8;
                    uint32_t bh[2], bl[2];
                    ldmx2(bh, saddr(sWh + wbuf + br * 72 + bc));
                    ldmx2(bl, saddr(sWl + wbuf + br * 72 + bc));
                    mma_bf16(acc[nt], ah, bh);
                    mma_bf16(acc[nt], ah, bl);
                    mma_bf16(acc[nt], al, bh);
                }
            }
            __syncthreads();
        }

        // write C frags to smem
#pragma unroll
        for (int nt = 0; nt < 3; nt++) {
            const int cr = m0 + (lane >> 2);
            const int cc = n0 + nt * 8 + 2 * (lane & 3);
            Cs[cr * 52 + cc]           = acc[nt][0];
            Cs[cr * 52 + cc + 1]       = acc[nt][1];
            Cs[(cr + 8) * 52 + cc]     = acc[nt][2];
            Cs[(cr + 8) * 52 + cc + 1] = acc[nt][3];
        }
        __syncthreads();

        // GRU pointwise epilogue: 64 b x 16 j
#pragma unroll
        for (int p = 0; p < 4; p++) {
            const int idx = tid + (p << 8);
            const int b = idx >> 4, jj = idx & 15;
            const int j = j0 + jj;
            const size_t gbase = (size_t)(b * TT + t_idx) * G3;
            const float cr = Cs[b * 52 + jj]      + bhh[j];
            const float cz = Cs[b * 52 + 16 + jj] + bhh[HH + j];
            const float cn = Cs[b * 52 + 32 + jj] + bhh[2 * HH + j];
            const float rr = 1.f / (1.f + expf(-(gi[gbase + j] + cr)));
            const float zz = 1.f / (1.f + expf(-(gi[gbase + HH + j] + cz)));
            const float nn = tanhf(gi[gbase + 2 * HH + j] + rr * cn);
            const float hp = hpf[b * HH + j];
            const float hn = (1.f - zz) * nn + zz * hp;
            hnf[b * HH + j] = hn;
            bf16 hh = __float2bfloat16(hn);
            hnhi[b * HH + j] = hh;
            hnlo[b * HH + j] = __float2bfloat16(hn - __bfloat162float(hh));
            const size_t yb = (size_t)(b * TT + t_idx) * (2 * HH) + dir * HH + j;
            y[yb] = hn;
            yhi[yb] = hh;
            ylo[yb] = __float2bfloat16(hn - __bfloat162float(hh));
        }
        dir_barrier(dir, 64);
    }
}

// ---------------- final mean ----------------
__global__ void mean_kernel(const float* __restrict__ y, float* __restrict__ out) {
    const int b = blockIdx.x;
    const int tid = threadIdx.x;
    const size_t base = (size_t)b * TT * 2 * HH;
    float s = 0.f;
    for (int i = tid; i < TT * 2 * HH; i += 256) s += y[base + i];
    __shared__ float red[256];
    red[tid] = s;
    __syncthreads();
    for (int o = 128; o > 0; o >>= 1) {
        if (tid < o) red[tid] += red[tid + o];
        __syncthreads();
    }
    if (tid == 0) out[b] = red[0] / (float)(TT * 2 * HH);
}

// ---------------- launcher ----------------
extern "C" void kernel_launch(void* const* d_in, const int* in_sizes, int n_in,
                              void* d_out, int out_size)
{
    const float* cond     = (const float*)d_in[0];
    const float* input    = (const float*)d_in[1];
    const float* ce_w1    = (const float*)d_in[2];
    const float* ce_b1    = (const float*)d_in[3];
    const float* ce_w2    = (const float*)d_in[4];
    const float* ce_b2    = (const float*)d_in[5];
    const float* me_w1    = (const float*)d_in[6];
    const float* me_b1    = (const float*)d_in[7];
    const float* me_w2    = (const float*)d_in[8];
    const float* me_b2    = (const float*)d_in[9];
    const float* w_ih_l0f = (const float*)d_in[10];
    const float* w_hh_l0f = (const float*)d_in[11];
    const float* b_ih_l0f = (const float*)d_in[12];
    const float* b_hh_l0f = (const float*)d_in[13];
    const float* w_ih_l0b = (const float*)d_in[14];
    const float* w_hh_l0b = (const float*)d_in[15];
    const float* b_ih_l0b = (const float*)d_in[16];
    const float* b_hh_l0b = (const float*)d_in[17];
    const float* w_ih_l1f = (const float*)d_in[18];
    const float* w_hh_l1f = (const float*)d_in[19];
    const float* b_ih_l1f = (const float*)d_in[20];
    const float* b_hh_l1f = (const float*)d_in[21];
    const float* w_ih_l1b = (const float*)d_in[22];
    const float* w_hh_l1b = (const float*)d_in[23];
    const float* b_ih_l1b = (const float*)d_in[24];
    const float* b_hh_l1b = (const float*)d_in[25];
    float* out = (float*)d_out;

    void* p;
    cudaGetSymbolAddress(&p, g_h1);    float* s_h1  = (float*)p;
    cudaGetSymbolAddress(&p, g_x0);    float* s_x0  = (float*)p;
    cudaGetSymbolAddress(&p, g_y);     float* s_y   = (float*)p;
    cudaGetSymbolAddress(&p, g_xhi);   bf16*  s_xhi = (bf16*)p;
    cudaGetSymbolAddress(&p, g_xlo);   bf16*  s_xlo = (bf16*)p;
    cudaGetSymbolAddress(&p, g_yhi);   bf16*  s_yhi = (bf16*)p;
    cudaGetSymbolAddress(&p, g_ylo);   bf16*  s_ylo = (bf16*)p;
    cudaGetSymbolAddress(&p, g_gif);   float* s_gif = (float*)p;
    cudaGetSymbolAddress(&p, g_gib);   float* s_gib = (float*)p;
    cudaGetSymbolAddress(&p, g_wihhi); bf16*  s_wih_hi = (bf16*)p;
    cudaGetSymbolAddress(&p, g_wihlo); bf16*  s_wih_lo = (bf16*)p;
    cudaGetSymbolAddress(&p, g_whhhi); bf16*  s_whh_hi = (bf16*)p;
    cudaGetSymbolAddress(&p, g_whhlo); bf16*  s_whh_lo = (bf16*)p;

    const int GEMM_SMEM = 81920;
    const int GRU_SMEM  = 32256 * 2 + 64 * 52 * 4;
    cudaFuncSetAttribute(gemm_bf16x3, cudaFuncAttributeMaxDynamicSharedMemorySize, GEMM_SMEM);
    cudaFuncSetAttribute(gru_mma_kernel, cudaFuncAttributeMaxDynamicSharedMemorySize, GRU_SMEM);

    const size_t WIH0 = (size_t)G3 * HH;          // elems of l0 w_ih
    const size_t WIH1 = (size_t)G3 * 2 * HH;      // elems of l1 w_ih
    const size_t WHH  = (size_t)G3 * HH;

    dim3 blk(256);

    // weight splits (every launch; deterministic)
    split_kernel<<<512, 256>>>(w_ih_l0f, s_wih_hi,            s_wih_lo,            WIH0);
    split_kernel<<<512, 256>>>(w_ih_l0b, s_wih_hi + WIH0,     s_wih_lo + WIH0,     WIH0);
    split_kernel<<<512, 256>>>(w_ih_l1f, s_wih_hi + 2*WIH0,   s_wih_lo + 2*WIH0,   WIH1);
    split_kernel<<<512, 256>>>(w_ih_l1b, s_wih_hi + 4*WIH0,   s_wih_lo + 4*WIH0,   WIH1);
    split_kernel<<<512, 256>>>(w_hh_l0f, s_whh_hi,            s_whh_lo,            WHH);
    split_kernel<<<512, 256>>>(w_hh_l0b, s_whh_hi + WHH,      s_whh_lo + WHH,      WHH);
    split_kernel<<<512, 256>>>(w_hh_l1f, s_whh_hi + 2*WHH,    s_whh_lo + 2*WHH,    WHH);
    split_kernel<<<512, 256>>>(w_hh_l1b, s_whh_hi + 3*WHH,    s_whh_lo + 3*WHH,    WHH);

    // encoders (FFMA2 path, small K) -> concat into g_x0
    gemm_nt_kernel<<<dim3(H4 / 128, MR / 128), blk>>>(cond,  ce_w1, ce_b1, s_h1, CONDD, H4,  0,   1);
    gemm_nt_kernel<<<dim3(H2 / 128, MR / 128), blk>>>(s_h1,  ce_w2, ce_b2, s_x0, H4,    HH,  0,   0);
    gemm_nt_kernel<<<dim3(H4 / 128, MR / 128), blk>>>(input, me_w1, me_b1, s_h1, OUTD,  H4,  0,   1);
    gemm_nt_kernel<<<dim3(H2 / 128, MR / 128), blk>>>(s_h1,  me_w2, me_b2, s_x0, H4,    HH,  512, 0);

    // split x0 for tensor-core gi GEMMs
    split_kernel<<<512, 256>>>(s_x0, s_xhi, s_xlo, (size_t)MR * HH);

    // layer 0: gi projections + recurrence
    gemm_bf16x3<<<dim3(G3 / 128, MR / 128), blk, GEMM_SMEM>>>(
        s_xhi, s_xlo, s_wih_hi, s_wih_lo, b_ih_l0f, s_gif, HH, G3);
    gemm_bf16x3<<<dim3(G3 / 128, MR / 128), blk, GEMM_SMEM>>>(
        s_xhi, s_xlo, s_wih_hi + WIH0, s_wih_lo + WIH0, b_ih_l0b, s_gib, HH, G3);
    zero_h_kernel<<<64, 256>>>();
    gru_mma_kernel<<<128, 256, GRU_SMEM>>>(
        s_gif, s_gib,
        s_whh_hi, s_whh_lo, s_whh_hi + WHH, s_whh_lo + WHH,
        b_hh_l0f, b_hh_l0b, s_y, s_yhi, s_ylo);

    // layer 1: gi from layer-0 output (K=2048) + recurrence
    gemm_bf16x3<<<dim3(G3 / 128, MR / 128), blk, GEMM_SMEM>>>(
        s_yhi, s_ylo, s_wih_hi + 2*WIH0, s_wih_lo + 2*WIH0, b_ih_l1f, s_gif, 2 * HH, G3);
    gemm_bf16x3<<<dim3(G3 / 128, MR / 128), blk, GEMM_SMEM>>>(
        s_yhi, s_ylo, s_wih_hi + 4*WIH0, s_wih_lo + 4*WIH0, b_ih_l1b, s_gib, 2 * HH, G3);
    zero_h_kernel<<<64, 256>>>();
    gru_mma_kernel<<<128, 256, GRU_SMEM>>>(
        s_gif, s_gib,
        s_whh_hi + 2*WHH, s_whh_lo + 2*WHH, s_whh_hi + 3*WHH, s_whh_lo + 3*WHH,
        b_hh_l1f, b_hh_l1b, s_y, s_yhi, s_ylo);

    mean_kernel<<<BB, 256>>>(s_y, out);
}

// round 5
// speedup vs baseline: 3.1105x; 1.0373x over previous
#include <cuda_runtime.h>
#include <cuda_bf16.h>
#include <math.h>
#include <stdint.h>

#define BB    64
#define TT    300
#define CONDD 64
#define OUTD  72
#define HH    1024
#define H4    256
#define H2    512
#define G3    3072
#define MR    (BB*TT)

typedef __nv_bfloat16 bf16;

// ---------------- device globals ----------------
__device__ float g_h1 [MR * H4];
__device__ float g_x0 [(size_t)MR * HH];
__device__ float g_y  [(size_t)MR * 2 * HH];
__device__ bf16  g_xhi[(size_t)MR * HH],     g_xlo[(size_t)MR * HH];
__device__ bf16  g_yhi[(size_t)MR * 2 * HH], g_ylo[(size_t)MR * 2 * HH];
__device__ float g_gif[(size_t)MR * G3], g_gib[(size_t)MR * G3];
__device__ float g_hf [2][2][BB * HH];
__device__ bf16  g_hhi[2][2][BB * HH], g_hlo[2][2][BB * HH];
__device__ bf16  g_wihhi[(size_t)6 * G3 * HH], g_wihlo[(size_t)6 * G3 * HH];
__device__ bf16  g_whhhi[(size_t)4 * G3 * HH], g_whhlo[(size_t)4 * G3 * HH];
__device__ unsigned int g_barc[2];
__device__ unsigned int g_barg[2];

// ---------------- helpers ----------------
__device__ __forceinline__ uint32_t saddr(const void* p) {
    return (uint32_t)__cvta_generic_to_shared(p);
}
__device__ __forceinline__ void cpa16(uint32_t s, const void* g) {
    asm volatile("cp.async.cg.shared.global [%0], [%1], 16;" :: "r"(s), "l"(g));
}
__device__ __forceinline__ void cpa_commit() { asm volatile("cp.async.commit_group;"); }
__device__ __forceinline__ void cpa_wait1() { asm volatile("cp.async.wait_group 1;"); }
__device__ __forceinline__ void cpa_wait0() { asm volatile("cp.async.wait_group 0;"); }

__device__ __forceinline__ void ldmx4(uint32_t* r, uint32_t a) {
    asm volatile("ldmatrix.sync.aligned.m8n8.x4.shared.b16 {%0,%1,%2,%3}, [%4];"
                 : "=r"(r[0]), "=r"(r[1]), "=r"(r[2]), "=r"(r[3]) : "r"(a));
}
__device__ __forceinline__ void ldmx2(uint32_t* r, uint32_t a) {
    asm volatile("ldmatrix.sync.aligned.m8n8.x2.shared.b16 {%0,%1}, [%2];"
                 : "=r"(r[0]), "=r"(r[1]) : "r"(a));
}
__device__ __forceinline__ void mma_bf16(float* c, const uint32_t* a, const uint32_t* b) {
    asm volatile("mma.sync.aligned.m16n8k16.row.col.f32.bf16.bf16.f32 "
                 "{%0,%1,%2,%3}, {%4,%5,%6,%7}, {%8,%9}, {%0,%1,%2,%3};"
                 : "+f"(c[0]), "+f"(c[1]), "+f"(c[2]), "+f"(c[3])
                 : "r"(a[0]), "r"(a[1]), "r"(a[2]), "r"(a[3]), "r"(b[0]), "r"(b[1]));
}

__device__ __forceinline__ unsigned long long ffma2(unsigned long long a,
                                                    unsigned long long b,
                                                    unsigned long long c) {
    unsigned long long d;
    asm("fma.rn.f32x2 %0, %1, %2, %3;" : "=l"(d) : "l"(a), "l"(b), "l"(c));
    return d;
}
__device__ __forceinline__ unsigned long long pack2(float x, float y) {
    unsigned long long d;
    asm("mov.b64 %0, {%1, %2};" : "=l"(d) : "f"(x), "f"(y));
    return d;
}
__device__ __forceinline__ void unpack2(unsigned long long p, float& lo, float& hi) {
    asm("mov.b64 {%0, %1}, %2;" : "=f"(lo), "=f"(hi) : "l"(p));
}

// per-direction software grid barrier (graph-capturable)
__device__ __forceinline__ void dir_barrier(int dir, unsigned int nb) {
    __syncthreads();
    if (threadIdx.x == 0) {
        __threadfence();
        unsigned int gen = *(volatile unsigned int*)&g_barg[dir];
        unsigned int arrived = atomicAdd(&g_barc[dir], 1u);
        if (arrived == nb - 1u) {
            g_barc[dir] = 0u;
            __threadfence();
            atomicExch(&g_barg[dir], gen + 1u);
        } else {
            while (*(volatile unsigned int*)&g_barg[dir] == gen) { __nanosleep(20); }
        }
        __threadfence();
    }
    __syncthreads();
}

// ---------------- split f32 -> bf16 hi/lo (vectorized) ----------------
__global__ void split_kernel(const float* __restrict__ s, bf16* __restrict__ hi,
                             bf16* __restrict__ lo, size_t n) {
    // n is always a multiple of 4 here
    const size_t n4 = n >> 2;
    for (size_t i = blockIdx.x * (size_t)blockDim.x + threadIdx.x; i < n4;
         i += (size_t)gridDim.x * blockDim.x) {
        float4 v = ((const float4*)s)[i];
        bf16 h0 = __float2bfloat16(v.x), h1 = __float2bfloat16(v.y);
        bf16 h2 = __float2bfloat16(v.z), h3 = __float2bfloat16(v.w);
        bf16 l0 = __float2bfloat16(v.x - __bfloat162float(h0));
        bf16 l1 = __float2bfloat16(v.y - __bfloat162float(h1));
        bf16 l2 = __float2bfloat16(v.z - __bfloat162float(h2));
        bf16 l3 = __float2bfloat16(v.w - __bfloat162float(h3));
        ushort4 hv, lv;
        hv.x = __bfloat16_as_ushort(h0); hv.y = __bfloat16_as_ushort(h1);
        hv.z = __bfloat16_as_ushort(h2); hv.w = __bfloat16_as_ushort(h3);
        lv.x = __bfloat16_as_ushort(l0); lv.y = __bfloat16_as_ushort(l1);
        lv.z = __bfloat16_as_ushort(l2); lv.w = __bfloat16_as_ushort(l3);
        ((ushort4*)hi)[i] = hv;
        ((ushort4*)lo)[i] = lv;
    }
}

// ---------------- encoder FFMA2 GEMM ----------------
__global__ void __launch_bounds__(256) gemm_nt_kernel(
    const float* __restrict__ A, const float* __restrict__ W,
    const float* __restrict__ bias, float* __restrict__ C,
    int K, int ldc, int coff, int leaky)
{
    __shared__ float As[8][128];
    __shared__ float Bs[8][128];
    const int tid = threadIdx.x;
    const int bx = blockIdx.x, by = blockIdx.y;
    const int tx = tid & 15, ty = tid >> 4;
    const int r  = tid >> 1;
    const int cq = (tid & 1) * 4;
    const float* Ap = A + (size_t)(by * 128 + r) * K + cq;
    const float* Wp = W + (size_t)(bx * 128 + r) * K + cq;

    unsigned long long acc[8][4];
#pragma unroll
    for (int m = 0; m < 8; m++)
#pragma unroll
        for (int p = 0; p < 4; p++) acc[m][p] = 0ULL;

    const int nkt = K >> 3;
    for (int kt = 0; kt < nkt; kt++) {
        __syncthreads();
        float4 av = *(const float4*)(Ap + kt * 8);
        float4 wv = *(const float4*)(Wp + kt * 8);
        As[cq + 0][r] = av.x; As[cq + 1][r] = av.y; As[cq + 2][r] = av.z; As[cq + 3][r] = av.w;
        Bs[cq + 0][r] = wv.x; Bs[cq + 1][r] = wv.y; Bs[cq + 2][r] = wv.z; Bs[cq + 3][r] = wv.w;
        __syncthreads();
#pragma unroll
        for (int k = 0; k < 8; k++) {
            float4 a0 = *(const float4*)&As[k][ty * 8];
            float4 a1 = *(const float4*)&As[k][ty * 8 + 4];
            ulonglong2 bq0 = *(const ulonglong2*)&Bs[k][tx * 8];
            ulonglong2 bq1 = *(const ulonglong2*)&Bs[k][tx * 8 + 4];
            float a[8] = {a0.x, a0.y, a0.z, a0.w, a1.x, a1.y, a1.z, a1.w};
#pragma unroll
            for (int m = 0; m < 8; m++) {
                unsigned long long ap = pack2(a[m], a[m]);
                acc[m][0] = ffma2(ap, bq0.x, acc[m][0]);
                acc[m][1] = ffma2(ap, bq0.y, acc[m][1]);
                acc[m][2] = ffma2(ap, bq1.x, acc[m][2]);
                acc[m][3] = ffma2(ap, bq1.y, acc[m][3]);
            }
        }
    }
#pragma unroll
    for (int m = 0; m < 8; m++) {
        const int row = by * 128 + ty * 8 + m;
        float* crow = C + (size_t)row * ldc + coff;
#pragma unroll
        for (int p = 0; p < 4; p++) {
            float lo, hi;
            unpack2(acc[m][p], lo, hi);
            const int nn = bx * 128 + tx * 8 + p * 2;
            float v0 = lo + bias[nn];
            float v1 = hi + bias[nn + 1];
            if (leaky) {
                v0 = (v0 >= 0.f) ? v0 : 0.2f * v0;
                v1 = (v1 >= 0.f) ? v1 : 0.2f * v1;
            }
            crow[nn]     = v0;
            crow[nn + 1] = v1;
        }
    }
}

// ---------------- bf16x3 mma.sync GEMM (proven in R3): C = A@W^T + bias ----------------
// BM=128, BN=128, BK=32, 256 thr, 8 warps (2m x 4n), warp tile 64x32.
__global__ void __launch_bounds__(256) gemm_bf16x3(
    const bf16* __restrict__ Ahi, const bf16* __restrict__ Alo,
    const bf16* __restrict__ Whi, const bf16* __restrict__ Wlo,
    const float* __restrict__ bias, float* __restrict__ C, int K, int ldc)
{
    extern __shared__ bf16 sm_[];
    bf16* sAh = sm_;
    bf16* sAl = sm_ + 10240;
    bf16* sBh = sm_ + 20480;
    bf16* sBl = sm_ + 30720;

    const int tid = threadIdx.x, lane = tid & 31, warp = tid >> 5;
    const int wm = warp & 1, wn = warp >> 1;
    const int bx = blockIdx.x, by = blockIdx.y;

    float acc[4][4][4];
#pragma unroll
    for (int mt = 0; mt < 4; mt++)
#pragma unroll
        for (int nt = 0; nt < 4; nt++)
#pragma unroll
            for (int i = 0; i < 4; i++) acc[mt][nt][i] = 0.f;

    const int nkt = K >> 5;

    {
#pragma unroll
        for (int c0 = 0; c0 < 2; c0++) {
            int c = tid + c0 * 256;
            int row = c >> 2, kc = c & 3;
            size_t ga = (size_t)(by * 128 + row) * K + kc * 8;
            cpa16(saddr(sAh + row * 40 + kc * 8), Ahi + ga);
            cpa16(saddr(sAl + row * 40 + kc * 8), Alo + ga);
            size_t gb = (size_t)(bx * 128 + row) * K + kc * 8;
            cpa16(saddr(sBh + row * 40 + kc * 8), Whi + gb);
            cpa16(saddr(sBl + row * 40 + kc * 8), Wlo + gb);
        }
        cpa_commit();
    }

    for (int kt = 0; kt < nkt; kt++) {
        const int buf = (kt & 1) * 5120;
        if (kt + 1 < nkt) {
            const int nb = ((kt + 1) & 1) * 5120;
            const int ko = (kt + 1) * 32;
#pragma unroll
            for (int c0 = 0; c0 < 2; c0++) {
                int c = tid + c0 * 256;
                int row = c >> 2, kc = c & 3;
                size_t ga = (size_t)(by * 128 + row) * K + ko + kc * 8;
                cpa16(saddr(sAh + nb + row * 40 + kc * 8), Ahi + ga);
                cpa16(saddr(sAl + nb + row * 40 + kc * 8), Alo + ga);
                size_t gb = (size_t)(bx * 128 + row) * K + ko + kc * 8;
                cpa16(saddr(sBh + nb + row * 40 + kc * 8), Whi + gb);
                cpa16(saddr(sBl + nb + row * 40 + kc * 8), Wlo + gb);
            }
            cpa_commit();
            cpa_wait1();
        } else {
            cpa_wait0();
        }
        __syncthreads();

#pragma unroll
        for (int ks = 0; ks < 2; ks++) {
            const int kk = ks * 16;
            uint32_t ah[4][4], al[4][4];
#pragma unroll
            for (int mt = 0; mt < 4; mt++) {
                const int ar = wm * 64 + mt * 16 + (lane & 15);
                const int ac = kk + (lane >> 4) * 8;
                ldmx4(ah[mt], saddr(sAh + buf + ar * 40 + ac));
                ldmx4(al[mt], saddr(sAl + buf + ar * 40 + ac));
            }
            uint32_t bh[4][2], bl[4][2];
#pragma unroll
            for (int nt = 0; nt < 4; nt++) {
                const int br = wn * 32 + nt * 8 + (lane & 7);
                const int bc = kk + ((lane >> 3) & 1) * 8;
                ldmx2(bh[nt], saddr(sBh + buf + br * 40 + bc));
                ldmx2(bl[nt], saddr(sBl + buf + br * 40 + bc));
            }
#pragma unroll
            for (int mt = 0; mt < 4; mt++)
#pragma unroll
                for (int nt = 0; nt < 4; nt++) {
                    mma_bf16(acc[mt][nt], ah[mt], bh[nt]);
                    mma_bf16(acc[mt][nt], ah[mt], bl[nt]);
                    mma_bf16(acc[mt][nt], al[mt], bh[nt]);
                }
        }
        __syncthreads();
    }

#pragma unroll
    for (int mt = 0; mt < 4; mt++) {
        const int r0 = by * 128 + wm * 64 + mt * 16 + (lane >> 2);
#pragma unroll
        for (int nt = 0; nt < 4; nt++) {
            const int c0 = bx * 128 + wn * 32 + nt * 8 + 2 * (lane & 3);
            const float b0 = bias[c0], b1 = bias[c0 + 1];
            C[(size_t)r0 * ldc + c0]           = acc[mt][nt][0] + b0;
            C[(size_t)r0 * ldc + c0 + 1]       = acc[mt][nt][1] + b1;
            C[(size_t)(r0 + 8) * ldc + c0]     = acc[mt][nt][2] + b0;
            C[(size_t)(r0 + 8) * ldc + c0 + 1] = acc[mt][nt][3] + b1;
        }
    }
}

// ---------------- zero hidden state ----------------
__global__ void zero_h_kernel() {
    const int n = 4 * BB * HH;
    float* pf = &g_hf[0][0][0];
    bf16* ph = &g_hhi[0][0][0];
    bf16* pl = &g_hlo[0][0][0];
    for (int i = blockIdx.x * blockDim.x + threadIdx.x; i < n;
         i += gridDim.x * blockDim.x) {
        pf[i] = 0.f;
        ph[i] = __float2bfloat16(0.f);
        pl[i] = __float2bfloat16(0.f);
    }
}

// ---------------- persistent GRU layer: W resident in smem ----------------
// 128 CTAs (64/dir), 16 hidden units each. W slice hi+lo in smem (198KB, stride
// 2064B = conflict-free ldmatrix). Per step only H streams (3-stage cp.async,
// K-chunk 32). Cs overlays H stages after the K loop.
#define WLO_OFF 99072     // bytes
#define HST_BASE 198144   // bytes
#define GRU_SMEM_BYTES 228864
__global__ void __launch_bounds__(256, 1) gru_mma_kernel(
    const float* __restrict__ gif, const float* __restrict__ gib,
    const bf16* __restrict__ whf_hi, const bf16* __restrict__ whf_lo,
    const bf16* __restrict__ whb_hi, const bf16* __restrict__ whb_lo,
    const float* __restrict__ bhhf, const float* __restrict__ bhhb,
    float* __restrict__ y, bf16* __restrict__ yhi, bf16* __restrict__ ylo)
{
    extern __shared__ char smem[];
    const uint32_t sb = saddr(smem);
    float* Cs = (float*)(smem + HST_BASE);

    const int tid = threadIdx.x, lane = tid & 31, warp = tid >> 5;
    const int dir = blockIdx.x >> 6;
    const int j0  = (blockIdx.x & 63) << 4;
    const int wm = warp & 3, wn = warp >> 2;
    const int m0 = wm * 16, n0 = wn * 24;

    const float* gi  = dir ? gib    : gif;
    const bf16* whhh = dir ? whb_hi : whf_hi;
    const bf16* whhl = dir ? whb_lo : whf_lo;
    const float* bhh = dir ? bhhb   : bhhf;

    // ---- load W slice into smem once ----
    for (int i = tid; i < 6144; i += 256) {
        const int row = i >> 7, kc = i & 127;
        const int grow = (row >> 4) * HH + j0 + (row & 15);
        const uint32_t dst = sb + (uint32_t)(row * 2064 + kc * 16);
        cpa16(dst,           whhh + (size_t)grow * HH + kc * 8);
        cpa16(dst + WLO_OFF, whhl + (size_t)grow * HH + kc * 8);
    }
    cpa_commit();
    cpa_wait0();
    __syncthreads();

    const uint32_t sWh = sb;
    const uint32_t sWl = sb + WLO_OFF;

    for (int s = 0; s < TT; s++) {
        const int t_idx = dir ? (TT - 1 - s) : s;
        const int rb = s & 1;
        const bf16* hhi = g_hhi[dir][rb];
        const bf16* hlo = g_hlo[dir][rb];
        const float* hpf = g_hf[dir][rb];
        float* hnf = g_hf[dir][rb ^ 1];
        bf16* hnhi = g_hhi[dir][rb ^ 1];
        bf16* hnlo = g_hlo[dir][rb ^ 1];

        float acc[3][4];
#pragma unroll
        for (int nt = 0; nt < 3; nt++)
#pragma unroll
            for (int i = 0; i < 4; i++) acc[nt][i] = 0.f;

        // prologue: stage 0 = K chunk 0 (64 rows x 32 k x 2B per half)
        {
            const int row = tid >> 2, kc = tid & 3;
            const uint32_t dst = sb + HST_BASE + (uint32_t)(row * 80 + kc * 16);
            cpa16(dst,        hhi + (size_t)row * HH + kc * 8);
            cpa16(dst + 5120, hlo + (size_t)row * HH + kc * 8);
        }
        cpa_commit();

        for (int kt = 0; kt < 32; kt++) {
            const int st = kt % 3;
            if (kt + 1 < 32) {
                const int sn = (kt + 1) % 3;
                const int row = tid >> 2, kc = tid & 3;
                const uint32_t dst = sb + HST_BASE + (uint32_t)(sn * 10240 + row * 80 + kc * 16);
                const size_t gofs = (size_t)row * HH + (kt + 1) * 32 + kc * 8;
                cpa16(dst,        hhi + gofs);
                cpa16(dst + 5120, hlo + gofs);
                cpa_commit();
                cpa_wait1();
            } else {
                cpa_wait0();
            }
            __syncthreads();

            const uint32_t Hh = sb + HST_BASE + st * 10240;
            const uint32_t Hl = Hh + 5120;
#pragma unroll
            for (int ks = 0; ks < 2; ks++) {
                uint32_t ah[4], al[4];
                const int ar = m0 + (lane & 15);
                const int ac = ks * 16 + ((lane >> 4) << 3);
                ldmx4(ah, Hh + ar * 80 + ac * 2);
                ldmx4(al, Hl + ar * 80 + ac * 2);
                const int kcolg = kt * 32 + ks * 16 + (((lane >> 3) & 1) << 3);
#pragma unroll
                for (int nt = 0; nt < 3; nt++) {
                    const int brow = n0 + nt * 8 + (lane & 7);
                    uint32_t bh[2], bl[2];
                    ldmx2(bh, sWh + brow * 2064 + kcolg * 2);
                    ldmx2(bl, sWl + brow * 2064 + kcolg * 2);
                    mma_bf16(acc[nt], ah, bh);
                    mma_bf16(acc[nt], ah, bl);
                    mma_bf16(acc[nt], al, bh);
                }
            }
        }
        __syncthreads();   // H-stage reads done; Cs overlay safe

#pragma unroll
        for (int nt = 0; nt < 3; nt++) {
            const int cr = m0 + (lane >> 2);
            const int cc = n0 + nt * 8 + 2 * (lane & 3);
            Cs[cr * 52 + cc]           = acc[nt][0];
            Cs[cr * 52 + cc + 1]       = acc[nt][1];
            Cs[(cr + 8) * 52 + cc]     = acc[nt][2];
            Cs[(cr + 8) * 52 + cc + 1] = acc[nt][3];
        }
        __syncthreads();

        // GRU pointwise epilogue: 64 b x 16 j
#pragma unroll
        for (int p = 0; p < 4; p++) {
            const int idx = tid + (p << 8);
            const int b = idx >> 4, jj = idx & 15;
            const int j = j0 + jj;
            const size_t gbase = (size_t)(b * TT + t_idx) * G3;
            const float cr = Cs[b * 52 + jj]      + bhh[j];
            const float cz = Cs[b * 52 + 16 + jj] + bhh[HH + j];
            const float cn = Cs[b * 52 + 32 + jj] + bhh[2 * HH + j];
            const float rr = 1.f / (1.f + expf(-(gi[gbase + j] + cr)));
            const float zz = 1.f / (1.f + expf(-(gi[gbase + HH + j] + cz)));
            const float nn = tanhf(gi[gbase + 2 * HH + j] + rr * cn);
            const float hp = hpf[b * HH + j];
            const float hn = (1.f - zz) * nn + zz * hp;
            hnf[b * HH + j] = hn;
            bf16 hh = __float2bfloat16(hn);
            hnhi[b * HH + j] = hh;
            hnlo[b * HH + j] = __float2bfloat16(hn - __bfloat162float(hh));
            const size_t yb = (size_t)(b * TT + t_idx) * (2 * HH) + dir * HH + j;
            y[yb] = hn;
            yhi[yb] = hh;
            ylo[yb] = __float2bfloat16(hn - __bfloat162float(hh));
        }
        dir_barrier(dir, 64);
    }
}

// ---------------- final mean ----------------
__global__ void mean_kernel(const float* __restrict__ y, float* __restrict__ out) {
    const int b = blockIdx.x;
    const int tid = threadIdx.x;
    const size_t base = (size_t)b * TT * 2 * HH;
    float s = 0.f;
    for (int i = tid; i < TT * 2 * HH; i += 256) s += y[base + i];
    __shared__ float red[256];
    red[tid] = s;
    __syncthreads();
    for (int o = 128; o > 0; o >>= 1) {
        if (tid < o) red[tid] += red[tid + o];
        __syncthreads();
    }
    if (tid == 0) out[b] = red[0] / (float)(TT * 2 * HH);
}

// ---------------- launcher ----------------
extern "C" void kernel_launch(void* const* d_in, const int* in_sizes, int n_in,
                              void* d_out, int out_size)
{
    const float* cond     = (const float*)d_in[0];
    const float* input    = (const float*)d_in[1];
    const float* ce_w1    = (const float*)d_in[2];
    const float* ce_b1    = (const float*)d_in[3];
    const float* ce_w2    = (const float*)d_in[4];
    const float* ce_b2    = (const float*)d_in[5];
    const float* me_w1    = (const float*)d_in[6];
    const float* me_b1    = (const float*)d_in[7];
    const float* me_w2    = (const float*)d_in[8];
    const float* me_b2    = (const float*)d_in[9];
    const float* w_ih_l0f = (const float*)d_in[10];
    const float* w_hh_l0f = (const float*)d_in[11];
    const float* b_ih_l0f = (const float*)d_in[12];
    const float* b_hh_l0f = (const float*)d_in[13];
    const float* w_ih_l0b = (const float*)d_in[14];
    const float* w_hh_l0b = (const float*)d_in[15];
    const float* b_ih_l0b = (const float*)d_in[16];
    const float* b_hh_l0b = (const float*)d_in[17];
    const float* w_ih_l1f = (const float*)d_in[18];
    const float* w_hh_l1f = (const float*)d_in[19];
    const float* b_ih_l1f = (const float*)d_in[20];
    const float* b_hh_l1f = (const float*)d_in[21];
    const float* w_ih_l1b = (const float*)d_in[22];
    const float* w_hh_l1b = (const float*)d_in[23];
    const float* b_ih_l1b = (const float*)d_in[24];
    const float* b_hh_l1b = (const float*)d_in[25];
    float* out = (float*)d_out;

    void* p;
    cudaGetSymbolAddress(&p, g_h1);    float* s_h1  = (float*)p;
    cudaGetSymbolAddress(&p, g_x0);    float* s_x0  = (float*)p;
    cudaGetSymbolAddress(&p, g_y);     float* s_y   = (float*)p;
    cudaGetSymbolAddress(&p, g_xhi);   bf16*  s_xhi = (bf16*)p;
    cudaGetSymbolAddress(&p, g_xlo);   bf16*  s_xlo = (bf16*)p;
    cudaGetSymbolAddress(&p, g_yhi);   bf16*  s_yhi = (bf16*)p;
    cudaGetSymbolAddress(&p, g_ylo);   bf16*  s_ylo = (bf16*)p;
    cudaGetSymbolAddress(&p, g_gif);   float* s_gif = (float*)p;
    cudaGetSymbolAddress(&p, g_gib);   float* s_gib = (float*)p;
    cudaGetSymbolAddress(&p, g_wihhi); bf16*  s_wih_hi = (bf16*)p;
    cudaGetSymbolAddress(&p, g_wihlo); bf16*  s_wih_lo = (bf16*)p;
    cudaGetSymbolAddress(&p, g_whhhi); bf16*  s_whh_hi = (bf16*)p;
    cudaGetSymbolAddress(&p, g_whhlo); bf16*  s_whh_lo = (bf16*)p;

    const int GEMM_SMEM = 81920;
    cudaFuncSetAttribute(gemm_bf16x3, cudaFuncAttributeMaxDynamicSharedMemorySize, GEMM_SMEM);
    cudaFuncSetAttribute(gru_mma_kernel, cudaFuncAttributeMaxDynamicSharedMemorySize, GRU_SMEM_BYTES);

    const size_t WIH0 = (size_t)G3 * HH;
    const size_t WIH1 = (size_t)G3 * 2 * HH;
    const size_t WHH  = (size_t)G3 * HH;

    dim3 blk(256);

    // weight splits (vectorized)
    split_kernel<<<1024, 256>>>(w_ih_l0f, s_wih_hi,          s_wih_lo,          WIH0);
    split_kernel<<<1024, 256>>>(w_ih_l0b, s_wih_hi + WIH0,   s_wih_lo + WIH0,   WIH0);
    split_kernel<<<1024, 256>>>(w_ih_l1f, s_wih_hi + 2*WIH0, s_wih_lo + 2*WIH0, WIH1);
    split_kernel<<<1024, 256>>>(w_ih_l1b, s_wih_hi + 4*WIH0, s_wih_lo + 4*WIH0, WIH1);
    split_kernel<<<1024, 256>>>(w_hh_l0f, s_whh_hi,          s_whh_lo,          WHH);
    split_kernel<<<1024, 256>>>(w_hh_l0b, s_whh_hi + WHH,    s_whh_lo + WHH,    WHH);
    split_kernel<<<1024, 256>>>(w_hh_l1f, s_whh_hi + 2*WHH,  s_whh_lo + 2*WHH,  WHH);
    split_kernel<<<1024, 256>>>(w_hh_l1b, s_whh_hi + 3*WHH,  s_whh_lo + 3*WHH,  WHH);

    // encoders -> concat into g_x0
    gemm_nt_kernel<<<dim3(H4 / 128, MR / 128), blk>>>(cond,  ce_w1, ce_b1, s_h1, CONDD, H4,  0,   1);
    gemm_nt_kernel<<<dim3(H2 / 128, MR / 128), blk>>>(s_h1,  ce_w2, ce_b2, s_x0, H4,    HH,  0,   0);
    gemm_nt_kernel<<<dim3(H4 / 128, MR / 128), blk>>>(input, me_w1, me_b1, s_h1, OUTD,  H4,  0,   1);
    gemm_nt_kernel<<<dim3(H2 / 128, MR / 128), blk>>>(s_h1,  me_w2, me_b2, s_x0, H4,    HH,  512, 0);

    split_kernel<<<1024, 256>>>(s_x0, s_xhi, s_xlo, (size_t)MR * HH);

    // layer 0: gi + recurrence
    gemm_bf16x3<<<dim3(G3 / 128, MR / 128), blk, GEMM_SMEM>>>(
        s_xhi, s_xlo, s_wih_hi, s_wih_lo, b_ih_l0f, s_gif, HH, G3);
    gemm_bf16x3<<<dim3(G3 / 128, MR / 128), blk, GEMM_SMEM>>>(
        s_xhi, s_xlo, s_wih_hi + WIH0, s_wih_lo + WIH0, b_ih_l0b, s_gib, HH, G3);
    zero_h_kernel<<<64, 256>>>();
    gru_mma_kernel<<<128, 256, GRU_SMEM_BYTES>>>(
        s_gif, s_gib,
        s_whh_hi, s_whh_lo, s_whh_hi + WHH, s_whh_lo + WHH,
        b_hh_l0f, b_hh_l0b, s_y, s_yhi, s_ylo);

    // layer 1: gi (K=2048) + recurrence
    gemm_bf16x3<<<dim3(G3 / 128, MR / 128), blk, GEMM_SMEM>>>(
        s_yhi, s_ylo, s_wih_hi + 2*WIH0, s_wih_lo + 2*WIH0, b_ih_l1f, s_gif, 2 * HH, G3);
    gemm_bf16x3<<<dim3(G3 / 128, MR / 128), blk, GEMM_SMEM>>>(
        s_yhi, s_ylo, s_wih_hi + 4*WIH0, s_wih_lo + 4*WIH0, b_ih_l1b, s_gib, 2 * HH, G3);
    zero_h_kernel<<<64, 256>>>();
    gru_mma_kernel<<<128, 256, GRU_SMEM_BYTES>>>(
        s_gif, s_gib,
        s_whh_hi + 2*WHH, s_whh_lo + 2*WHH, s_whh_hi + 3*WHH, s_whh_lo + 3*WHH,
        b_hh_l1f, b_hh_l1b, s_y, s_yhi, s_ylo);

    mean_kernel<<<BB, 256>>>(s_y, out);
}

// round 6
// speedup vs baseline: 3.5280x; 1.1342x over previous
#include <cuda_runtime.h>
#include <cuda_bf16.h>
#include <math.h>
#include <stdint.h>

#define BB    64
#define TT    300
#define CONDD 64
#define OUTD  72
#define HH    1024
#define H4    256
#define H2    512
#define G3    3072
#define MR    (BB*TT)

typedef __nv_bfloat16 bf16;

// ---------------- device globals ----------------
__device__ float g_h1 [MR * H4];
__device__ float g_y  [(size_t)MR * 2 * HH];
__device__ bf16  g_xhi[(size_t)MR * HH],     g_xlo[(size_t)MR * HH];
__device__ bf16  g_yhi[(size_t)MR * 2 * HH], g_ylo[(size_t)MR * 2 * HH];
__device__ float g_gif[(size_t)MR * G3], g_gib[(size_t)MR * G3];
__device__ float g_hf [2][2][BB * HH];
__device__ bf16  g_hhi[2][2][BB * HH], g_hlo[2][2][BB * HH];
__device__ bf16  g_wihhi[(size_t)6 * G3 * HH], g_wihlo[(size_t)6 * G3 * HH];
__device__ bf16  g_whhhi[(size_t)4 * G3 * HH], g_whhlo[(size_t)4 * G3 * HH];
__device__ unsigned int g_barc[2];
__device__ unsigned int g_barg[2];

// ---------------- helpers ----------------
__device__ __forceinline__ uint32_t saddr(const void* p) {
    return (uint32_t)__cvta_generic_to_shared(p);
}
__device__ __forceinline__ void cpa16(uint32_t s, const void* g) {
    asm volatile("cp.async.cg.shared.global [%0], [%1], 16;" :: "r"(s), "l"(g));
}
__device__ __forceinline__ void cpa_commit() { asm volatile("cp.async.commit_group;"); }
__device__ __forceinline__ void cpa_wait1() { asm volatile("cp.async.wait_group 1;"); }
__device__ __forceinline__ void cpa_wait0() { asm volatile("cp.async.wait_group 0;"); }

__device__ __forceinline__ void ldmx4(uint32_t* r, uint32_t a) {
    asm volatile("ldmatrix.sync.aligned.m8n8.x4.shared.b16 {%0,%1,%2,%3}, [%4];"
                 : "=r"(r[0]), "=r"(r[1]), "=r"(r[2]), "=r"(r[3]) : "r"(a));
}
__device__ __forceinline__ void ldmx2(uint32_t* r, uint32_t a) {
    asm volatile("ldmatrix.sync.aligned.m8n8.x2.shared.b16 {%0,%1}, [%2];"
                 : "=r"(r[0]), "=r"(r[1]) : "r"(a));
}
__device__ __forceinline__ void mma_bf16(float* c, const uint32_t* a, const uint32_t* b) {
    asm volatile("mma.sync.aligned.m16n8k16.row.col.f32.bf16.bf16.f32 "
                 "{%0,%1,%2,%3}, {%4,%5,%6,%7}, {%8,%9}, {%0,%1,%2,%3};"
                 : "+f"(c[0]), "+f"(c[1]), "+f"(c[2]), "+f"(c[3])
                 : "r"(a[0]), "r"(a[1]), "r"(a[2]), "r"(a[3]), "r"(b[0]), "r"(b[1]));
}

__device__ __forceinline__ unsigned long long ffma2(unsigned long long a,
                                                    unsigned long long b,
                                                    unsigned long long c) {
    unsigned long long d;
    asm("fma.rn.f32x2 %0, %1, %2, %3;" : "=l"(d) : "l"(a), "l"(b), "l"(c));
    return d;
}
__device__ __forceinline__ unsigned long long pack2(float x, float y) {
    unsigned long long d;
    asm("mov.b64 %0, {%1, %2};" : "=l"(d) : "f"(x), "f"(y));
    return d;
}
__device__ __forceinline__ void unpack2(unsigned long long p, float& lo, float& hi) {
    asm("mov.b64 {%0, %1}, %2;" : "=f"(lo), "=f"(hi) : "l"(p));
}

__device__ __forceinline__ float fast_sigmoid(float x) {
    return 1.f / (1.f + __expf(-x));
}
__device__ __forceinline__ float fast_tanh(float x) {
    float r;
    asm("tanh.approx.f32 %0, %1;" : "=f"(r) : "f"(x));
    return r;
}

// per-direction software grid barrier (graph-capturable)
__device__ __forceinline__ void dir_barrier(int dir, unsigned int nb) {
    __syncthreads();
    if (threadIdx.x == 0) {
        __threadfence();
        unsigned int gen = *(volatile unsigned int*)&g_barg[dir];
        unsigned int arrived = atomicAdd(&g_barc[dir], 1u);
        if (arrived == nb - 1u) {
            g_barc[dir] = 0u;
            __threadfence();
            atomicExch(&g_barg[dir], gen + 1u);
        } else {
            while (*(volatile unsigned int*)&g_barg[dir] == gen) { __nanosleep(20); }
        }
        __threadfence();
    }
    __syncthreads();
}

// ---------------- fused weight split: 8 jobs in one launch ----------------
struct SplitJobs {
    const float* src[8];
    bf16* hi[8];
    bf16* lo[8];
    unsigned int n4[8];   // n/4
};
__global__ void split_w_kernel(SplitJobs jobs) {
    const int j = blockIdx.y;
    const float4* s = (const float4*)jobs.src[j];
    ushort4* hi = (ushort4*)jobs.hi[j];
    ushort4* lo = (ushort4*)jobs.lo[j];
    const unsigned int n4 = jobs.n4[j];
    for (unsigned int i = blockIdx.x * blockDim.x + threadIdx.x; i < n4;
         i += gridDim.x * blockDim.x) {
        float4 v = s[i];
        bf16 h0 = __float2bfloat16(v.x), h1 = __float2bfloat16(v.y);
        bf16 h2 = __float2bfloat16(v.z), h3 = __float2bfloat16(v.w);
        ushort4 hv, lv;
        hv.x = __bfloat16_as_ushort(h0); hv.y = __bfloat16_as_ushort(h1);
        hv.z = __bfloat16_as_ushort(h2); hv.w = __bfloat16_as_ushort(h3);
        lv.x = __bfloat16_as_ushort(__float2bfloat16(v.x - __bfloat162float(h0)));
        lv.y = __bfloat16_as_ushort(__float2bfloat16(v.y - __bfloat162float(h1)));
        lv.z = __bfloat16_as_ushort(__float2bfloat16(v.z - __bfloat162float(h2)));
        lv.w = __bfloat16_as_ushort(__float2bfloat16(v.w - __bfloat162float(h3)));
        hi[i] = hv;
        lo[i] = lv;
    }
}

// ---------------- encoder FFMA2 GEMM (optional fused bf16 split output) ----------------
__global__ void __launch_bounds__(256) gemm_nt_kernel(
    const float* __restrict__ A, const float* __restrict__ W,
    const float* __restrict__ bias, float* __restrict__ C,
    bf16* __restrict__ Ohi, bf16* __restrict__ Olo,
    int K, int ldc, int coff, int leaky)
{
    __shared__ float As[8][128];
    __shared__ float Bs[8][128];
    const int tid = threadIdx.x;
    const int bx = blockIdx.x, by = blockIdx.y;
    const int tx = tid & 15, ty = tid >> 4;
    const int r  = tid >> 1;
    const int cq = (tid & 1) * 4;
    const float* Ap = A + (size_t)(by * 128 + r) * K + cq;
    const float* Wp = W + (size_t)(bx * 128 + r) * K + cq;

    unsigned long long acc[8][4];
#pragma unroll
    for (int m = 0; m < 8; m++)
#pragma unroll
        for (int p = 0; p < 4; p++) acc[m][p] = 0ULL;

    const int nkt = K >> 3;
    for (int kt = 0; kt < nkt; kt++) {
        __syncthreads();
        float4 av = *(const float4*)(Ap + kt * 8);
        float4 wv = *(const float4*)(Wp + kt * 8);
        As[cq + 0][r] = av.x; As[cq + 1][r] = av.y; As[cq + 2][r] = av.z; As[cq + 3][r] = av.w;
        Bs[cq + 0][r] = wv.x; Bs[cq + 1][r] = wv.y; Bs[cq + 2][r] = wv.z; Bs[cq + 3][r] = wv.w;
        __syncthreads();
#pragma unroll
        for (int k = 0; k < 8; k++) {
            float4 a0 = *(const float4*)&As[k][ty * 8];
            float4 a1 = *(const float4*)&As[k][ty * 8 + 4];
            ulonglong2 bq0 = *(const ulonglong2*)&Bs[k][tx * 8];
            ulonglong2 bq1 = *(const ulonglong2*)&Bs[k][tx * 8 + 4];
            float a[8] = {a0.x, a0.y, a0.z, a0.w, a1.x, a1.y, a1.z, a1.w};
#pragma unroll
            for (int m = 0; m < 8; m++) {
                unsigned long long ap = pack2(a[m], a[m]);
                acc[m][0] = ffma2(ap, bq0.x, acc[m][0]);
                acc[m][1] = ffma2(ap, bq0.y, acc[m][1]);
                acc[m][2] = ffma2(ap, bq1.x, acc[m][2]);
                acc[m][3] = ffma2(ap, bq1.y, acc[m][3]);
            }
        }
    }
#pragma unroll
    for (int m = 0; m < 8; m++) {
        const int row = by * 128 + ty * 8 + m;
        const size_t rbase = (size_t)row * ldc + coff;
#pragma unroll
        for (int p = 0; p < 4; p++) {
            float lo, hi;
            unpack2(acc[m][p], lo, hi);
            const int nn = bx * 128 + tx * 8 + p * 2;
            float v0 = lo + bias[nn];
            float v1 = hi + bias[nn + 1];
            if (leaky) {
                v0 = (v0 >= 0.f) ? v0 : 0.2f * v0;
                v1 = (v1 >= 0.f) ? v1 : 0.2f * v1;
            }
            if (Ohi) {
                bf16 h0 = __float2bfloat16(v0), h1 = __float2bfloat16(v1);
                Ohi[rbase + nn]     = h0;
                Ohi[rbase + nn + 1] = h1;
                Olo[rbase + nn]     = __float2bfloat16(v0 - __bfloat162float(h0));
                Olo[rbase + nn + 1] = __float2bfloat16(v1 - __bfloat162float(h1));
            } else {
                C[rbase + nn]     = v0;
                C[rbase + nn + 1] = v1;
            }
        }
    }
}

// ---------------- bf16x3 mma.sync GEMM, 512 threads / 16 warps ----------------
// BM=128, BN=128, BK=32, 2-stage cp.async; warp grid 4m x 4n, warp tile 32x32.
__global__ void __launch_bounds__(512) gemm_bf16x3(
    const bf16* __restrict__ Ahi, const bf16* __restrict__ Alo,
    const bf16* __restrict__ Whi, const bf16* __restrict__ Wlo,
    const float* __restrict__ bias, float* __restrict__ C, int K, int ldc)
{
    extern __shared__ bf16 sm_[];
    bf16* sAh = sm_;
    bf16* sAl = sm_ + 10240;
    bf16* sBh = sm_ + 20480;
    bf16* sBl = sm_ + 30720;

    const int tid = threadIdx.x, lane = tid & 31, warp = tid >> 5;
    const int wm = warp & 3, wn = warp >> 2;
    const int bx = blockIdx.x, by = blockIdx.y;

    float acc[2][4][4];
#pragma unroll
    for (int mt = 0; mt < 2; mt++)
#pragma unroll
        for (int nt = 0; nt < 4; nt++)
#pragma unroll
            for (int i = 0; i < 4; i++) acc[mt][nt][i] = 0.f;

    const int nkt = K >> 5;
    const int lrow = tid >> 2, lkc = tid & 3;

    {   // prologue stage 0: each thread 1 chunk per matrix
        const uint32_t so = (uint32_t)(lrow * 40 + lkc * 8);
        size_t ga = (size_t)(by * 128 + lrow) * K + lkc * 8;
        size_t gb = (size_t)(bx * 128 + lrow) * K + lkc * 8;
        cpa16(saddr(sAh + so), Ahi + ga);
        cpa16(saddr(sAl + so), Alo + ga);
        cpa16(saddr(sBh + so), Whi + gb);
        cpa16(saddr(sBl + so), Wlo + gb);
        cpa_commit();
    }

    for (int kt = 0; kt < nkt; kt++) {
        const int buf = (kt & 1) * 5120;
        if (kt + 1 < nkt) {
            const int nb = ((kt + 1) & 1) * 5120;
            const int ko = (kt + 1) * 32;
            const uint32_t so = (uint32_t)(nb + lrow * 40 + lkc * 8);
            size_t ga = (size_t)(by * 128 + lrow) * K + ko + lkc * 8;
            size_t gb = (size_t)(bx * 128 + lrow) * K + ko + lkc * 8;
            cpa16(saddr(sAh + so), Ahi + ga);
            cpa16(saddr(sAl + so), Alo + ga);
            cpa16(saddr(sBh + so), Whi + gb);
            cpa16(saddr(sBl + so), Wlo + gb);
            cpa_commit();
            cpa_wait1();
        } else {
            cpa_wait0();
        }
        __syncthreads();

#pragma unroll
        for (int ks = 0; ks < 2; ks++) {
            const int kk = ks * 16;
            uint32_t ah[2][4], al[2][4];
#pragma unroll
            for (int mt = 0; mt < 2; mt++) {
                const int ar = wm * 32 + mt * 16 + (lane & 15);
                const int ac = kk + (lane >> 4) * 8;
                ldmx4(ah[mt], saddr(sAh + buf + ar * 40 + ac));
                ldmx4(al[mt], saddr(sAl + buf + ar * 40 + ac));
            }
            uint32_t bh[4][2], bl[4][2];
#pragma unroll
            for (int nt = 0; nt < 4; nt++) {
                const int br = wn * 32 + nt * 8 + (lane & 7);
                const int bc = kk + ((lane >> 3) & 1) * 8;
                ldmx2(bh[nt], saddr(sBh + buf + br * 40 + bc));
                ldmx2(bl[nt], saddr(sBl + buf + br * 40 + bc));
            }
#pragma unroll
            for (int mt = 0; mt < 2; mt++)
#pragma unroll
                for (int nt = 0; nt < 4; nt++) {
                    mma_bf16(acc[mt][nt], ah[mt], bh[nt]);
                    mma_bf16(acc[mt][nt], ah[mt], bl[nt]);
                    mma_bf16(acc[mt][nt], al[mt], bh[nt]);
                }
        }
        __syncthreads();
    }

#pragma unroll
    for (int mt = 0; mt < 2; mt++) {
        const int r0 = by * 128 + wm * 32 + mt * 16 + (lane >> 2);
#pragma unroll
        for (int nt = 0; nt < 4; nt++) {
            const int c0 = bx * 128 + wn * 32 + nt * 8 + 2 * (lane & 3);
            const float b0 = bias[c0], b1 = bias[c0 + 1];
            C[(size_t)r0 * ldc + c0]           = acc[mt][nt][0] + b0;
            C[(size_t)r0 * ldc + c0 + 1]       = acc[mt][nt][1] + b1;
            C[(size_t)(r0 + 8) * ldc + c0]     = acc[mt][nt][2] + b0;
            C[(size_t)(r0 + 8) * ldc + c0 + 1] = acc[mt][nt][3] + b1;
        }
    }
}

// ---------------- zero hidden state ----------------
__global__ void zero_h_kernel() {
    const int n = 4 * BB * HH;
    float* pf = &g_hf[0][0][0];
    bf16* ph = &g_hhi[0][0][0];
    bf16* pl = &g_hlo[0][0][0];
    for (int i = blockIdx.x * blockDim.x + threadIdx.x; i < n;
         i += gridDim.x * blockDim.x) {
        pf[i] = 0.f;
        ph[i] = __float2bfloat16(0.f);
        pl[i] = __float2bfloat16(0.f);
    }
}

// ---------------- persistent GRU layer: W resident in smem ----------------
#define WLO_OFF 99072     // bytes
#define HST_BASE 198144   // bytes
#define GRU_SMEM_BYTES 228864
__global__ void __launch_bounds__(256, 1) gru_mma_kernel(
    const float* __restrict__ gif, const float* __restrict__ gib,
    const bf16* __restrict__ whf_hi, const bf16* __restrict__ whf_lo,
    const bf16* __restrict__ whb_hi, const bf16* __restrict__ whb_lo,
    const float* __restrict__ bhhf, const float* __restrict__ bhhb,
    float* __restrict__ y, bf16* __restrict__ yhi, bf16* __restrict__ ylo)
{
    extern __shared__ char smem[];
    const uint32_t sb = saddr(smem);
    float* Cs = (float*)(smem + HST_BASE);

    const int tid = threadIdx.x, lane = tid & 31, warp = tid >> 5;
    const int dir = blockIdx.x >> 6;
    const int j0  = (blockIdx.x & 63) << 4;
    const int wm = warp & 3, wn = warp >> 2;
    const int m0 = wm * 16, n0 = wn * 24;

    const float* gi  = dir ? gib    : gif;
    const bf16* whhh = dir ? whb_hi : whf_hi;
    const bf16* whhl = dir ? whb_lo : whf_lo;
    const float* bhh = dir ? bhhb   : bhhf;

    // per-thread epilogue indices (4 items) + biases preloaded once
    const int ep_b [4] = { tid >> 4, (tid + 256) >> 4, (tid + 512) >> 4, (tid + 768) >> 4 };
    const int ep_jj = tid & 15;
    const int ep_j  = j0 + ep_jj;
    const float bh_r = bhh[ep_j];
    const float bh_z = bhh[HH + ep_j];
    const float bh_n = bhh[2 * HH + ep_j];

    // ---- load W slice into smem once ----
    for (int i = tid; i < 6144; i += 256) {
        const int row = i >> 7, kc = i & 127;
        const int grow = (row >> 4) * HH + j0 + (row & 15);
        const uint32_t dst = sb + (uint32_t)(row * 2064 + kc * 16);
        cpa16(dst,           whhh + (size_t)grow * HH + kc * 8);
        cpa16(dst + WLO_OFF, whhl + (size_t)grow * HH + kc * 8);
    }
    cpa_commit();
    cpa_wait0();
    __syncthreads();

    const uint32_t sWh = sb;
    const uint32_t sWl = sb + WLO_OFF;

    for (int s = 0; s < TT; s++) {
        const int t_idx = dir ? (TT - 1 - s) : s;
        const int rb = s & 1;
        const bf16* hhi = g_hhi[dir][rb];
        const bf16* hlo = g_hlo[dir][rb];
        const float* hpf = g_hf[dir][rb];
        float* hnf = g_hf[dir][rb ^ 1];
        bf16* hnhi = g_hhi[dir][rb ^ 1];
        bf16* hnlo = g_hlo[dir][rb ^ 1];

        // prefetch gi + h_prev for epilogue (hidden behind the K loop)
        float pre_gr[4], pre_gz[4], pre_gn[4], pre_hp[4];
#pragma unroll
        for (int p = 0; p < 4; p++) {
            const size_t gbase = (size_t)(ep_b[p] * TT + t_idx) * G3;
            pre_gr[p] = __ldg(gi + gbase + ep_j);
            pre_gz[p] = __ldg(gi + gbase + HH + ep_j);
            pre_gn[p] = __ldg(gi + gbase + 2 * HH + ep_j);
            pre_hp[p] = __ldg(hpf + ep_b[p] * HH + ep_j);
        }

        float acc[3][4];
#pragma unroll
        for (int nt = 0; nt < 3; nt++)
#pragma unroll
            for (int i = 0; i < 4; i++) acc[nt][i] = 0.f;

        {   // prologue: stage 0
            const int row = tid >> 2, kc = tid & 3;
            const uint32_t dst = sb + HST_BASE + (uint32_t)(row * 80 + kc * 16);
            cpa16(dst,        hhi + (size_t)row * HH + kc * 8);
            cpa16(dst + 5120, hlo + (size_t)row * HH + kc * 8);
        }
        cpa_commit();

        for (int kt = 0; kt < 32; kt++) {
            const int st = kt % 3;
            if (kt + 1 < 32) {
                const int sn = (kt + 1) % 3;
                const int row = tid >> 2, kc = tid & 3;
                const uint32_t dst = sb + HST_BASE + (uint32_t)(sn * 10240 + row * 80 + kc * 16);
                const size_t gofs = (size_t)row * HH + (kt + 1) * 32 + kc * 8;
                cpa16(dst,        hhi + gofs);
                cpa16(dst + 5120, hlo + gofs);
                cpa_commit();
                cpa_wait1();
            } else {
                cpa_wait0();
            }
            __syncthreads();

            const uint32_t Hh = sb + HST_BASE + st * 10240;
            const uint32_t Hl = Hh + 5120;
#pragma unroll
            for (int ks = 0; ks < 2; ks++) {
                uint32_t ah[4], al[4];
                const int ar = m0 + (lane & 15);
                const int ac = ks * 16 + ((lane >> 4) << 3);
                ldmx4(ah, Hh + ar * 80 + ac * 2);
                ldmx4(al, Hl + ar * 80 + ac * 2);
                const int kcolg = kt * 32 + ks * 16 + (((lane >> 3) & 1) << 3);
#pragma unroll
                for (int nt = 0; nt < 3; nt++) {
                    const int brow = n0 + nt * 8 + (lane & 7);
                    uint32_t bh[2], bl[2];
                    ldmx2(bh, sWh + brow * 2064 + kcolg * 2);
                    ldmx2(bl, sWl + brow * 2064 + kcolg * 2);
                    mma_bf16(acc[nt], ah, bh);
                    mma_bf16(acc[nt], ah, bl);
                    mma_bf16(acc[nt], al, bh);
                }
            }
        }
        __syncthreads();

#pragma unroll
        for (int nt = 0; nt < 3; nt++) {
            const int cr = m0 + (lane >> 2);
            const int cc = n0 + nt * 8 + 2 * (lane & 3);
            Cs[cr * 52 + cc]           = acc[nt][0];
            Cs[cr * 52 + cc + 1]       = acc[nt][1];
            Cs[(cr + 8) * 52 + cc]     = acc[nt][2];
            Cs[(cr + 8) * 52 + cc + 1] = acc[nt][3];
        }
        __syncthreads();

        // GRU pointwise epilogue: 64 b x 16 j (prefetched operands)
#pragma unroll
        for (int p = 0; p < 4; p++) {
            const int b = ep_b[p];
            const float cr = Cs[b * 52 + ep_jj]      + bh_r;
            const float cz = Cs[b * 52 + 16 + ep_jj] + bh_z;
            const float cn = Cs[b * 52 + 32 + ep_jj] + bh_n;
            const float rr = fast_sigmoid(pre_gr[p] + cr);
            const float zz = fast_sigmoid(pre_gz[p] + cz);
            const float nn = fast_tanh(pre_gn[p] + rr * cn);
            const float hp = pre_hp[p];
            const float hn = (1.f - zz) * nn + zz * hp;
            hnf[b * HH + ep_j] = hn;
            bf16 hh = __float2bfloat16(hn);
            hnhi[b * HH + ep_j] = hh;
            hnlo[b * HH + ep_j] = __float2bfloat16(hn - __bfloat162float(hh));
            const size_t yb = (size_t)(b * TT + t_idx) * (2 * HH) + dir * HH + ep_j;
            y[yb] = hn;
            yhi[yb] = hh;
            ylo[yb] = __float2bfloat16(hn - __bfloat162float(hh));
        }
        dir_barrier(dir, 64);
    }
}

// ---------------- final mean ----------------
__global__ void mean_kernel(const float* __restrict__ y, float* __restrict__ out) {
    const int b = blockIdx.x;
    const int tid = threadIdx.x;
    const size_t base = (size_t)b * TT * 2 * HH;
    float s = 0.f;
    for (int i = tid; i < TT * 2 * HH; i += 256) s += y[base + i];
    __shared__ float red[256];
    red[tid] = s;
    __syncthreads();
    for (int o = 128; o > 0; o >>= 1) {
        if (tid < o) red[tid] += red[tid + o];
        __syncthreads();
    }
    if (tid == 0) out[b] = red[0] / (float)(TT * 2 * HH);
}

// ---------------- launcher ----------------
extern "C" void kernel_launch(void* const* d_in, const int* in_sizes, int n_in,
                              void* d_out, int out_size)
{
    const float* cond     = (const float*)d_in[0];
    const float* input    = (const float*)d_in[1];
    const float* ce_w1    = (const float*)d_in[2];
    const float* ce_b1    = (const float*)d_in[3];
    const float* ce_w2    = (const float*)d_in[4];
    const float* ce_b2    = (const float*)d_in[5];
    const float* me_w1    = (const float*)d_in[6];
    const float* me_b1    = (const float*)d_in[7];
    const float* me_w2    = (const float*)d_in[8];
    const float* me_b2    = (const float*)d_in[9];
    const float* w_ih_l0f = (const float*)d_in[10];
    const float* w_hh_l0f = (const float*)d_in[11];
    const float* b_ih_l0f = (const float*)d_in[12];
    const float* b_hh_l0f = (const float*)d_in[13];
    const float* w_ih_l0b = (const float*)d_in[14];
    const float* w_hh_l0b = (const float*)d_in[15];
    const float* b_ih_l0b = (const float*)d_in[16];
    const float* b_hh_l0b = (const float*)d_in[17];
    const float* w_ih_l1f = (const float*)d_in[18];
    const float* w_hh_l1f = (const float*)d_in[19];
    const float* b_ih_l1f = (const float*)d_in[20];
    const float* b_hh_l1f = (const float*)d_in[21];
    const float* w_ih_l1b = (const float*)d_in[22];
    const float* w_hh_l1b = (const float*)d_in[23];
    const float* b_ih_l1b = (const float*)d_in[24];
    const float* b_hh_l1b = (const float*)d_in[25];
    float* out = (float*)d_out;

    void* p;
    cudaGetSymbolAddress(&p, g_h1);    float* s_h1  = (float*)p;
    cudaGetSymbolAddress(&p, g_y);     float* s_y   = (float*)p;
    cudaGetSymbolAddress(&p, g_xhi);   bf16*  s_xhi = (bf16*)p;
    cudaGetSymbolAddress(&p, g_xlo);   bf16*  s_xlo = (bf16*)p;
    cudaGetSymbolAddress(&p, g_yhi);   bf16*  s_yhi = (bf16*)p;
    cudaGetSymbolAddress(&p, g_ylo);   bf16*  s_ylo = (bf16*)p;
    cudaGetSymbolAddress(&p, g_gif);   float* s_gif = (float*)p;
    cudaGetSymbolAddress(&p, g_gib);   float* s_gib = (float*)p;
    cudaGetSymbolAddress(&p, g_wihhi); bf16*  s_wih_hi = (bf16*)p;
    cudaGetSymbolAddress(&p, g_wihlo); bf16*  s_wih_lo = (bf16*)p;
    cudaGetSymbolAddress(&p, g_whhhi); bf16*  s_whh_hi = (bf16*)p;
    cudaGetSymbolAddress(&p, g_whhlo); bf16*  s_whh_lo = (bf16*)p;

    const int GEMM_SMEM = 81920;
    cudaFuncSetAttribute(gemm_bf16x3, cudaFuncAttributeMaxDynamicSharedMemorySize, GEMM_SMEM);
    cudaFuncSetAttribute(gru_mma_kernel, cudaFuncAttributeMaxDynamicSharedMemorySize, GRU_SMEM_BYTES);

    const size_t WIH0 = (size_t)G3 * HH;
    const size_t WHH  = (size_t)G3 * HH;

    // fused weight splits: one launch (launch #0)
    SplitJobs jobs;
    jobs.src[0] = w_ih_l0f; jobs.hi[0] = s_wih_hi;            jobs.lo[0] = s_wih_lo;            jobs.n4[0] = (unsigned)(WIH0 >> 2);
    jobs.src[1] = w_ih_l0b; jobs.hi[1] = s_wih_hi + WIH0;     jobs.lo[1] = s_wih_lo + WIH0;     jobs.n4[1] = (unsigned)(WIH0 >> 2);
    jobs.src[2] = w_ih_l1f; jobs.hi[2] = s_wih_hi + 2*WIH0;   jobs.lo[2] = s_wih_lo + 2*WIH0;   jobs.n4[2] = (unsigned)(WIH0 >> 1);
    jobs.src[3] = w_ih_l1b; jobs.hi[3] = s_wih_hi + 4*WIH0;   jobs.lo[3] = s_wih_lo + 4*WIH0;   jobs.n4[3] = (unsigned)(WIH0 >> 1);
    jobs.src[4] = w_hh_l0f; jobs.hi[4] = s_whh_hi;            jobs.lo[4] = s_whh_lo;            jobs.n4[4] = (unsigned)(WHH >> 2);
    jobs.src[5] = w_hh_l0b; jobs.hi[5] = s_whh_hi + WHH;      jobs.lo[5] = s_whh_lo + WHH;      jobs.n4[5] = (unsigned)(WHH >> 2);
    jobs.src[6] = w_hh_l1f; jobs.hi[6] = s_whh_hi + 2*WHH;    jobs.lo[6] = s_whh_lo + 2*WHH;    jobs.n4[6] = (unsigned)(WHH >> 2);
    jobs.src[7] = w_hh_l1b; jobs.hi[7] = s_whh_hi + 3*WHH;    jobs.lo[7] = s_whh_lo + 3*WHH;    jobs.n4[7] = (unsigned)(WHH >> 2);
    split_w_kernel<<<dim3(160, 8), 256>>>(jobs);

    dim3 blk(256);

    // encoders (launches 1-4); stage-2 writes bf16 hi/lo directly (fused split)
    gemm_nt_kernel<<<dim3(H4 / 128, MR / 128), blk>>>(cond,  ce_w1, ce_b1, s_h1, nullptr, nullptr, CONDD, H4,  0,   1);
    gemm_nt_kernel<<<dim3(H2 / 128, MR / 128), blk>>>(s_h1,  ce_w2, ce_b2, nullptr, s_xhi, s_xlo, H4,    HH,  0,   0);
    gemm_nt_kernel<<<dim3(H4 / 128, MR / 128), blk>>>(input, me_w1, me_b1, s_h1, nullptr, nullptr, OUTD,  H4,  0,   1);
    gemm_nt_kernel<<<dim3(H2 / 128, MR / 128), blk>>>(s_h1,  me_w2, me_b2, nullptr, s_xhi, s_xlo, H4,    HH,  512, 0);

    dim3 blk2(512);

    // layer 0: gi (launch #5 = ncu capture target) + recurrence
    gemm_bf16x3<<<dim3(G3 / 128, MR / 128), blk2, GEMM_SMEM>>>(
        s_xhi, s_xlo, s_wih_hi, s_wih_lo, b_ih_l0f, s_gif, HH, G3);
    gemm_bf16x3<<<dim3(G3 / 128, MR / 128), blk2, GEMM_SMEM>>>(
        s_xhi, s_xlo, s_wih_hi + WIH0, s_wih_lo + WIH0, b_ih_l0b, s_gib, HH, G3);
    zero_h_kernel<<<64, 256>>>();
    gru_mma_kernel<<<128, 256, GRU_SMEM_BYTES>>>(
        s_gif, s_gib,
        s_whh_hi, s_whh_lo, s_whh_hi + WHH, s_whh_lo + WHH,
        b_hh_l0f, b_hh_l0b, s_y, s_yhi, s_ylo);

    // layer 1: gi (K=2048) + recurrence
    gemm_bf16x3<<<dim3(G3 / 128, MR / 128), blk2, GEMM_SMEM>>>(
        s_yhi, s_ylo, s_wih_hi + 2*WIH0, s_wih_lo + 2*WIH0, b_ih_l1f, s_gif, 2 * HH, G3);
    gemm_bf16x3<<<dim3(G3 / 128, MR / 128), blk2, GEMM_SMEM>>>(
        s_yhi, s_ylo, s_wih_hi + 4*WIH0, s_wih_lo + 4*WIH0, b_ih_l1b, s_gib, 2 * HH, G3);
    zero_h_kernel<<<64, 256>>>();
    gru_mma_kernel<<<128, 256, GRU_SMEM_BYTES>>>(
        s_gif, s_gib,
        s_whh_hi + 2*WHH, s_whh_lo + 2*WHH, s_whh_hi + 3*WHH, s_whh_lo + 3*WHH,
        b_hh_l1f, b_hh_l1b, s_y, s_yhi, s_ylo);

    mean_kernel<<<BB, 256>>>(s_y, out);
}

// round 10
// speedup vs baseline: 3.8485x; 1.0908x over previous
#include <cuda_runtime.h>
#include <cuda_bf16.h>
#include <math.h>
#include <stdint.h>

#define BB    64
#define TT    300
#define CONDD 64
#define OUTD  72
#define HH    1024
#define H4    256
#define H2    512
#define G3    3072
#define MR    (BB*TT)

typedef __nv_bfloat16 bf16;

// ---------------- device globals ----------------
__device__ float g_h1 [MR * H4];
__device__ float g_y  [(size_t)MR * 2 * HH];
__device__ bf16  g_xhi[(size_t)MR * HH],     g_xlo[(size_t)MR * HH];
__device__ bf16  g_yhi[(size_t)MR * 2 * HH], g_ylo[(size_t)MR * 2 * HH];
__device__ float g_gif[(size_t)MR * G3], g_gib[(size_t)MR * G3];
__device__ float g_hf [2][2][BB * HH];
__device__ bf16  g_hhi[2][2][BB * HH], g_hlo[2][2][BB * HH];
__device__ bf16  g_wihhi[(size_t)6 * G3 * HH], g_wihlo[(size_t)6 * G3 * HH];
__device__ bf16  g_whhhi[(size_t)4 * G3 * HH], g_whhlo[(size_t)4 * G3 * HH];
__device__ unsigned int g_barc[2];
__device__ unsigned int g_barg[2];

// ---------------- helpers ----------------
__device__ __forceinline__ uint32_t saddr(const void* p) {
    return (uint32_t)__cvta_generic_to_shared(p);
}
__device__ __forceinline__ void cpa16(uint32_t s, const void* g) {
    asm volatile("cp.async.cg.shared.global [%0], [%1], 16;" :: "r"(s), "l"(g));
}
__device__ __forceinline__ void cpa_commit() { asm volatile("cp.async.commit_group;"); }
__device__ __forceinline__ void cpa_wait2() { asm volatile("cp.async.wait_group 2;"); }
__device__ __forceinline__ void cpa_wait1() { asm volatile("cp.async.wait_group 1;"); }
__device__ __forceinline__ void cpa_wait0() { asm volatile("cp.async.wait_group 0;"); }

__device__ __forceinline__ void ldmx4(uint32_t* r, uint32_t a) {
    asm volatile("ldmatrix.sync.aligned.m8n8.x4.shared.b16 {%0,%1,%2,%3}, [%4];"
                 : "=r"(r[0]), "=r"(r[1]), "=r"(r[2]), "=r"(r[3]) : "r"(a));
}
__device__ __forceinline__ void ldmx2(uint32_t* r, uint32_t a) {
    asm volatile("ldmatrix.sync.aligned.m8n8.x2.shared.b16 {%0,%1}, [%2];"
                 : "=r"(r[0]), "=r"(r[1]) : "r"(a));
}
__device__ __forceinline__ void mma_bf16(float* c, const uint32_t* a, const uint32_t* b) {
    asm volatile("mma.sync.aligned.m16n8k16.row.col.f32.bf16.bf16.f32 "
                 "{%0,%1,%2,%3}, {%4,%5,%6,%7}, {%8,%9}, {%0,%1,%2,%3};"
                 : "+f"(c[0]), "+f"(c[1]), "+f"(c[2]), "+f"(c[3])
                 : "r"(a[0]), "r"(a[1]), "r"(a[2]), "r"(a[3]), "r"(b[0]), "r"(b[1]));
}

__device__ __forceinline__ unsigned long long ffma2(unsigned long long a,
                                                    unsigned long long b,
                                                    unsigned long long c) {
    unsigned long long d;
    asm("fma.rn.f32x2 %0, %1, %2, %3;" : "=l"(d) : "l"(a), "l"(b), "l"(c));
    return d;
}
__device__ __forceinline__ unsigned long long pack2(float x, float y) {
    unsigned long long d;
    asm("mov.b64 %0, {%1, %2};" : "=l"(d) : "f"(x), "f"(y));
    return d;
}
__device__ __forceinline__ void unpack2(unsigned long long p, float& lo, float& hi) {
    asm("mov.b64 {%0, %1}, %2;" : "=f"(lo), "=f"(hi) : "l"(p));
}

__device__ __forceinline__ float fast_sigmoid(float x) {
    return 1.f / (1.f + __expf(-x));
}
__device__ __forceinline__ float fast_tanh(float x) {
    float r;
    asm("tanh.approx.f32 %0, %1;" : "=f"(r) : "f"(x));
    return r;
}

// per-direction software grid barrier (graph-capturable)
__device__ __forceinline__ void dir_barrier(int dir, unsigned int nb) {
    __syncthreads();
    if (threadIdx.x == 0) {
        __threadfence();
        unsigned int gen = *(volatile unsigned int*)&g_barg[dir];
        unsigned int arrived = atomicAdd(&g_barc[dir], 1u);
        if (arrived == nb - 1u) {
            g_barc[dir] = 0u;
            __threadfence();
            atomicExch(&g_barg[dir], gen + 1u);
        } else {
            while (*(volatile unsigned int*)&g_barg[dir] == gen) { __nanosleep(20); }
        }
        __threadfence();
    }
    __syncthreads();
}

// ---------------- fused weight split: 8 jobs in one launch ----------------
struct SplitJobs {
    const float* src[8];
    bf16* hi[8];
    bf16* lo[8];
    unsigned int n4[8];
};
__global__ void split_w_kernel(SplitJobs jobs) {
    const int j = blockIdx.y;
    const float4* s = (const float4*)jobs.src[j];
    ushort4* hi = (ushort4*)jobs.hi[j];
    ushort4* lo = (ushort4*)jobs.lo[j];
    const unsigned int n4 = jobs.n4[j];
    for (unsigned int i = blockIdx.x * blockDim.x + threadIdx.x; i < n4;
         i += gridDim.x * blockDim.x) {
        float4 v = s[i];
        bf16 h0 = __float2bfloat16(v.x), h1 = __float2bfloat16(v.y);
        bf16 h2 = __float2bfloat16(v.z), h3 = __float2bfloat16(v.w);
        ushort4 hv, lv;
        hv.x = __bfloat16_as_ushort(h0); hv.y = __bfloat16_as_ushort(h1);
        hv.z = __bfloat16_as_ushort(h2); hv.w = __bfloat16_as_ushort(h3);
        lv.x = __bfloat16_as_ushort(__float2bfloat16(v.x - __bfloat162float(h0)));
        lv.y = __bfloat16_as_ushort(__float2bfloat16(v.y - __bfloat162float(h1)));
        lv.z = __bfloat16_as_ushort(__float2bfloat16(v.z - __bfloat162float(h2)));
        lv.w = __bfloat16_as_ushort(__float2bfloat16(v.w - __bfloat162float(h3)));
        hi[i] = hv;
        lo[i] = lv;
    }
}

// ---------------- encoder FFMA2 GEMM (optional fused bf16 split output) ----------------
__global__ void __launch_bounds__(256) gemm_nt_kernel(
    const float* __restrict__ A, const float* __restrict__ W,
    const float* __restrict__ bias, float* __restrict__ C,
    bf16* __restrict__ Ohi, bf16* __restrict__ Olo,
    int K, int ldc, int coff, int leaky)
{
    __shared__ float As[8][128];
    __shared__ float Bs[8][128];
    const int tid = threadIdx.x;
    const int bx = blockIdx.x, by = blockIdx.y;
    const int tx = tid & 15, ty = tid >> 4;
    const int r  = tid >> 1;
    const int cq = (tid & 1) * 4;
    const float* Ap = A + (size_t)(by * 128 + r) * K + cq;
    const float* Wp = W + (size_t)(bx * 128 + r) * K + cq;

    unsigned long long acc[8][4];
#pragma unroll
    for (int m = 0; m < 8; m++)
#pragma unroll
        for (int p = 0; p < 4; p++) acc[m][p] = 0ULL;

    const int nkt = K >> 3;
    for (int kt = 0; kt < nkt; kt++) {
        __syncthreads();
        float4 av = *(const float4*)(Ap + kt * 8);
        float4 wv = *(const float4*)(Wp + kt * 8);
        As[cq + 0][r] = av.x; As[cq + 1][r] = av.y; As[cq + 2][r] = av.z; As[cq + 3][r] = av.w;
        Bs[cq + 0][r] = wv.x; Bs[cq + 1][r] = wv.y; Bs[cq + 2][r] = wv.z; Bs[cq + 3][r] = wv.w;
        __syncthreads();
#pragma unroll
        for (int k = 0; k < 8; k++) {
            float4 a0 = *(const float4*)&As[k][ty * 8];
            float4 a1 = *(const float4*)&As[k][ty * 8 + 4];
            ulonglong2 bq0 = *(const ulonglong2*)&Bs[k][tx * 8];
            ulonglong2 bq1 = *(const ulonglong2*)&Bs[k][tx * 8 + 4];
            float a[8] = {a0.x, a0.y, a0.z, a0.w, a1.x, a1.y, a1.z, a1.w};
#pragma unroll
            for (int m = 0; m < 8; m++) {
                unsigned long long ap = pack2(a[m], a[m]);
                acc[m][0] = ffma2(ap, bq0.x, acc[m][0]);
                acc[m][1] = ffma2(ap, bq0.y, acc[m][1]);
                acc[m][2] = ffma2(ap, bq1.x, acc[m][2]);
                acc[m][3] = ffma2(ap, bq1.y, acc[m][3]);
            }
        }
    }
#pragma unroll
    for (int m = 0; m < 8; m++) {
        const int row = by * 128 + ty * 8 + m;
        const size_t rbase = (size_t)row * ldc + coff;
#pragma unroll
        for (int p = 0; p < 4; p++) {
            float lo, hi;
            unpack2(acc[m][p], lo, hi);
            const int nn = bx * 128 + tx * 8 + p * 2;
            float v0 = lo + bias[nn];
            float v1 = hi + bias[nn + 1];
            if (leaky) {
                v0 = (v0 >= 0.f) ? v0 : 0.2f * v0;
                v1 = (v1 >= 0.f) ? v1 : 0.2f * v1;
            }
            if (Ohi) {
                bf16 h0 = __float2bfloat16(v0), h1 = __float2bfloat16(v1);
                Ohi[rbase + nn]     = h0;
                Ohi[rbase + nn + 1] = h1;
                Olo[rbase + nn]     = __float2bfloat16(v0 - __bfloat162float(h0));
                Olo[rbase + nn + 1] = __float2bfloat16(v1 - __bfloat162float(h1));
            } else {
                C[rbase + nn]     = v0;
                C[rbase + nn + 1] = v1;
            }
        }
    }
}

// ---------------- bf16x3 mma.sync GEMM, 512 thr, BK=32, 4-stage pipeline ----------------
// Order per chunk: wait2 -> sync (publish + protect) -> prefetch kt+3 -> compute kt.
#define GI_STAGE 40960                    // bytes per stage: 4 matrices x 10240
#define GI_SMEM  (4 * GI_STAGE)           // 163840
__global__ void __launch_bounds__(512) gemm_bf16x3(
    const bf16* __restrict__ Ahi, const bf16* __restrict__ Alo,
    const bf16* __restrict__ Whi, const bf16* __restrict__ Wlo,
    const float* __restrict__ bias, float* __restrict__ C, int K, int ldc)
{
    extern __shared__ char smem[];
    const uint32_t sb = saddr(smem);

    const int tid = threadIdx.x, lane = tid & 31, warp = tid >> 5;
    const int wm = warp & 3, wn = warp >> 2;
    const int bx = blockIdx.x, by = blockIdx.y;

    float acc[2][4][4];
#pragma unroll
    for (int mt = 0; mt < 2; mt++)
#pragma unroll
        for (int nt = 0; nt < 4; nt++)
#pragma unroll
            for (int i = 0; i < 4; i++) acc[mt][nt][i] = 0.f;

    const int nkt = K >> 5;
    const int lrow = tid >> 2, lkc = tid & 3;
    const uint32_t so = (uint32_t)(lrow * 80 + lkc * 16);
    const bf16* pa_hi = Ahi + (size_t)(by * 128 + lrow) * K + lkc * 8;
    const bf16* pa_lo = Alo + (size_t)(by * 128 + lrow) * K + lkc * 8;
    const bf16* pb_hi = Whi + (size_t)(bx * 128 + lrow) * K + lkc * 8;
    const bf16* pb_lo = Wlo + (size_t)(bx * 128 + lrow) * K + lkc * 8;

#define GI_LOAD(KT) do {                                   \
        const uint32_t st_ = sb + ((KT) & 3) * GI_STAGE;   \
        const int ko_ = (KT) * 32;                         \
        cpa16(st_ + so,          pa_hi + ko_);             \
        cpa16(st_ + 10240 + so,  pa_lo + ko_);             \
        cpa16(st_ + 20480 + so,  pb_hi + ko_);             \
        cpa16(st_ + 30720 + so,  pb_lo + ko_);             \
    } while (0)

    GI_LOAD(0); cpa_commit();
    GI_LOAD(1); cpa_commit();
    GI_LOAD(2); cpa_commit();

    for (int kt = 0; kt < nkt; kt++) {
        cpa_wait2();        // per-thread: groups 0..kt complete
        __syncthreads();    // publish stage kt; all warps past compute kt-1
        if (kt + 3 < nkt) GI_LOAD(kt + 3);   // overwrites buffer (kt-1)&3 (drained)
        cpa_commit();       // empty groups at tail keep wait_group arithmetic valid

        const uint32_t st = sb + (kt & 3) * GI_STAGE;
#pragma unroll
        for (int ks = 0; ks < 2; ks++) {
            const int kk = ks * 16;
            uint32_t ah[2][4], al[2][4];
#pragma unroll
            for (int mt = 0; mt < 2; mt++) {
                const int ar = wm * 32 + mt * 16 + (lane & 15);
                const int ac = kk + (lane >> 4) * 8;
                ldmx4(ah[mt], st + ar * 80 + ac * 2);
                ldmx4(al[mt], st + 10240 + ar * 80 + ac * 2);
            }
            uint32_t bh[4][2], bl[4][2];
#pragma unroll
            for (int nt = 0; nt < 4; nt++) {
                const int br = wn * 32 + nt * 8 + (lane & 7);
                const int bc = kk + ((lane >> 3) & 1) * 8;
                ldmx2(bh[nt], st + 20480 + br * 80 + bc * 2);
                ldmx2(bl[nt], st + 30720 + br * 80 + bc * 2);
            }
#pragma unroll
            for (int mt = 0; mt < 2; mt++)
#pragma unroll
                for (int nt = 0; nt < 4; nt++) {
                    mma_bf16(acc[mt][nt], ah[mt], bh[nt]);
                    mma_bf16(acc[mt][nt], ah[mt], bl[nt]);
                    mma_bf16(acc[mt][nt], al[mt], bh[nt]);
                }
        }
    }
#undef GI_LOAD

#pragma unroll
    for (int mt = 0; mt < 2; mt++) {
        const int r0 = by * 128 + wm * 32 + mt * 16 + (lane >> 2);
#pragma unroll
        for (int nt = 0; nt < 4; nt++) {
            const int c0 = bx * 128 + wn * 32 + nt * 8 + 2 * (lane & 3);
            const float b0 = bias[c0], b1 = bias[c0 + 1];
            C[(size_t)r0 * ldc + c0]           = acc[mt][nt][0] + b0;
            C[(size_t)r0 * ldc + c0 + 1]       = acc[mt][nt][1] + b1;
            C[(size_t)(r0 + 8) * ldc + c0]     = acc[mt][nt][2] + b0;
            C[(size_t)(r0 + 8) * ldc + c0 + 1] = acc[mt][nt][3] + b1;
        }
    }
}

// ---------------- zero hidden state ----------------
__global__ void zero_h_kernel() {
    const int n = 4 * BB * HH;
    float* pf = &g_hf[0][0][0];
    bf16* ph = &g_hhi[0][0][0];
    bf16* pl = &g_hlo[0][0][0];
    for (int i = blockIdx.x * blockDim.x + threadIdx.x; i < n;
         i += gridDim.x * blockDim.x) {
        pf[i] = 0.f;
        ph[i] = __float2bfloat16(0.f);
        pl[i] = __float2bfloat16(0.f);
    }
}

// ---------------- persistent GRU layer: W resident, BK=64, 2-stage swizzled H ----------------
// Per chunk: prefetch kt+1 -> commit -> wait1 -> sync (PUBLISH) -> compute -> sync (PROTECT).
#define WLO_OFF 99072     // bytes
#define HST_BASE 198144   // bytes
#define HST_STAGE 16384   // Hh 8KB + Hl 8KB
#define GRU_SMEM_BYTES (HST_BASE + 2 * HST_STAGE)   // 230912
__global__ void __launch_bounds__(256, 1) gru_mma_kernel(
    const float* __restrict__ gif, const float* __restrict__ gib,
    const bf16* __restrict__ whf_hi, const bf16* __restrict__ whf_lo,
    const bf16* __restrict__ whb_hi, const bf16* __restrict__ whb_lo,
    const float* __restrict__ bhhf, const float* __restrict__ bhhb,
    float* __restrict__ y, bf16* __restrict__ yhi, bf16* __restrict__ ylo)
{
    extern __shared__ char smem[];
    const uint32_t sb = saddr(smem);
    float* Cs = (float*)(smem + HST_BASE);   // overlays stage 0 only (13312 < 16384)

    const int tid = threadIdx.x, lane = tid & 31, warp = tid >> 5;
    const int dir = blockIdx.x >> 6;
    const int j0  = (blockIdx.x & 63) << 4;
    const int wm = warp & 3, wn = warp >> 2;
    const int m0 = wm * 16, n0 = wn * 24;

    const float* gi  = dir ? gib    : gif;
    const bf16* whhh = dir ? whb_hi : whf_hi;
    const bf16* whhl = dir ? whb_lo : whf_lo;
    const float* bhh = dir ? bhhb   : bhhf;

    const int ep_b [4] = { tid >> 4, (tid + 256) >> 4, (tid + 512) >> 4, (tid + 768) >> 4 };
    const int ep_jj = tid & 15;
    const int ep_j  = j0 + ep_jj;
    const float bh_r = bhh[ep_j];
    const float bh_z = bhh[HH + ep_j];
    const float bh_n = bhh[2 * HH + ep_j];

    // ---- load W slice into smem once (stride 2064B, conflict-free) ----
    for (int i = tid; i < 6144; i += 256) {
        const int row = i >> 7, kc = i & 127;
        const int grow = (row >> 4) * HH + j0 + (row & 15);
        const uint32_t dst = sb + (uint32_t)(row * 2064 + kc * 16);
        cpa16(dst,           whhh + (size_t)grow * HH + kc * 8);
        cpa16(dst + WLO_OFF, whhl + (size_t)grow * HH + kc * 8);
    }
    cpa_commit();
    cpa_wait0();
    __syncthreads();

    const uint32_t sWh = sb;
    const uint32_t sWl = sb + WLO_OFF;

    // H stage loads: 2 chunks/thread/half; row b (128B = full 64-k chunk), SW128 swizzle
    const int hl_b0 = tid >> 3;          // rows for i=0 (0..31) / +32 for i=1
    const int hl_c  = tid & 7;

    for (int s = 0; s < TT; s++) {
        const int t_idx = dir ? (TT - 1 - s) : s;
        const int rb = s & 1;
        const bf16* hhi = g_hhi[dir][rb];
        const bf16* hlo = g_hlo[dir][rb];
        const float* hpf = g_hf[dir][rb];
        float* hnf = g_hf[dir][rb ^ 1];
        bf16* hnhi = g_hhi[dir][rb ^ 1];
        bf16* hnlo = g_hlo[dir][rb ^ 1];

        // prefetch epilogue operands (hidden behind K loop)
        float pre_gr[4], pre_gz[4], pre_gn[4], pre_hp[4];
#pragma unroll
        for (int p = 0; p < 4; p++) {
            const size_t gbase = (size_t)(ep_b[p] * TT + t_idx) * G3;
            pre_gr[p] = __ldg(gi + gbase + ep_j);
            pre_gz[p] = __ldg(gi + gbase + HH + ep_j);
            pre_gn[p] = __ldg(gi + gbase + 2 * HH + ep_j);
            pre_hp[p] = __ldg(hpf + ep_b[p] * HH + ep_j);
        }

        float acc[3][4];
#pragma unroll
        for (int nt = 0; nt < 3; nt++)
#pragma unroll
            for (int i = 0; i < 4; i++) acc[nt][i] = 0.f;

#define H_LOAD(KT) do {                                                          \
        const uint32_t st_ = sb + HST_BASE + ((KT) & 1) * HST_STAGE;             \
        const int ko_ = (KT) * 64;                                               \
        _Pragma("unroll")                                                        \
        for (int i_ = 0; i_ < 2; i_++) {                                         \
            const int b_ = hl_b0 + i_ * 32;                                      \
            const uint32_t off_ = (uint32_t)(b_ * 128 +                          \
                                  ((hl_c * 16) ^ ((b_ & 7) << 4)));              \
            cpa16(st_ + off_,        hhi + (size_t)b_ * HH + ko_ + hl_c * 8);    \
            cpa16(st_ + 8192 + off_, hlo + (size_t)b_ * HH + ko_ + hl_c * 8);    \
        }                                                                        \
    } while (0)

        H_LOAD(0);
        cpa_commit();

        for (int kt = 0; kt < 16; kt++) {
            if (kt + 1 < 16) {
                // buffer (kt+1)&1 was last read in compute kt-1; the trailing
                // sync of iteration kt-1 protects it.
                H_LOAD(kt + 1);
                cpa_commit();
                cpa_wait1();          // loads 0..kt complete (per-thread)
            } else {
                cpa_wait0();
            }
            __syncthreads();          // PUBLISH stage kt across warps

            const uint32_t Hh = sb + HST_BASE + (kt & 1) * HST_STAGE;
            const uint32_t Hl = Hh + 8192;
#pragma unroll
            for (int ks = 0; ks < 4; ks++) {
                uint32_t ah[4], al[4];
                const int ar = m0 + (lane & 15);
                const uint32_t aoff = (uint32_t)(ar * 128 +
                    ((ks * 32 + (lane >> 4) * 16) ^ ((ar & 7) << 4)));
                ldmx4(ah, Hh + aoff);
                ldmx4(al, Hl + aoff);
                const int kcolg = kt * 64 + ks * 16 + (((lane >> 3) & 1) << 3);
#pragma unroll
                for (int nt = 0; nt < 3; nt++) {
                    const int brow = n0 + nt * 8 + (lane & 7);
                    uint32_t bh[2], bl[2];
                    ldmx2(bh, sWh + brow * 2064 + kcolg * 2);
                    ldmx2(bl, sWl + brow * 2064 + kcolg * 2);
                    mma_bf16(acc[nt], ah, bh);
                    mma_bf16(acc[nt], ah, bl);
                    mma_bf16(acc[nt], al, bh);
                }
            }
            __syncthreads();          // PROTECT buffer kt&1 before next H_LOAD(kt+2)
        }
#undef H_LOAD
        // trailing sync of kt=15 also guards the Cs overlay (stage-0 region)

#pragma unroll
        for (int nt = 0; nt < 3; nt++) {
            const int cr = m0 + (lane >> 2);
            const int cc = n0 + nt * 8 + 2 * (lane & 3);
            Cs[cr * 52 + cc]           = acc[nt][0];
            Cs[cr * 52 + cc + 1]       = acc[nt][1];
            Cs[(cr + 8) * 52 + cc]     = acc[nt][2];
            Cs[(cr + 8) * 52 + cc + 1] = acc[nt][3];
        }
        __syncthreads();

#pragma unroll
        for (int p = 0; p < 4; p++) {
            const int b = ep_b[p];
            const float cr = Cs[b * 52 + ep_jj]      + bh_r;
            const float cz = Cs[b * 52 + 16 + ep_jj] + bh_z;
            const float cn = Cs[b * 52 + 32 + ep_jj] + bh_n;
            const float rr = fast_sigmoid(pre_gr[p] + cr);
            const float zz = fast_sigmoid(pre_gz[p] + cz);
            const float nn = fast_tanh(pre_gn[p] + rr * cn);
            const float hp = pre_hp[p];
            const float hn = (1.f - zz) * nn + zz * hp;
            hnf[b * HH + ep_j] = hn;
            bf16 hh = __float2bfloat16(hn);
            hnhi[b * HH + ep_j] = hh;
            hnlo[b * HH + ep_j] = __float2bfloat16(hn - __bfloat162float(hh));
            const size_t yb = (size_t)(b * TT + t_idx) * (2 * HH) + dir * HH + ep_j;
            y[yb] = hn;
            yhi[yb] = hh;
            ylo[yb] = __float2bfloat16(hn - __bfloat162float(hh));
        }
        dir_barrier(dir, 64);
    }
}

// ---------------- final mean ----------------
__global__ void mean_kernel(const float* __restrict__ y, float* __restrict__ out) {
    const int b = blockIdx.x;
    const int tid = threadIdx.x;
    const size_t base = (size_t)b * TT * 2 * HH;
    float s = 0.f;
    for (int i = tid; i < TT * 2 * HH; i += 256) s += y[base + i];
    __shared__ float red[256];
    red[tid] = s;
    __syncthreads();
    for (int o = 128; o > 0; o >>= 1) {
        if (tid < o) red[tid] += red[tid + o];
        __syncthreads();
    }
    if (tid == 0) out[b] = red[0] / (float)(TT * 2 * HH);
}

// ---------------- launcher ----------------
extern "C" void kernel_launch(void* const* d_in, const int* in_sizes, int n_in,
                              void* d_out, int out_size)
{
    const float* cond     = (const float*)d_in[0];
    const float* input    = (const float*)d_in[1];
    const float* ce_w1    = (const float*)d_in[2];
    const float* ce_b1    = (const float*)d_in[3];
    const float* ce_w2    = (const float*)d_in[4];
    const float* ce_b2    = (const float*)d_in[5];
    const float* me_w1    = (const float*)d_in[6];
    const float* me_b1    = (const float*)d_in[7];
    const float* me_w2    = (const float*)d_in[8];
    const float* me_b2    = (const float*)d_in[9];
    const float* w_ih_l0f = (const float*)d_in[10];
    const float* w_hh_l0f = (const float*)d_in[11];
    const float* b_ih_l0f = (const float*)d_in[12];
    const float* b_hh_l0f = (const float*)d_in[13];
    const float* w_ih_l0b = (const float*)d_in[14];
    const float* w_hh_l0b = (const float*)d_in[15];
    const float* b_ih_l0b = (const float*)d_in[16];
    const float* b_hh_l0b = (const float*)d_in[17];
    const float* w_ih_l1f = (const float*)d_in[18];
    const float* w_hh_l1f = (const float*)d_in[19];
    const float* b_ih_l1f = (const float*)d_in[20];
    const float* b_hh_l1f = (const float*)d_in[21];
    const float* w_ih_l1b = (const float*)d_in[22];
    const float* w_hh_l1b = (const float*)d_in[23];
    const float* b_ih_l1b = (const float*)d_in[24];
    const float* b_hh_l1b = (const float*)d_in[25];
    float* out = (float*)d_out;

    void* p;
    cudaGetSymbolAddress(&p, g_h1);    float* s_h1  = (float*)p;
    cudaGetSymbolAddress(&p, g_y);     float* s_y   = (float*)p;
    cudaGetSymbolAddress(&p, g_xhi);   bf16*  s_xhi = (bf16*)p;
    cudaGetSymbolAddress(&p, g_xlo);   bf16*  s_xlo = (bf16*)p;
    cudaGetSymbolAddress(&p, g_yhi);   bf16*  s_yhi = (bf16*)p;
    cudaGetSymbolAddress(&p, g_ylo);   bf16*  s_ylo = (bf16*)p;
    cudaGetSymbolAddress(&p, g_gif);   float* s_gif = (float*)p;
    cudaGetSymbolAddress(&p, g_gib);   float* s_gib = (float*)p;
    cudaGetSymbolAddress(&p, g_wihhi); bf16*  s_wih_hi = (bf16*)p;
    cudaGetSymbolAddress(&p, g_wihlo); bf16*  s_wih_lo = (bf16*)p;
    cudaGetSymbolAddress(&p, g_whhhi); bf16*  s_whh_hi = (bf16*)p;
    cudaGetSymbolAddress(&p, g_whhlo); bf16*  s_whh_lo = (bf16*)p;

    cudaFuncSetAttribute(gemm_bf16x3, cudaFuncAttributeMaxDynamicSharedMemorySize, GI_SMEM);
    cudaFuncSetAttribute(gru_mma_kernel, cudaFuncAttributeMaxDynamicSharedMemorySize, GRU_SMEM_BYTES);

    const size_t WIH0 = (size_t)G3 * HH;
    const size_t WHH  = (size_t)G3 * HH;

    SplitJobs jobs;
    jobs.src[0] = w_ih_l0f; jobs.hi[0] = s_wih_hi;            jobs.lo[0] = s_wih_lo;            jobs.n4[0] = (unsigned)(WIH0 >> 2);
    jobs.src[1] = w_ih_l0b; jobs.hi[1] = s_wih_hi + WIH0;     jobs.lo[1] = s_wih_lo + WIH0;     jobs.n4[1] = (unsigned)(WIH0 >> 2);
    jobs.src[2] = w_ih_l1f; jobs.hi[2] = s_wih_hi + 2*WIH0;   jobs.lo[2] = s_wih_lo + 2*WIH0;   jobs.n4[2] = (unsigned)(WIH0 >> 1);
    jobs.src[3] = w_ih_l1b; jobs.hi[3] = s_wih_hi + 4*WIH0;   jobs.lo[3] = s_wih_lo + 4*WIH0;   jobs.n4[3] = (unsigned)(WIH0 >> 1);
    jobs.src[4] = w_hh_l0f; jobs.hi[4] = s_whh_hi;            jobs.lo[4] = s_whh_lo;            jobs.n4[4] = (unsigned)(WHH >> 2);
    jobs.src[5] = w_hh_l0b; jobs.hi[5] = s_whh_hi + WHH;      jobs.lo[5] = s_whh_lo + WHH;      jobs.n4[5] = (unsigned)(WHH >> 2);
    jobs.src[6] = w_hh_l1f; jobs.hi[6] = s_whh_hi + 2*WHH;    jobs.lo[6] = s_whh_lo + 2*WHH;    jobs.n4[6] = (unsigned)(WHH >> 2);
    jobs.src[7] = w_hh_l1b; jobs.hi[7] = s_whh_hi + 3*WHH;    jobs.lo[7] = s_whh_lo + 3*WHH;    jobs.n4[7] = (unsigned)(WHH >> 2);
    split_w_kernel<<<dim3(160, 8), 256>>>(jobs);

    dim3 blk(256);
    gemm_nt_kernel<<<dim3(H4 / 128, MR / 128), blk>>>(cond,  ce_w1, ce_b1, s_h1, nullptr, nullptr, CONDD, H4,  0,   1);
    gemm_nt_kernel<<<dim3(H2 / 128, MR / 128), blk>>>(s_h1,  ce_w2, ce_b2, nullptr, s_xhi, s_xlo, H4,    HH,  0,   0);
    gemm_nt_kernel<<<dim3(H4 / 128, MR / 128), blk>>>(input, me_w1, me_b1, s_h1, nullptr, nullptr, OUTD,  H4,  0,   1);
    gemm_nt_kernel<<<dim3(H2 / 128, MR / 128), blk>>>(s_h1,  me_w2, me_b2, nullptr, s_xhi, s_xlo, H4,    HH,  512, 0);

    dim3 blk2(512);
    gemm_bf16x3<<<dim3(G3 / 128, MR / 128), blk2, GI_SMEM>>>(
        s_xhi, s_xlo, s_wih_hi, s_wih_lo, b_ih_l0f, s_gif, HH, G3);
    gemm_bf16x3<<<dim3(G3 / 128, MR / 128), blk2, GI_SMEM>>>(
        s_xhi, s_xlo, s_wih_hi + WIH0, s_wih_lo + WIH0, b_ih_l0b, s_gib, HH, G3);
    zero_h_kernel<<<64, 256>>>();
    gru_mma_kernel<<<128, 256, GRU_SMEM_BYTES>>>(
        s_gif, s_gib,
        s_whh_hi, s_whh_lo, s_whh_hi + WHH, s_whh_lo + WHH,
        b_hh_l0f, b_hh_l0b, s_y, s_yhi, s_ylo);

    gemm_bf16x3<<<dim3(G3 / 128, MR / 128), blk2, GI_SMEM>>>(
        s_yhi, s_ylo, s_wih_hi + 2*WIH0, s_wih_lo + 2*WIH0, b_ih_l1f, s_gif, 2 * HH, G3);
    gemm_bf16x3<<<dim3(G3 / 128, MR / 128), blk2, GI_SMEM>>>(
        s_yhi, s_ylo, s_wih_hi + 4*WIH0, s_wih_lo + 4*WIH0, b_ih_l1b, s_gib, 2 * HH, G3);
    zero_h_kernel<<<64, 256>>>();
    gru_mma_kernel<<<128, 256, GRU_SMEM_BYTES>>>(
        s_gif, s_gib,
        s_whh_hi + 2*WHH, s_whh_lo + 2*WHH, s_whh_hi + 3*WHH, s_whh_lo + 3*WHH,
        b_hh_l1f, b_hh_l1b, s_y, s_yhi, s_ylo);

    mean_kernel<<<BB, 256>>>(s_y, out);
}

// round 11
// speedup vs baseline: 4.1235x; 1.0714x over previous
#include <cuda_runtime.h>
#include <cuda_bf16.h>
#include <math.h>
#include <stdint.h>

#define BB    64
#define TT    300
#define CONDD 64
#define OUTD  72
#define HH    1024
#define H4    256
#define H2    512
#define G3    3072
#define MR    (BB*TT)

typedef __nv_bfloat16 bf16;

// ---------------- device globals ----------------
__device__ float g_h1 [MR * H4];
__device__ float g_y  [(size_t)MR * 2 * HH];
__device__ bf16  g_xhi[(size_t)MR * HH],     g_xlo[(size_t)MR * HH];
__device__ bf16  g_yhi[(size_t)MR * 2 * HH], g_ylo[(size_t)MR * 2 * HH];
__device__ float g_gif[(size_t)MR * G3], g_gib[(size_t)MR * G3];
__device__ float g_hf [2][2][BB * HH];
__device__ bf16  g_hhi[2][2][BB * HH], g_hlo[2][2][BB * HH];
__device__ bf16  g_wihhi[(size_t)6 * G3 * HH], g_wihlo[(size_t)6 * G3 * HH];
__device__ bf16  g_whhhi[(size_t)4 * G3 * HH], g_whhlo[(size_t)4 * G3 * HH];
__device__ unsigned int g_barc[2];
__device__ unsigned int g_barg[2];

// ---------------- helpers ----------------
__device__ __forceinline__ uint32_t saddr(const void* p) {
    return (uint32_t)__cvta_generic_to_shared(p);
}
__device__ __forceinline__ void cpa16(uint32_t s, const void* g) {
    asm volatile("cp.async.cg.shared.global [%0], [%1], 16;" :: "r"(s), "l"(g));
}
__device__ __forceinline__ void cpa_commit() { asm volatile("cp.async.commit_group;"); }
__device__ __forceinline__ void cpa_wait2() { asm volatile("cp.async.wait_group 2;"); }
__device__ __forceinline__ void cpa_wait1() { asm volatile("cp.async.wait_group 1;"); }
__device__ __forceinline__ void cpa_wait0() { asm volatile("cp.async.wait_group 0;"); }

__device__ __forceinline__ void ldmx4(uint32_t* r, uint32_t a) {
    asm volatile("ldmatrix.sync.aligned.m8n8.x4.shared.b16 {%0,%1,%2,%3}, [%4];"
                 : "=r"(r[0]), "=r"(r[1]), "=r"(r[2]), "=r"(r[3]) : "r"(a));
}
__device__ __forceinline__ void ldmx2(uint32_t* r, uint32_t a) {
    asm volatile("ldmatrix.sync.aligned.m8n8.x2.shared.b16 {%0,%1}, [%2];"
                 : "=r"(r[0]), "=r"(r[1]) : "r"(a));
}
__device__ __forceinline__ void mma_bf16(float* c, const uint32_t* a, const uint32_t* b) {
    asm volatile("mma.sync.aligned.m16n8k16.row.col.f32.bf16.bf16.f32 "
                 "{%0,%1,%2,%3}, {%4,%5,%6,%7}, {%8,%9}, {%0,%1,%2,%3};"
                 : "+f"(c[0]), "+f"(c[1]), "+f"(c[2]), "+f"(c[3])
                 : "r"(a[0]), "r"(a[1]), "r"(a[2]), "r"(a[3]), "r"(b[0]), "r"(b[1]));
}

__device__ __forceinline__ unsigned long long ffma2(unsigned long long a,
                                                    unsigned long long b,
                                                    unsigned long long c) {
    unsigned long long d;
    asm("fma.rn.f32x2 %0, %1, %2, %3;" : "=l"(d) : "l"(a), "l"(b), "l"(c));
    return d;
}
__device__ __forceinline__ unsigned long long pack2(float x, float y) {
    unsigned long long d;
    asm("mov.b64 %0, {%1, %2};" : "=l"(d) : "f"(x), "f"(y));
    return d;
}
__device__ __forceinline__ void unpack2(unsigned long long p, float& lo, float& hi) {
    asm("mov.b64 {%0, %1}, %2;" : "=f"(lo), "=f"(hi) : "l"(p));
}

__device__ __forceinline__ float fast_sigmoid(float x) {
    return 1.f / (1.f + __expf(-x));
}
__device__ __forceinline__ float fast_tanh(float x) {
    float r;
    asm("tanh.approx.f32 %0, %1;" : "=f"(r) : "f"(x));
    return r;
}

// per-direction software grid barrier (graph-capturable)
__device__ __forceinline__ void dir_barrier(int dir, unsigned int nb) {
    __syncthreads();
    if (threadIdx.x == 0) {
        __threadfence();
        unsigned int gen = *(volatile unsigned int*)&g_barg[dir];
        unsigned int arrived = atomicAdd(&g_barc[dir], 1u);
        if (arrived == nb - 1u) {
            g_barc[dir] = 0u;
            __threadfence();
            atomicExch(&g_barg[dir], gen + 1u);
        } else {
            while (*(volatile unsigned int*)&g_barg[dir] == gen) { __nanosleep(20); }
        }
        __threadfence();
    }
    __syncthreads();
}

// ---------------- fused weight split: 8 jobs in one launch ----------------
struct SplitJobs {
    const float* src[8];
    bf16* hi[8];
    bf16* lo[8];
    unsigned int n4[8];
};
__global__ void split_w_kernel(SplitJobs jobs) {
    const int j = blockIdx.y;
    const float4* s = (const float4*)jobs.src[j];
    ushort4* hi = (ushort4*)jobs.hi[j];
    ushort4* lo = (ushort4*)jobs.lo[j];
    const unsigned int n4 = jobs.n4[j];
    for (unsigned int i = blockIdx.x * blockDim.x + threadIdx.x; i < n4;
         i += gridDim.x * blockDim.x) {
        float4 v = s[i];
        bf16 h0 = __float2bfloat16(v.x), h1 = __float2bfloat16(v.y);
        bf16 h2 = __float2bfloat16(v.z), h3 = __float2bfloat16(v.w);
        ushort4 hv, lv;
        hv.x = __bfloat16_as_ushort(h0); hv.y = __bfloat16_as_ushort(h1);
        hv.z = __bfloat16_as_ushort(h2); hv.w = __bfloat16_as_ushort(h3);
        lv.x = __bfloat16_as_ushort(__float2bfloat16(v.x - __bfloat162float(h0)));
        lv.y = __bfloat16_as_ushort(__float2bfloat16(v.y - __bfloat162float(h1)));
        lv.z = __bfloat16_as_ushort(__float2bfloat16(v.z - __bfloat162float(h2)));
        lv.w = __bfloat16_as_ushort(__float2bfloat16(v.w - __bfloat162float(h3)));
        hi[i] = hv;
        lo[i] = lv;
    }
}

// ---------------- encoder FFMA2 GEMM (optional fused bf16 split output) ----------------
__global__ void __launch_bounds__(256) gemm_nt_kernel(
    const float* __restrict__ A, const float* __restrict__ W,
    const float* __restrict__ bias, float* __restrict__ C,
    bf16* __restrict__ Ohi, bf16* __restrict__ Olo,
    int K, int ldc, int coff, int leaky)
{
    __shared__ float As[8][128];
    __shared__ float Bs[8][128];
    const int tid = threadIdx.x;
    const int bx = blockIdx.x, by = blockIdx.y;
    const int tx = tid & 15, ty = tid >> 4;
    const int r  = tid >> 1;
    const int cq = (tid & 1) * 4;
    const float* Ap = A + (size_t)(by * 128 + r) * K + cq;
    const float* Wp = W + (size_t)(bx * 128 + r) * K + cq;

    unsigned long long acc[8][4];
#pragma unroll
    for (int m = 0; m < 8; m++)
#pragma unroll
        for (int p = 0; p < 4; p++) acc[m][p] = 0ULL;

    const int nkt = K >> 3;
    for (int kt = 0; kt < nkt; kt++) {
        __syncthreads();
        float4 av = *(const float4*)(Ap + kt * 8);
        float4 wv = *(const float4*)(Wp + kt * 8);
        As[cq + 0][r] = av.x; As[cq + 1][r] = av.y; As[cq + 2][r] = av.z; As[cq + 3][r] = av.w;
        Bs[cq + 0][r] = wv.x; Bs[cq + 1][r] = wv.y; Bs[cq + 2][r] = wv.z; Bs[cq + 3][r] = wv.w;
        __syncthreads();
#pragma unroll
        for (int k = 0; k < 8; k++) {
            float4 a0 = *(const float4*)&As[k][ty * 8];
            float4 a1 = *(const float4*)&As[k][ty * 8 + 4];
            ulonglong2 bq0 = *(const ulonglong2*)&Bs[k][tx * 8];
            ulonglong2 bq1 = *(const ulonglong2*)&Bs[k][tx * 8 + 4];
            float a[8] = {a0.x, a0.y, a0.z, a0.w, a1.x, a1.y, a1.z, a1.w};
#pragma unroll
            for (int m = 0; m < 8; m++) {
                unsigned long long ap = pack2(a[m], a[m]);
                acc[m][0] = ffma2(ap, bq0.x, acc[m][0]);
                acc[m][1] = ffma2(ap, bq0.y, acc[m][1]);
                acc[m][2] = ffma2(ap, bq1.x, acc[m][2]);
                acc[m][3] = ffma2(ap, bq1.y, acc[m][3]);
            }
        }
    }
#pragma unroll
    for (int m = 0; m < 8; m++) {
        const int row = by * 128 + ty * 8 + m;
        const size_t rbase = (size_t)row * ldc + coff;
#pragma unroll
        for (int p = 0; p < 4; p++) {
            float lo, hi;
            unpack2(acc[m][p], lo, hi);
            const int nn = bx * 128 + tx * 8 + p * 2;
            float v0 = lo + bias[nn];
            float v1 = hi + bias[nn + 1];
            if (leaky) {
                v0 = (v0 >= 0.f) ? v0 : 0.2f * v0;
                v1 = (v1 >= 0.f) ? v1 : 0.2f * v1;
            }
            if (Ohi) {
                bf16 h0 = __float2bfloat16(v0), h1 = __float2bfloat16(v1);
                Ohi[rbase + nn]     = h0;
                Ohi[rbase + nn + 1] = h1;
                Olo[rbase + nn]     = __float2bfloat16(v0 - __bfloat162float(h0));
                Olo[rbase + nn + 1] = __float2bfloat16(v1 - __bfloat162float(h1));
            } else {
                C[rbase + nn]     = v0;
                C[rbase + nn + 1] = v1;
            }
        }
    }
}

// ---------------- bf16x3 mma.sync GEMM, 512 thr, BK=32, 4-stage pipeline ----------------
// B fragments loaded as n-tile PAIRS via ldmatrix.x4 (halves LDSM issue count).
#define GI_STAGE 40960                    // bytes per stage: 4 matrices x 10240
#define GI_SMEM  (4 * GI_STAGE)           // 163840
__global__ void __launch_bounds__(512) gemm_bf16x3(
    const bf16* __restrict__ Ahi, const bf16* __restrict__ Alo,
    const bf16* __restrict__ Whi, const bf16* __restrict__ Wlo,
    const float* __restrict__ bias, float* __restrict__ C, int K, int ldc)
{
    extern __shared__ char smem[];
    const uint32_t sb = saddr(smem);

    const int tid = threadIdx.x, lane = tid & 31, warp = tid >> 5;
    const int wm = warp & 3, wn = warp >> 2;
    const int bx = blockIdx.x, by = blockIdx.y;

    float acc[2][4][4];
#pragma unroll
    for (int mt = 0; mt < 2; mt++)
#pragma unroll
        for (int nt = 0; nt < 4; nt++)
#pragma unroll
            for (int i = 0; i < 4; i++) acc[mt][nt][i] = 0.f;

    const int nkt = K >> 5;
    const int lrow = tid >> 2, lkc = tid & 3;
    const uint32_t so = (uint32_t)(lrow * 80 + lkc * 16);
    const bf16* pa_hi = Ahi + (size_t)(by * 128 + lrow) * K + lkc * 8;
    const bf16* pa_lo = Alo + (size_t)(by * 128 + lrow) * K + lkc * 8;
    const bf16* pb_hi = Whi + (size_t)(bx * 128 + lrow) * K + lkc * 8;
    const bf16* pb_lo = Wlo + (size_t)(bx * 128 + lrow) * K + lkc * 8;

#define GI_LOAD(KT) do {                                   \
        const uint32_t st_ = sb + ((KT) & 3) * GI_STAGE;   \
        const int ko_ = (KT) * 32;                         \
        cpa16(st_ + so,          pa_hi + ko_);             \
        cpa16(st_ + 10240 + so,  pa_lo + ko_);             \
        cpa16(st_ + 20480 + so,  pb_hi + ko_);             \
        cpa16(st_ + 30720 + so,  pb_lo + ko_);             \
    } while (0)

    GI_LOAD(0); cpa_commit();
    GI_LOAD(1); cpa_commit();
    GI_LOAD(2); cpa_commit();

    for (int kt = 0; kt < nkt; kt++) {
        cpa_wait2();        // per-thread: groups 0..kt complete
        __syncthreads();    // publish stage kt; all warps past compute kt-1
        if (kt + 3 < nkt) GI_LOAD(kt + 3);   // overwrites buffer (kt-1)&3 (drained)
        cpa_commit();       // empty groups at tail keep wait_group arithmetic valid

        const uint32_t st = sb + (kt & 3) * GI_STAGE;
#pragma unroll
        for (int ks = 0; ks < 2; ks++) {
            const int kk = ks * 16;
            uint32_t ah[2][4], al[2][4];
#pragma unroll
            for (int mt = 0; mt < 2; mt++) {
                const int ar = wm * 32 + mt * 16 + (lane & 15);
                const int ac = kk + (lane >> 4) * 8;
                ldmx4(ah[mt], st + ar * 80 + ac * 2);
                ldmx4(al[mt], st + 10240 + ar * 80 + ac * 2);
            }
            // B: two n-tile pairs via ldmatrix.x4 each (hi+lo)
            uint32_t bh[2][4], bl[2][4];
#pragma unroll
            for (int pr = 0; pr < 2; pr++) {
                const int br = wn * 32 + pr * 16 + (lane & 7) + ((lane >> 4) << 3);
                const int bc = kk + (((lane >> 3) & 1) << 3);
                ldmx4(bh[pr], st + 20480 + br * 80 + bc * 2);
                ldmx4(bl[pr], st + 30720 + br * 80 + bc * 2);
            }
#pragma unroll
            for (int mt = 0; mt < 2; mt++)
#pragma unroll
                for (int nt = 0; nt < 4; nt++) {
                    const uint32_t* bhp = &bh[nt >> 1][(nt & 1) * 2];
                    const uint32_t* blp = &bl[nt >> 1][(nt & 1) * 2];
                    mma_bf16(acc[mt][nt], ah[mt], bhp);
                    mma_bf16(acc[mt][nt], ah[mt], blp);
                    mma_bf16(acc[mt][nt], al[mt], bhp);
                }
        }
    }
#undef GI_LOAD

#pragma unroll
    for (int mt = 0; mt < 2; mt++) {
        const int r0 = by * 128 + wm * 32 + mt * 16 + (lane >> 2);
#pragma unroll
        for (int nt = 0; nt < 4; nt++) {
            const int c0 = bx * 128 + wn * 32 + nt * 8 + 2 * (lane & 3);
            const float b0 = bias[c0], b1 = bias[c0 + 1];
            C[(size_t)r0 * ldc + c0]           = acc[mt][nt][0] + b0;
            C[(size_t)r0 * ldc + c0 + 1]       = acc[mt][nt][1] + b1;
            C[(size_t)(r0 + 8) * ldc + c0]     = acc[mt][nt][2] + b0;
            C[(size_t)(r0 + 8) * ldc + c0 + 1] = acc[mt][nt][3] + b1;
        }
    }
}

// ---------------- zero hidden state ----------------
__global__ void zero_h_kernel() {
    const int n = 4 * BB * HH;
    float* pf = &g_hf[0][0][0];
    bf16* ph = &g_hhi[0][0][0];
    bf16* pl = &g_hlo[0][0][0];
    for (int i = blockIdx.x * blockDim.x + threadIdx.x; i < n;
         i += gridDim.x * blockDim.x) {
        pf[i] = 0.f;
        ph[i] = __float2bfloat16(0.f);
        pl[i] = __float2bfloat16(0.f);
    }
}

// ---------------- persistent GRU layer: W resident, BK=64, 2-stage swizzled H ----------------
// Per chunk: prefetch kt+1 -> commit -> wait1 -> sync (PUBLISH) -> compute -> sync (PROTECT).
// W fragments: nt{0,1} via one ldmatrix.x4, nt2 via ldmatrix.x2 (per half).
#define WLO_OFF 99072     // bytes
#define HST_BASE 198144   // bytes
#define HST_STAGE 16384   // Hh 8KB + Hl 8KB
#define GRU_SMEM_BYTES (HST_BASE + 2 * HST_STAGE)   // 230912
__global__ void __launch_bounds__(256, 1) gru_mma_kernel(
    const float* __restrict__ gif, const float* __restrict__ gib,
    const bf16* __restrict__ whf_hi, const bf16* __restrict__ whf_lo,
    const bf16* __restrict__ whb_hi, const bf16* __restrict__ whb_lo,
    const float* __restrict__ bhhf, const float* __restrict__ bhhb,
    float* __restrict__ y, bf16* __restrict__ yhi, bf16* __restrict__ ylo)
{
    extern __shared__ char smem[];
    const uint32_t sb = saddr(smem);
    float* Cs = (float*)(smem + HST_BASE);   // overlays stage 0 only (13312 < 16384)

    const int tid = threadIdx.x, lane = tid & 31, warp = tid >> 5;
    const int dir = blockIdx.x >> 6;
    const int j0  = (blockIdx.x & 63) << 4;
    const int wm = warp & 3, wn = warp >> 2;
    const int m0 = wm * 16, n0 = wn * 24;

    const float* gi  = dir ? gib    : gif;
    const bf16* whhh = dir ? whb_hi : whf_hi;
    const bf16* whhl = dir ? whb_lo : whf_lo;
    const float* bhh = dir ? bhhb   : bhhf;

    const int ep_b [4] = { tid >> 4, (tid + 256) >> 4, (tid + 512) >> 4, (tid + 768) >> 4 };
    const int ep_jj = tid & 15;
    const int ep_j  = j0 + ep_jj;
    const float bh_r = bhh[ep_j];
    const float bh_z = bhh[HH + ep_j];
    const float bh_n = bhh[2 * HH + ep_j];

    // ---- load W slice into smem once (stride 2064B, conflict-free) ----
    for (int i = tid; i < 6144; i += 256) {
        const int row = i >> 7, kc = i & 127;
        const int grow = (row >> 4) * HH + j0 + (row & 15);
        const uint32_t dst = sb + (uint32_t)(row * 2064 + kc * 16);
        cpa16(dst,           whhh + (size_t)grow * HH + kc * 8);
        cpa16(dst + WLO_OFF, whhl + (size_t)grow * HH + kc * 8);
    }
    cpa_commit();
    cpa_wait0();
    __syncthreads();

    const uint32_t sWh = sb;
    const uint32_t sWl = sb + WLO_OFF;

    // H stage loads: 2 chunks/thread/half; row b (128B = full 64-k chunk), SW128 swizzle
    const int hl_b0 = tid >> 3;          // rows for i=0 (0..31) / +32 for i=1
    const int hl_c  = tid & 7;

    for (int s = 0; s < TT; s++) {
        const int t_idx = dir ? (TT - 1 - s) : s;
        const int rb = s & 1;
        const bf16* hhi = g_hhi[dir][rb];
        const bf16* hlo = g_hlo[dir][rb];
        const float* hpf = g_hf[dir][rb];
        float* hnf = g_hf[dir][rb ^ 1];
        bf16* hnhi = g_hhi[dir][rb ^ 1];
        bf16* hnlo = g_hlo[dir][rb ^ 1];

        // prefetch epilogue operands (hidden behind K loop)
        float pre_gr[4], pre_gz[4], pre_gn[4], pre_hp[4];
#pragma unroll
        for (int p = 0; p < 4; p++) {
            const size_t gbase = (size_t)(ep_b[p] * TT + t_idx) * G3;
            pre_gr[p] = __ldg(gi + gbase + ep_j);
            pre_gz[p] = __ldg(gi + gbase + HH + ep_j);
            pre_gn[p] = __ldg(gi + gbase + 2 * HH + ep_j);
            pre_hp[p] = __ldg(hpf + ep_b[p] * HH + ep_j);
        }

        float acc[3][4];
#pragma unroll
        for (int nt = 0; nt < 3; nt++)
#pragma unroll
            for (int i = 0; i < 4; i++) acc[nt][i] = 0.f;

#define H_LOAD(KT) do {                                                          \
        const uint32_t st_ = sb + HST_BASE + ((KT) & 1) * HST_STAGE;             \
        const int ko_ = (KT) * 64;                                               \
        _Pragma("unroll")                                                        \
        for (int i_ = 0; i_ < 2; i_++) {                                         \
            const int b_ = hl_b0 + i_ * 32;                                      \
            const uint32_t off_ = (uint32_t)(b_ * 128 +                          \
                                  ((hl_c * 16) ^ ((b_ & 7) << 4)));              \
            cpa16(st_ + off_,        hhi + (size_t)b_ * HH + ko_ + hl_c * 8);    \
            cpa16(st_ + 8192 + off_, hlo + (size_t)b_ * HH + ko_ + hl_c * 8);    \
        }                                                                        \
    } while (0)

        H_LOAD(0);
        cpa_commit();

        for (int kt = 0; kt < 16; kt++) {
            if (kt + 1 < 16) {
                // buffer (kt+1)&1 was last read in compute kt-1; the trailing
                // sync of iteration kt-1 protects it.
                H_LOAD(kt + 1);
                cpa_commit();
                cpa_wait1();          // loads 0..kt complete (per-thread)
            } else {
                cpa_wait0();
            }
            __syncthreads();          // PUBLISH stage kt across warps

            const uint32_t Hh = sb + HST_BASE + (kt & 1) * HST_STAGE;
            const uint32_t Hl = Hh + 8192;
#pragma unroll
            for (int ks = 0; ks < 4; ks++) {
                uint32_t ah[4], al[4];
                const int ar = m0 + (lane & 15);
                const uint32_t aoff = (uint32_t)(ar * 128 +
                    ((ks * 32 + (lane >> 4) * 16) ^ ((ar & 7) << 4)));
                ldmx4(ah, Hh + aoff);
                ldmx4(al, Hl + aoff);
                const int kcolg = kt * 64 + ks * 16 + (((lane >> 3) & 1) << 3);
                // W frags: pair (nt0,nt1) via ldmatrix.x4, nt2 via ldmatrix.x2
                uint32_t bh4[4], bl4[4], bh2[2], bl2[2];
                {
                    const int brp = n0 + (lane & 7) + ((lane >> 4) << 3);
                    ldmx4(bh4, sWh + brp * 2064 + kcolg * 2);
                    ldmx4(bl4, sWl + brp * 2064 + kcolg * 2);
                    const int br2 = n0 + 16 + (lane & 7);
                    ldmx2(bh2, sWh + br2 * 2064 + kcolg * 2);
                    ldmx2(bl2, sWl + br2 * 2064 + kcolg * 2);
                }
                mma_bf16(acc[0], ah, &bh4[0]);
                mma_bf16(acc[0], ah, &bl4[0]);
                mma_bf16(acc[0], al, &bh4[0]);
                mma_bf16(acc[1], ah, &bh4[2]);
                mma_bf16(acc[1], ah, &bl4[2]);
                mma_bf16(acc[1], al, &bh4[2]);
                mma_bf16(acc[2], ah, bh2);
                mma_bf16(acc[2], ah, bl2);
                mma_bf16(acc[2], al, bh2);
            }
            __syncthreads();          // PROTECT buffer kt&1 before next H_LOAD(kt+2)
        }
#undef H_LOAD
        // trailing sync of kt=15 also guards the Cs overlay (stage-0 region)

#pragma unroll
        for (int nt = 0; nt < 3; nt++) {
            const int cr = m0 + (lane >> 2);
            const int cc = n0 + nt * 8 + 2 * (lane & 3);
            Cs[cr * 52 + cc]           = acc[nt][0];
            Cs[cr * 52 + cc + 1]       = acc[nt][1];
            Cs[(cr + 8) * 52 + cc]     = acc[nt][2];
            Cs[(cr + 8) * 52 + cc + 1] = acc[nt][3];
        }
        __syncthreads();

#pragma unroll
        for (int p = 0; p < 4; p++) {
            const int b = ep_b[p];
            const float cr = Cs[b * 52 + ep_jj]      + bh_r;
            const float cz = Cs[b * 52 + 16 + ep_jj] + bh_z;
            const float cn = Cs[b * 52 + 32 + ep_jj] + bh_n;
            const float rr = fast_sigmoid(pre_gr[p] + cr);
            const float zz = fast_sigmoid(pre_gz[p] + cz);
            const float nn = fast_tanh(pre_gn[p] + rr * cn);
            const float hp = pre_hp[p];
            const float hn = (1.f - zz) * nn + zz * hp;
            hnf[b * HH + ep_j] = hn;
            bf16 hh = __float2bfloat16(hn);
            hnhi[b * HH + ep_j] = hh;
            hnlo[b * HH + ep_j] = __float2bfloat16(hn - __bfloat162float(hh));
            const size_t yb = (size_t)(b * TT + t_idx) * (2 * HH) + dir * HH + ep_j;
            y[yb] = hn;
            yhi[yb] = hh;
            ylo[yb] = __float2bfloat16(hn - __bfloat162float(hh));
        }
        dir_barrier(dir, 64);
    }
}

// ---------------- final mean ----------------
__global__ void mean_kernel(const float* __restrict__ y, float* __restrict__ out) {
    const int b = blockIdx.x;
    const int tid = threadIdx.x;
    const size_t base = (size_t)b * TT * 2 * HH;
    float s = 0.f;
    for (int i = tid; i < TT * 2 * HH; i += 256) s += y[base + i];
    __shared__ float red[256];
    red[tid] = s;
    __syncthreads();
    for (int o = 128; o > 0; o >>= 1) {
        if (tid < o) red[tid] += red[tid + o];
        __syncthreads();
    }
    if (tid == 0) out[b] = red[0] / (float)(TT * 2 * HH);
}

// ---------------- launcher ----------------
extern "C" void kernel_launch(void* const* d_in, const int* in_sizes, int n_in,
                              void* d_out, int out_size)
{
    const float* cond     = (const float*)d_in[0];
    const float* input    = (const float*)d_in[1];
    const float* ce_w1    = (const float*)d_in[2];
    const float* ce_b1    = (const float*)d_in[3];
    const float* ce_w2    = (const float*)d_in[4];
    const float* ce_b2    = (const float*)d_in[5];
    const float* me_w1    = (const float*)d_in[6];
    const float* me_b1    = (const float*)d_in[7];
    const float* me_w2    = (const float*)d_in[8];
    const float* me_b2    = (const float*)d_in[9];
    const float* w_ih_l0f = (const float*)d_in[10];
    const float* w_hh_l0f = (const float*)d_in[11];
    const float* b_ih_l0f = (const float*)d_in[12];
    const float* b_hh_l0f = (const float*)d_in[13];
    const float* w_ih_l0b = (const float*)d_in[14];
    const float* w_hh_l0b = (const float*)d_in[15];
    const float* b_ih_l0b = (const float*)d_in[16];
    const float* b_hh_l0b = (const float*)d_in[17];
    const float* w_ih_l1f = (const float*)d_in[18];
    const float* w_hh_l1f = (const float*)d_in[19];
    const float* b_ih_l1f = (const float*)d_in[20];
    const float* b_hh_l1f = (const float*)d_in[21];
    const float* w_ih_l1b = (const float*)d_in[22];
    const float* w_hh_l1b = (const float*)d_in[23];
    const float* b_ih_l1b = (const float*)d_in[24];
    const float* b_hh_l1b = (const float*)d_in[25];
    float* out = (float*)d_out;

    void* p;
    cudaGetSymbolAddress(&p, g_h1);    float* s_h1  = (float*)p;
    cudaGetSymbolAddress(&p, g_y);     float* s_y   = (float*)p;
    cudaGetSymbolAddress(&p, g_xhi);   bf16*  s_xhi = (bf16*)p;
    cudaGetSymbolAddress(&p, g_xlo);   bf16*  s_xlo = (bf16*)p;
    cudaGetSymbolAddress(&p, g_yhi);   bf16*  s_yhi = (bf16*)p;
    cudaGetSymbolAddress(&p, g_ylo);   bf16*  s_ylo = (bf16*)p;
    cudaGetSymbolAddress(&p, g_gif);   float* s_gif = (float*)p;
    cudaGetSymbolAddress(&p, g_gib);   float* s_gib = (float*)p;
    cudaGetSymbolAddress(&p, g_wihhi); bf16*  s_wih_hi = (bf16*)p;
    cudaGetSymbolAddress(&p, g_wihlo); bf16*  s_wih_lo = (bf16*)p;
    cudaGetSymbolAddress(&p, g_whhhi); bf16*  s_whh_hi = (bf16*)p;
    cudaGetSymbolAddress(&p, g_whhlo); bf16*  s_whh_lo = (bf16*)p;

    cudaFuncSetAttribute(gemm_bf16x3, cudaFuncAttributeMaxDynamicSharedMemorySize, GI_SMEM);
    cudaFuncSetAttribute(gru_mma_kernel, cudaFuncAttributeMaxDynamicSharedMemorySize, GRU_SMEM_BYTES);

    const size_t WIH0 = (size_t)G3 * HH;
    const size_t WHH  = (size_t)G3 * HH;

    SplitJobs jobs;
    jobs.src[0] = w_ih_l0f; jobs.hi[0] = s_wih_hi;            jobs.lo[0] = s_wih_lo;            jobs.n4[0] = (unsigned)(WIH0 >> 2);
    jobs.src[1] = w_ih_l0b; jobs.hi[1] = s_wih_hi + WIH0;     jobs.lo[1] = s_wih_lo + WIH0;     jobs.n4[1] = (unsigned)(WIH0 >> 2);
    jobs.src[2] = w_ih_l1f; jobs.hi[2] = s_wih_hi + 2*WIH0;   jobs.lo[2] = s_wih_lo + 2*WIH0;   jobs.n4[2] = (unsigned)(WIH0 >> 1);
    jobs.src[3] = w_ih_l1b; jobs.hi[3] = s_wih_hi + 4*WIH0;   jobs.lo[3] = s_wih_lo + 4*WIH0;   jobs.n4[3] = (unsigned)(WIH0 >> 1);
    jobs.src[4] = w_hh_l0f; jobs.hi[4] = s_whh_hi;            jobs.lo[4] = s_whh_lo;            jobs.n4[4] = (unsigned)(WHH >> 2);
    jobs.src[5] = w_hh_l0b; jobs.hi[5] = s_whh_hi + WHH;      jobs.lo[5] = s_whh_lo + WHH;      jobs.n4[5] = (unsigned)(WHH >> 2);
    jobs.src[6] = w_hh_l1f; jobs.hi[6] = s_whh_hi + 2*WHH;    jobs.lo[6] = s_whh_lo + 2*WHH;    jobs.n4[6] = (unsigned)(WHH >> 2);
    jobs.src[7] = w_hh_l1b; jobs.hi[7] = s_whh_hi + 3*WHH;    jobs.lo[7] = s_whh_lo + 3*WHH;    jobs.n4[7] = (unsigned)(WHH >> 2);
    split_w_kernel<<<dim3(160, 8), 256>>>(jobs);

    dim3 blk(256);
    gemm_nt_kernel<<<dim3(H4 / 128, MR / 128), blk>>>(cond,  ce_w1, ce_b1, s_h1, nullptr, nullptr, CONDD, H4,  0,   1);
    gemm_nt_kernel<<<dim3(H2 / 128, MR / 128), blk>>>(s_h1,  ce_w2, ce_b2, nullptr, s_xhi, s_xlo, H4,    HH,  0,   0);
    gemm_nt_kernel<<<dim3(H4 / 128, MR / 128), blk>>>(input, me_w1, me_b1, s_h1, nullptr, nullptr, OUTD,  H4,  0,   1);
    gemm_nt_kernel<<<dim3(H2 / 128, MR / 128), blk>>>(s_h1,  me_w2, me_b2, nullptr, s_xhi, s_xlo, H4,    HH,  512, 0);

    dim3 blk2(512);
    gemm_bf16x3<<<dim3(G3 / 128, MR / 128), blk2, GI_SMEM>>>(
        s_xhi, s_xlo, s_wih_hi, s_wih_lo, b_ih_l0f, s_gif, HH, G3);
    gemm_bf16x3<<<dim3(G3 / 128, MR / 128), blk2, GI_SMEM>>>(
        s_xhi, s_xlo, s_wih_hi + WIH0, s_wih_lo + WIH0, b_ih_l0b, s_gib, HH, G3);
    zero_h_kernel<<<64, 256>>>();
    gru_mma_kernel<<<128, 256, GRU_SMEM_BYTES>>>(
        s_gif, s_gib,
        s_whh_hi, s_whh_lo, s_whh_hi + WHH, s_whh_lo + WHH,
        b_hh_l0f, b_hh_l0b, s_y, s_yhi, s_ylo);

    gemm_bf16x3<<<dim3(G3 / 128, MR / 128), blk2, GI_SMEM>>>(
        s_yhi, s_ylo, s_wih_hi + 2*WIH0, s_wih_lo + 2*WIH0, b_ih_l1f, s_gif, 2 * HH, G3);
    gemm_bf16x3<<<dim3(G3 / 128, MR / 128), blk2, GI_SMEM>>>(
        s_yhi, s_ylo, s_wih_hi + 4*WIH0, s_wih_lo + 4*WIH0, b_ih_l1b, s_gib, 2 * HH, G3);
    zero_h_kernel<<<64, 256>>>();
    gru_mma_kernel<<<128, 256, GRU_SMEM_BYTES>>>(
        s_gif, s_gib,
        s_whh_hi + 2*WHH, s_whh_lo + 2*WHH, s_whh_hi + 3*WHH, s_whh_lo + 3*WHH,
        b_hh_l1f, b_hh_l1b, s_y, s_yhi, s_ylo);

    mean_kernel<<<BB, 256>>>(s_y, out);
}

// round 12
// speedup vs baseline: 4.6432x; 1.1260x over previous
#include <cuda_runtime.h>
#include <cuda_bf16.h>
#include <cuda_fp16.h>
#include <math.h>
#include <stdint.h>

#define BB    64
#define TT    300
#define CONDD 64
#define OUTD  72
#define HH    1024
#define H4    256
#define H2    512
#define G3    3072
#define MR    (BB*TT)

typedef __nv_bfloat16 bf16;

// ---------------- device globals ----------------
__device__ float  g_h1 [MR * H4];
__device__ float  g_y  [(size_t)MR * 2 * HH];
__device__ __half g_xf16[(size_t)MR * HH];
__device__ __half g_yf16[(size_t)MR * 2 * HH];
__device__ float  g_gif[(size_t)MR * G3], g_gib[(size_t)MR * G3];
__device__ float  g_hf [2][2][BB * HH];
__device__ bf16   g_hhi[2][2][BB * HH], g_hlo[2][2][BB * HH];
__device__ __half g_wihh[(size_t)6 * G3 * HH], g_wihl[(size_t)6 * G3 * HH];  // fp16 hi/lo
__device__ bf16   g_whhhi[(size_t)4 * G3 * HH], g_whhlo[(size_t)4 * G3 * HH];
__device__ unsigned int g_barc[2];
__device__ unsigned int g_barg[2];

// ---------------- helpers ----------------
__device__ __forceinline__ uint32_t saddr(const void* p) {
    return (uint32_t)__cvta_generic_to_shared(p);
}
__device__ __forceinline__ void cpa16(uint32_t s, const void* g) {
    asm volatile("cp.async.cg.shared.global [%0], [%1], 16;" :: "r"(s), "l"(g));
}
__device__ __forceinline__ void cpa_commit() { asm volatile("cp.async.commit_group;"); }
__device__ __forceinline__ void cpa_wait2() { asm volatile("cp.async.wait_group 2;"); }
__device__ __forceinline__ void cpa_wait1() { asm volatile("cp.async.wait_group 1;"); }
__device__ __forceinline__ void cpa_wait0() { asm volatile("cp.async.wait_group 0;"); }

__device__ __forceinline__ void ldmx4(uint32_t* r, uint32_t a) {
    asm volatile("ldmatrix.sync.aligned.m8n8.x4.shared.b16 {%0,%1,%2,%3}, [%4];"
                 : "=r"(r[0]), "=r"(r[1]), "=r"(r[2]), "=r"(r[3]) : "r"(a));
}
__device__ __forceinline__ void ldmx2(uint32_t* r, uint32_t a) {
    asm volatile("ldmatrix.sync.aligned.m8n8.x2.shared.b16 {%0,%1}, [%2];"
                 : "=r"(r[0]), "=r"(r[1]) : "r"(a));
}
__device__ __forceinline__ void mma_bf16(float* c, const uint32_t* a, const uint32_t* b) {
    asm volatile("mma.sync.aligned.m16n8k16.row.col.f32.bf16.bf16.f32 "
                 "{%0,%1,%2,%3}, {%4,%5,%6,%7}, {%8,%9}, {%0,%1,%2,%3};"
                 : "+f"(c[0]), "+f"(c[1]), "+f"(c[2]), "+f"(c[3])
                 : "r"(a[0]), "r"(a[1]), "r"(a[2]), "r"(a[3]), "r"(b[0]), "r"(b[1]));
}
__device__ __forceinline__ void mma_f16(float* c, const uint32_t* a, const uint32_t* b) {
    asm volatile("mma.sync.aligned.m16n8k16.row.col.f32.f16.f16.f32 "
                 "{%0,%1,%2,%3}, {%4,%5,%6,%7}, {%8,%9}, {%0,%1,%2,%3};"
                 : "+f"(c[0]), "+f"(c[1]), "+f"(c[2]), "+f"(c[3])
                 : "r"(a[0]), "r"(a[1]), "r"(a[2]), "r"(a[3]), "r"(b[0]), "r"(b[1]));
}

__device__ __forceinline__ unsigned long long ffma2(unsigned long long a,
                                                    unsigned long long b,
                                                    unsigned long long c) {
    unsigned long long d;
    asm("fma.rn.f32x2 %0, %1, %2, %3;" : "=l"(d) : "l"(a), "l"(b), "l"(c));
    return d;
}
__device__ __forceinline__ unsigned long long pack2(float x, float y) {
    unsigned long long d;
    asm("mov.b64 %0, {%1, %2};" : "=l"(d) : "f"(x), "f"(y));
    return d;
}
__device__ __forceinline__ void unpack2(unsigned long long p, float& lo, float& hi) {
    asm("mov.b64 {%0, %1}, %2;" : "=f"(lo), "=f"(hi) : "l"(p));
}

__device__ __forceinline__ float fast_sigmoid(float x) {
    return 1.f / (1.f + __expf(-x));
}
__device__ __forceinline__ float fast_tanh(float x) {
    float r;
    asm("tanh.approx.f32 %0, %1;" : "=f"(r) : "f"(x));
    return r;
}

// per-direction software grid barrier (graph-capturable)
__device__ __forceinline__ void dir_barrier(int dir, unsigned int nb) {
    __syncthreads();
    if (threadIdx.x == 0) {
        __threadfence();
        unsigned int gen = *(volatile unsigned int*)&g_barg[dir];
        unsigned int arrived = atomicAdd(&g_barc[dir], 1u);
        if (arrived == nb - 1u) {
            g_barc[dir] = 0u;
            __threadfence();
            atomicExch(&g_barg[dir], gen + 1u);
        } else {
            while (*(volatile unsigned int*)&g_barg[dir] == gen) { __nanosleep(20); }
        }
        __threadfence();
    }
    __syncthreads();
}

// ---------------- fused weight split: 8 jobs, fp16 (w_ih) or bf16 (w_hh) ----------------
struct SplitJobs {
    const float* src[8];
    void* hi[8];
    void* lo[8];
    unsigned int n4[8];
    int fp16[8];
};
__global__ void split_w_kernel(SplitJobs jobs) {
    const int j = blockIdx.y;
    const float4* s = (const float4*)jobs.src[j];
    ushort4* hi = (ushort4*)jobs.hi[j];
    ushort4* lo = (ushort4*)jobs.lo[j];
    const unsigned int n4 = jobs.n4[j];
    const int f16 = jobs.fp16[j];
    for (unsigned int i = blockIdx.x * blockDim.x + threadIdx.x; i < n4;
         i += gridDim.x * blockDim.x) {
        float4 v = s[i];
        ushort4 hv, lv;
        if (f16) {
            __half h0 = __float2half(v.x), h1 = __float2half(v.y);
            __half h2 = __float2half(v.z), h3 = __float2half(v.w);
            hv.x = __half_as_ushort(h0); hv.y = __half_as_ushort(h1);
            hv.z = __half_as_ushort(h2); hv.w = __half_as_ushort(h3);
            lv.x = __half_as_ushort(__float2half(v.x - __half2float(h0)));
            lv.y = __half_as_ushort(__float2half(v.y - __half2float(h1)));
            lv.z = __half_as_ushort(__float2half(v.z - __half2float(h2)));
            lv.w = __half_as_ushort(__float2half(v.w - __half2float(h3)));
        } else {
            bf16 h0 = __float2bfloat16(v.x), h1 = __float2bfloat16(v.y);
            bf16 h2 = __float2bfloat16(v.z), h3 = __float2bfloat16(v.w);
            hv.x = __bfloat16_as_ushort(h0); hv.y = __bfloat16_as_ushort(h1);
            hv.z = __bfloat16_as_ushort(h2); hv.w = __bfloat16_as_ushort(h3);
            lv.x = __bfloat16_as_ushort(__float2bfloat16(v.x - __bfloat162float(h0)));
            lv.y = __bfloat16_as_ushort(__float2bfloat16(v.y - __bfloat162float(h1)));
            lv.z = __bfloat16_as_ushort(__float2bfloat16(v.z - __bfloat162float(h2)));
            lv.w = __bfloat16_as_ushort(__float2bfloat16(v.w - __bfloat162float(h3)));
        }
        hi[i] = hv;
        lo[i] = lv;
    }
}

// ---------------- encoder FFMA2 GEMM (optional fused fp16 output) ----------------
__global__ void __launch_bounds__(256) gemm_nt_kernel(
    const float* __restrict__ A, const float* __restrict__ W,
    const float* __restrict__ bias, float* __restrict__ C,
    __half* __restrict__ Of16,
    int K, int ldc, int coff, int leaky)
{
    __shared__ float As[8][128];
    __shared__ float Bs[8][128];
    const int tid = threadIdx.x;
    const int bx = blockIdx.x, by = blockIdx.y;
    const int tx = tid & 15, ty = tid >> 4;
    const int r  = tid >> 1;
    const int cq = (tid & 1) * 4;
    const float* Ap = A + (size_t)(by * 128 + r) * K + cq;
    const float* Wp = W + (size_t)(bx * 128 + r) * K + cq;

    unsigned long long acc[8][4];
#pragma unroll
    for (int m = 0; m < 8; m++)
#pragma unroll
        for (int p = 0; p < 4; p++) acc[m][p] = 0ULL;

    const int nkt = K >> 3;
    for (int kt = 0; kt < nkt; kt++) {
        __syncthreads();
        float4 av = *(const float4*)(Ap + kt * 8);
        float4 wv = *(const float4*)(Wp + kt * 8);
        As[cq + 0][r] = av.x; As[cq + 1][r] = av.y; As[cq + 2][r] = av.z; As[cq + 3][r] = av.w;
        Bs[cq + 0][r] = wv.x; Bs[cq + 1][r] = wv.y; Bs[cq + 2][r] = wv.z; Bs[cq + 3][r] = wv.w;
        __syncthreads();
#pragma unroll
        for (int k = 0; k < 8; k++) {
            float4 a0 = *(const float4*)&As[k][ty * 8];
            float4 a1 = *(const float4*)&As[k][ty * 8 + 4];
            ulonglong2 bq0 = *(const ulonglong2*)&Bs[k][tx * 8];
            ulonglong2 bq1 = *(const ulonglong2*)&Bs[k][tx * 8 + 4];
            float a[8] = {a0.x, a0.y, a0.z, a0.w, a1.x, a1.y, a1.z, a1.w};
#pragma unroll
            for (int m = 0; m < 8; m++) {
                unsigned long long ap = pack2(a[m], a[m]);
                acc[m][0] = ffma2(ap, bq0.x, acc[m][0]);
                acc[m][1] = ffma2(ap, bq0.y, acc[m][1]);
                acc[m][2] = ffma2(ap, bq1.x, acc[m][2]);
                acc[m][3] = ffma2(ap, bq1.y, acc[m][3]);
            }
        }
    }
#pragma unroll
    for (int m = 0; m < 8; m++) {
        const int row = by * 128 + ty * 8 + m;
        const size_t rbase = (size_t)row * ldc + coff;
#pragma unroll
        for (int p = 0; p < 4; p++) {
            float lo, hi;
            unpack2(acc[m][p], lo, hi);
            const int nn = bx * 128 + tx * 8 + p * 2;
            float v0 = lo + bias[nn];
            float v1 = hi + bias[nn + 1];
            if (leaky) {
                v0 = (v0 >= 0.f) ? v0 : 0.2f * v0;
                v1 = (v1 >= 0.f) ? v1 : 0.2f * v1;
            }
            if (Of16) {
                Of16[rbase + nn]     = __float2half(v0);
                Of16[rbase + nn + 1] = __float2half(v1);
            } else {
                C[rbase + nn]     = v0;
                C[rbase + nn + 1] = v1;
            }
        }
    }
}

// ---------------- fp16x2 mma.sync GEMM, 512 thr, BK=32, 4-stage pipeline ----------------
// C = A_fp16 @ (Whi + Wlo)^T + bias ; 2 passes (asymmetric split, err ~1e-4).
#define GI_STAGE 30720                    // bytes per stage: 3 matrices x 10240
#define GI_SMEM  (4 * GI_STAGE)           // 122880
__global__ void __launch_bounds__(512) gemm_f16x2(
    const __half* __restrict__ Af, const __half* __restrict__ Whi,
    const __half* __restrict__ Wlo,
    const float* __restrict__ bias, float* __restrict__ C, int K, int ldc)
{
    extern __shared__ char smem[];
    const uint32_t sb = saddr(smem);

    const int tid = threadIdx.x, lane = tid & 31, warp = tid >> 5;
    const int wm = warp & 3, wn = warp >> 2;
    const int bx = blockIdx.x, by = blockIdx.y;

    float acc[2][4][4];
#pragma unroll
    for (int mt = 0; mt < 2; mt++)
#pragma unroll
        for (int nt = 0; nt < 4; nt++)
#pragma unroll
            for (int i = 0; i < 4; i++) acc[mt][nt][i] = 0.f;

    const int nkt = K >> 5;
    const int lrow = tid >> 2, lkc = tid & 3;
    const uint32_t so = (uint32_t)(lrow * 80 + lkc * 16);
    const __half* pa   = Af  + (size_t)(by * 128 + lrow) * K + lkc * 8;
    const __half* pb_h = Whi + (size_t)(bx * 128 + lrow) * K + lkc * 8;
    const __half* pb_l = Wlo + (size_t)(bx * 128 + lrow) * K + lkc * 8;

#define GI_LOAD(KT) do {                                   \
        const uint32_t st_ = sb + ((KT) & 3) * GI_STAGE;   \
        const int ko_ = (KT) * 32;                         \
        cpa16(st_ + so,          pa   + ko_);              \
        cpa16(st_ + 10240 + so,  pb_h + ko_);              \
        cpa16(st_ + 20480 + so,  pb_l + ko_);              \
    } while (0)

    GI_LOAD(0); cpa_commit();
    GI_LOAD(1); cpa_commit();
    GI_LOAD(2); cpa_commit();

    for (int kt = 0; kt < nkt; kt++) {
        cpa_wait2();        // per-thread: groups 0..kt complete
        __syncthreads();    // publish stage kt; all warps past compute kt-1
        if (kt + 3 < nkt) GI_LOAD(kt + 3);   // overwrites buffer (kt-1)&3 (drained)
        cpa_commit();       // empty groups at tail keep wait_group arithmetic valid

        const uint32_t st = sb + (kt & 3) * GI_STAGE;
#pragma unroll
        for (int ks = 0; ks < 2; ks++) {
            const int kk = ks * 16;
            uint32_t ah[2][4];
#pragma unroll
            for (int mt = 0; mt < 2; mt++) {
                const int ar = wm * 32 + mt * 16 + (lane & 15);
                const int ac = kk + (lane >> 4) * 8;
                ldmx4(ah[mt], st + ar * 80 + ac * 2);
            }
            // B: two n-tile pairs via ldmatrix.x4 each (hi+lo)
            uint32_t bh[2][4], bl[2][4];
#pragma unroll
            for (int pr = 0; pr < 2; pr++) {
                const int br = wn * 32 + pr * 16 + (lane & 7) + ((lane >> 4) << 3);
                const int bc = kk + (((lane >> 3) & 1) << 3);
                ldmx4(bh[pr], st + 10240 + br * 80 + bc * 2);
                ldmx4(bl[pr], st + 20480 + br * 80 + bc * 2);
            }
#pragma unroll
            for (int mt = 0; mt < 2; mt++)
#pragma unroll
                for (int nt = 0; nt < 4; nt++) {
                    const uint32_t* bhp = &bh[nt >> 1][(nt & 1) * 2];
                    const uint32_t* blp = &bl[nt >> 1][(nt & 1) * 2];
                    mma_f16(acc[mt][nt], ah[mt], bhp);
                    mma_f16(acc[mt][nt], ah[mt], blp);
                }
        }
    }
#undef GI_LOAD

#pragma unroll
    for (int mt = 0; mt < 2; mt++) {
        const int r0 = by * 128 + wm * 32 + mt * 16 + (lane >> 2);
#pragma unroll
        for (int nt = 0; nt < 4; nt++) {
            const int c0 = bx * 128 + wn * 32 + nt * 8 + 2 * (lane & 3);
            const float b0 = bias[c0], b1 = bias[c0 + 1];
            C[(size_t)r0 * ldc + c0]           = acc[mt][nt][0] + b0;
            C[(size_t)r0 * ldc + c0 + 1]       = acc[mt][nt][1] + b1;
            C[(size_t)(r0 + 8) * ldc + c0]     = acc[mt][nt][2] + b0;
            C[(size_t)(r0 + 8) * ldc + c0 + 1] = acc[mt][nt][3] + b1;
        }
    }
}

// ---------------- zero hidden state ----------------
__global__ void zero_h_kernel() {
    const int n = 4 * BB * HH;
    float* pf = &g_hf[0][0][0];
    bf16* ph = &g_hhi[0][0][0];
    bf16* pl = &g_hlo[0][0][0];
    for (int i = blockIdx.x * blockDim.x + threadIdx.x; i < n;
         i += gridDim.x * blockDim.x) {
        pf[i] = 0.f;
        ph[i] = __float2bfloat16(0.f);
        pl[i] = __float2bfloat16(0.f);
    }
}

// ---------------- persistent GRU layer: W resident (bf16x3), BK=64, 2-stage H ----------------
#define WLO_OFF 99072     // bytes
#define HST_BASE 198144   // bytes
#define HST_STAGE 16384   // Hh 8KB + Hl 8KB
#define GRU_SMEM_BYTES (HST_BASE + 2 * HST_STAGE)   // 230912
__global__ void __launch_bounds__(256, 1) gru_mma_kernel(
    const float* __restrict__ gif, const float* __restrict__ gib,
    const bf16* __restrict__ whf_hi, const bf16* __restrict__ whf_lo,
    const bf16* __restrict__ whb_hi, const bf16* __restrict__ whb_lo,
    const float* __restrict__ bhhf, const float* __restrict__ bhhb,
    float* __restrict__ y, __half* __restrict__ yf16)
{
    extern __shared__ char smem[];
    const uint32_t sb = saddr(smem);
    float* Cs = (float*)(smem + HST_BASE);   // overlays stage 0 only (13312 < 16384)

    const int tid = threadIdx.x, lane = tid & 31, warp = tid >> 5;
    const int dir = blockIdx.x >> 6;
    const int j0  = (blockIdx.x & 63) << 4;
    const int wm = warp & 3, wn = warp >> 2;
    const int m0 = wm * 16, n0 = wn * 24;

    const float* gi  = dir ? gib    : gif;
    const bf16* whhh = dir ? whb_hi : whf_hi;
    const bf16* whhl = dir ? whb_lo : whf_lo;
    const float* bhh = dir ? bhhb   : bhhf;

    const int ep_b [4] = { tid >> 4, (tid + 256) >> 4, (tid + 512) >> 4, (tid + 768) >> 4 };
    const int ep_jj = tid & 15;
    const int ep_j  = j0 + ep_jj;
    const float bh_r = bhh[ep_j];
    const float bh_z = bhh[HH + ep_j];
    const float bh_n = bhh[2 * HH + ep_j];

    // ---- load W slice into smem once (stride 2064B, conflict-free) ----
    for (int i = tid; i < 6144; i += 256) {
        const int row = i >> 7, kc = i & 127;
        const int grow = (row >> 4) * HH + j0 + (row & 15);
        const uint32_t dst = sb + (uint32_t)(row * 2064 + kc * 16);
        cpa16(dst,           whhh + (size_t)grow * HH + kc * 8);
        cpa16(dst + WLO_OFF, whhl + (size_t)grow * HH + kc * 8);
    }
    cpa_commit();
    cpa_wait0();
    __syncthreads();

    const uint32_t sWh = sb;
    const uint32_t sWl = sb + WLO_OFF;

    const int hl_b0 = tid >> 3;
    const int hl_c  = tid & 7;

    for (int s = 0; s < TT; s++) {
        const int t_idx = dir ? (TT - 1 - s) : s;
        const int rb = s & 1;
        const bf16* hhi = g_hhi[dir][rb];
        const bf16* hlo = g_hlo[dir][rb];
        const float* hpf = g_hf[dir][rb];
        float* hnf = g_hf[dir][rb ^ 1];
        bf16* hnhi = g_hhi[dir][rb ^ 1];
        bf16* hnlo = g_hlo[dir][rb ^ 1];

        float pre_gr[4], pre_gz[4], pre_gn[4], pre_hp[4];
#pragma unroll
        for (int p = 0; p < 4; p++) {
            const size_t gbase = (size_t)(ep_b[p] * TT + t_idx) * G3;
            pre_gr[p] = __ldg(gi + gbase + ep_j);
            pre_gz[p] = __ldg(gi + gbase + HH + ep_j);
            pre_gn[p] = __ldg(gi + gbase + 2 * HH + ep_j);
            pre_hp[p] = __ldg(hpf + ep_b[p] * HH + ep_j);
        }

        float acc[3][4];
#pragma unroll
        for (int nt = 0; nt < 3; nt++)
#pragma unroll
            for (int i = 0; i < 4; i++) acc[nt][i] = 0.f;

#define H_LOAD(KT) do {                                                          \
        const uint32_t st_ = sb + HST_BASE + ((KT) & 1) * HST_STAGE;             \
        const int ko_ = (KT) * 64;                                               \
        _Pragma("unroll")                                                        \
        for (int i_ = 0; i_ < 2; i_++) {                                         \
            const int b_ = hl_b0 + i_ * 32;                                      \
            const uint32_t off_ = (uint32_t)(b_ * 128 +                          \
                                  ((hl_c * 16) ^ ((b_ & 7) << 4)));              \
            cpa16(st_ + off_,        hhi + (size_t)b_ * HH + ko_ + hl_c * 8);    \
            cpa16(st_ + 8192 + off_, hlo + (size_t)b_ * HH + ko_ + hl_c * 8);    \
        }                                                                        \
    } while (0)

        H_LOAD(0);
        cpa_commit();

        for (int kt = 0; kt < 16; kt++) {
            if (kt + 1 < 16) {
                H_LOAD(kt + 1);
                cpa_commit();
                cpa_wait1();
            } else {
                cpa_wait0();
            }
            __syncthreads();          // PUBLISH stage kt across warps

            const uint32_t Hh = sb + HST_BASE + (kt & 1) * HST_STAGE;
            const uint32_t Hl = Hh + 8192;
#pragma unroll
            for (int ks = 0; ks < 4; ks++) {
                uint32_t ah[4], al[4];
                const int ar = m0 + (lane & 15);
                const uint32_t aoff = (uint32_t)(ar * 128 +
                    ((ks * 32 + (lane >> 4) * 16) ^ ((ar & 7) << 4)));
                ldmx4(ah, Hh + aoff);
                ldmx4(al, Hl + aoff);
                const int kcolg = kt * 64 + ks * 16 + (((lane >> 3) & 1) << 3);
                uint32_t bh4[4], bl4[4], bh2[2], bl2[2];
                {
                    const int brp = n0 + (lane & 7) + ((lane >> 4) << 3);
                    ldmx4(bh4, sWh + brp * 2064 + kcolg * 2);
                    ldmx4(bl4, sWl + brp * 2064 + kcolg * 2);
                    const int br2 = n0 + 16 + (lane & 7);
                    ldmx2(bh2, sWh + br2 * 2064 + kcolg * 2);
                    ldmx2(bl2, sWl + br2 * 2064 + kcolg * 2);
                }
                mma_bf16(acc[0], ah, &bh4[0]);
                mma_bf16(acc[0], ah, &bl4[0]);
                mma_bf16(acc[0], al, &bh4[0]);
                mma_bf16(acc[1], ah, &bh4[2]);
                mma_bf16(acc[1], ah, &bl4[2]);
                mma_bf16(acc[1], al, &bh4[2]);
                mma_bf16(acc[2], ah, bh2);
                mma_bf16(acc[2], ah, bl2);
                mma_bf16(acc[2], al, bh2);
            }
            __syncthreads();          // PROTECT buffer kt&1 before next H_LOAD(kt+2)
        }
#undef H_LOAD

#pragma unroll
        for (int nt = 0; nt < 3; nt++) {
            const int cr = m0 + (lane >> 2);
            const int cc = n0 + nt * 8 + 2 * (lane & 3);
            Cs[cr * 52 + cc]           = acc[nt][0];
            Cs[cr * 52 + cc + 1]       = acc[nt][1];
            Cs[(cr + 8) * 52 + cc]     = acc[nt][2];
            Cs[(cr + 8) * 52 + cc + 1] = acc[nt][3];
        }
        __syncthreads();

#pragma unroll
        for (int p = 0; p < 4; p++) {
            const int b = ep_b[p];
            const float cr = Cs[b * 52 + ep_jj]      + bh_r;
            const float cz = Cs[b * 52 + 16 + ep_jj] + bh_z;
            const float cn = Cs[b * 52 + 32 + ep_jj] + bh_n;
            const float rr = fast_sigmoid(pre_gr[p] + cr);
            const float zz = fast_sigmoid(pre_gz[p] + cz);
            const float nn = fast_tanh(pre_gn[p] + rr * cn);
            const float hp = pre_hp[p];
            const float hn = (1.f - zz) * nn + zz * hp;
            hnf[b * HH + ep_j] = hn;
            bf16 hh = __float2bfloat16(hn);
            hnhi[b * HH + ep_j] = hh;
            hnlo[b * HH + ep_j] = __float2bfloat16(hn - __bfloat162float(hh));
            const size_t yb = (size_t)(b * TT + t_idx) * (2 * HH) + dir * HH + ep_j;
            y[yb] = hn;
            yf16[yb] = __float2half(hn);
        }
        dir_barrier(dir, 64);
    }
}

// ---------------- final mean ----------------
__global__ void mean_kernel(const float* __restrict__ y, float* __restrict__ out) {
    const int b = blockIdx.x;
    const int tid = threadIdx.x;
    const size_t base = (size_t)b * TT * 2 * HH;
    float s = 0.f;
    for (int i = tid; i < TT * 2 * HH; i += 256) s += y[base + i];
    __shared__ float red[256];
    red[tid] = s;
    __syncthreads();
    for (int o = 128; o > 0; o >>= 1) {
        if (tid < o) red[tid] += red[tid + o];
        __syncthreads();
    }
    if (tid == 0) out[b] = red[0] / (float)(TT * 2 * HH);
}

// ---------------- launcher ----------------
extern "C" void kernel_launch(void* const* d_in, const int* in_sizes, int n_in,
                              void* d_out, int out_size)
{
    const float* cond     = (const float*)d_in[0];
    const float* input    = (const float*)d_in[1];
    const float* ce_w1    = (const float*)d_in[2];
    const float* ce_b1    = (const float*)d_in[3];
    const float* ce_w2    = (const float*)d_in[4];
    const float* ce_b2    = (const float*)d_in[5];
    const float* me_w1    = (const float*)d_in[6];
    const float* me_b1    = (const float*)d_in[7];
    const float* me_w2    = (const float*)d_in[8];
    const float* me_b2    = (const float*)d_in[9];
    const float* w_ih_l0f = (const float*)d_in[10];
    const float* w_hh_l0f = (const float*)d_in[11];
    const float* b_ih_l0f = (const float*)d_in[12];
    const float* b_hh_l0f = (const float*)d_in[13];
    const float* w_ih_l0b = (const float*)d_in[14];
    const float* w_hh_l0b = (const float*)d_in[15];
    const float* b_ih_l0b = (const float*)d_in[16];
    const float* b_hh_l0b = (const float*)d_in[17];
    const float* w_ih_l1f = (const float*)d_in[18];
    const float* w_hh_l1f = (const float*)d_in[19];
    const float* b_ih_l1f = (const float*)d_in[20];
    const float* b_hh_l1f = (const float*)d_in[21];
    const float* w_ih_l1b = (const float*)d_in[22];
    const float* w_hh_l1b = (const float*)d_in[23];
    const float* b_ih_l1b = (const float*)d_in[24];
    const float* b_hh_l1b = (const float*)d_in[25];
    float* out = (float*)d_out;

    void* p;
    cudaGetSymbolAddress(&p, g_h1);    float*  s_h1   = (float*)p;
    cudaGetSymbolAddress(&p, g_y);     float*  s_y    = (float*)p;
    cudaGetSymbolAddress(&p, g_xf16);  __half* s_xf16 = (__half*)p;
    cudaGetSymbolAddress(&p, g_yf16);  __half* s_yf16 = (__half*)p;
    cudaGetSymbolAddress(&p, g_gif);   float*  s_gif  = (float*)p;
    cudaGetSymbolAddress(&p, g_gib);   float*  s_gib  = (float*)p;
    cudaGetSymbolAddress(&p, g_wihh);  __half* s_wih_h = (__half*)p;
    cudaGetSymbolAddress(&p, g_wihl);  __half* s_wih_l = (__half*)p;
    cudaGetSymbolAddress(&p, g_whhhi); bf16*   s_whh_hi = (bf16*)p;
    cudaGetSymbolAddress(&p, g_whhlo); bf16*   s_whh_lo = (bf16*)p;

    cudaFuncSetAttribute(gemm_f16x2, cudaFuncAttributeMaxDynamicSharedMemorySize, GI_SMEM);
    cudaFuncSetAttribute(gru_mma_kernel, cudaFuncAttributeMaxDynamicSharedMemorySize, GRU_SMEM_BYTES);

    const size_t WIH0 = (size_t)G3 * HH;
    const size_t WHH  = (size_t)G3 * HH;

    SplitJobs jobs;
    jobs.src[0] = w_ih_l0f; jobs.hi[0] = s_wih_h;            jobs.lo[0] = s_wih_l;            jobs.n4[0] = (unsigned)(WIH0 >> 2); jobs.fp16[0] = 1;
    jobs.src[1] = w_ih_l0b; jobs.hi[1] = s_wih_h + WIH0;     jobs.lo[1] = s_wih_l + WIH0;     jobs.n4[1] = (unsigned)(WIH0 >> 2); jobs.fp16[1] = 1;
    jobs.src[2] = w_ih_l1f; jobs.hi[2] = s_wih_h + 2*WIH0;   jobs.lo[2] = s_wih_l + 2*WIH0;   jobs.n4[2] = (unsigned)(WIH0 >> 1); jobs.fp16[2] = 1;
    jobs.src[3] = w_ih_l1b; jobs.hi[3] = s_wih_h + 4*WIH0;   jobs.lo[3] = s_wih_l + 4*WIH0;   jobs.n4[3] = (unsigned)(WIH0 >> 1); jobs.fp16[3] = 1;
    jobs.src[4] = w_hh_l0f; jobs.hi[4] = s_whh_hi;           jobs.lo[4] = s_whh_lo;           jobs.n4[4] = (unsigned)(WHH >> 2);  jobs.fp16[4] = 0;
    jobs.src[5] = w_hh_l0b; jobs.hi[5] = s_whh_hi + WHH;     jobs.lo[5] = s_whh_lo + WHH;     jobs.n4[5] = (unsigned)(WHH >> 2);  jobs.fp16[5] = 0;
    jobs.src[6] = w_hh_l1f; jobs.hi[6] = s_whh_hi + 2*WHH;   jobs.lo[6] = s_whh_lo + 2*WHH;   jobs.n4[6] = (unsigned)(WHH >> 2);  jobs.fp16[6] = 0;
    jobs.src[7] = w_hh_l1b; jobs.hi[7] = s_whh_hi + 3*WHH;   jobs.lo[7] = s_whh_lo + 3*WHH;   jobs.n4[7] = (unsigned)(WHH >> 2);  jobs.fp16[7] = 0;
    split_w_kernel<<<dim3(160, 8), 256>>>(jobs);

    dim3 blk(256);
    gemm_nt_kernel<<<dim3(H4 / 128, MR / 128), blk>>>(cond,  ce_w1, ce_b1, s_h1, nullptr, CONDD, H4,  0,   1);
    gemm_nt_kernel<<<dim3(H2 / 128, MR / 128), blk>>>(s_h1,  ce_w2, ce_b2, nullptr, s_xf16, H4,   HH,  0,   0);
    gemm_nt_kernel<<<dim3(H4 / 128, MR / 128), blk>>>(input, me_w1, me_b1, s_h1, nullptr, OUTD,  H4,  0,   1);
    gemm_nt_kernel<<<dim3(H2 / 128, MR / 128), blk>>>(s_h1,  me_w2, me_b2, nullptr, s_xf16, H4,   HH,  512, 0);

    dim3 blk2(512);
    gemm_f16x2<<<dim3(G3 / 128, MR / 128), blk2, GI_SMEM>>>(
        s_xf16, s_wih_h, s_wih_l, b_ih_l0f, s_gif, HH, G3);
    gemm_f16x2<<<dim3(G3 / 128, MR / 128), blk2, GI_SMEM>>>(
        s_xf16, s_wih_h + WIH0, s_wih_l + WIH0, b_ih_l0b, s_gib, HH, G3);
    zero_h_kernel<<<64, 256>>>();
    gru_mma_kernel<<<128, 256, GRU_SMEM_BYTES>>>(
        s_gif, s_gib,
        s_whh_hi, s_whh_lo, s_whh_hi + WHH, s_whh_lo + WHH,
        b_hh_l0f, b_hh_l0b, s_y, s_yf16);

    gemm_f16x2<<<dim3(G3 / 128, MR / 128), blk2, GI_SMEM>>>(
        s_yf16, s_wih_h + 2*WIH0, s_wih_l + 2*WIH0, b_ih_l1f, s_gif, 2 * HH, G3);
    gemm_f16x2<<<dim3(G3 / 128, MR / 128), blk2, GI_SMEM>>>(
        s_yf16, s_wih_h + 4*WIH0, s_wih_l + 4*WIH0, b_ih_l1b, s_gib, 2 * HH, G3);
    zero_h_kernel<<<64, 256>>>();
    gru_mma_kernel<<<128, 256, GRU_SMEM_BYTES>>>(
        s_gif, s_gib,
        s_whh_hi + 2*WHH, s_whh_lo + 2*WHH, s_whh_hi + 3*WHH, s_whh_lo + 3*WHH,
        b_hh_l1f, b_hh_l1b, s_y, s_yf16);

    mean_kernel<<<BB, 256>>>(s_y, out);
}

// round 14
// speedup vs baseline: 5.0769x; 1.0934x over previous
#include <cuda_runtime.h>
#include <cuda_bf16.h>
#include <cuda_fp16.h>
#include <math.h>
#include <stdint.h>

#define BB    64
#define TT    300
#define CONDD 64
#define OUTD  72
#define HH    1024
#define H4    256
#define H2    512
#define G3    3072
#define MR    (BB*TT)

typedef __nv_bfloat16 bf16;

// ---------------- device globals ----------------
__device__ float  g_h1 [MR * H4];
__device__ float  g_y  [(size_t)MR * 2 * HH];
__device__ __half g_xf16[(size_t)MR * HH];
__device__ __half g_yf16[(size_t)MR * 2 * HH];
__device__ float  g_gif[(size_t)MR * G3], g_gib[(size_t)MR * G3];
__device__ float  g_hf [2][2][BB * HH];
__device__ __half g_h16[2][2][BB * HH];
__device__ __half g_wihh[(size_t)6 * G3 * HH], g_wihl[(size_t)6 * G3 * HH];  // w_ih fp16 hi/lo
__device__ __half g_whhh[(size_t)4 * G3 * HH], g_whhl[(size_t)4 * G3 * HH];  // w_hh fp16 hi/lo
__device__ unsigned int g_barc[2];
__device__ unsigned int g_barg[2];

// ---------------- helpers ----------------
__device__ __forceinline__ uint32_t saddr(const void* p) {
    return (uint32_t)__cvta_generic_to_shared(p);
}
__device__ __forceinline__ void cpa16(uint32_t s, const void* g) {
    asm volatile("cp.async.cg.shared.global [%0], [%1], 16;" :: "r"(s), "l"(g));
}
__device__ __forceinline__ void cpa_commit() { asm volatile("cp.async.commit_group;"); }
__device__ __forceinline__ void cpa_wait2() { asm volatile("cp.async.wait_group 2;"); }
__device__ __forceinline__ void cpa_wait1() { asm volatile("cp.async.wait_group 1;"); }
__device__ __forceinline__ void cpa_wait0() { asm volatile("cp.async.wait_group 0;"); }

__device__ __forceinline__ void ldmx4(uint32_t* r, uint32_t a) {
    asm volatile("ldmatrix.sync.aligned.m8n8.x4.shared.b16 {%0,%1,%2,%3}, [%4];"
                 : "=r"(r[0]), "=r"(r[1]), "=r"(r[2]), "=r"(r[3]) : "r"(a));
}
__device__ __forceinline__ void ldmx2(uint32_t* r, uint32_t a) {
    asm volatile("ldmatrix.sync.aligned.m8n8.x2.shared.b16 {%0,%1}, [%2];"
                 : "=r"(r[0]), "=r"(r[1]) : "r"(a));
}
__device__ __forceinline__ void mma_f16(float* c, const uint32_t* a, const uint32_t* b) {
    asm volatile("mma.sync.aligned.m16n8k16.row.col.f32.f16.f16.f32 "
                 "{%0,%1,%2,%3}, {%4,%5,%6,%7}, {%8,%9}, {%0,%1,%2,%3};"
                 : "+f"(c[0]), "+f"(c[1]), "+f"(c[2]), "+f"(c[3])
                 : "r"(a[0]), "r"(a[1]), "r"(a[2]), "r"(a[3]), "r"(b[0]), "r"(b[1]));
}

__device__ __forceinline__ unsigned long long ffma2(unsigned long long a,
                                                    unsigned long long b,
                                                    unsigned long long c) {
    unsigned long long d;
    asm("fma.rn.f32x2 %0, %1, %2, %3;" : "=l"(d) : "l"(a), "l"(b), "l"(c));
    return d;
}
__device__ __forceinline__ unsigned long long pack2(float x, float y) {
    unsigned long long d;
    asm("mov.b64 %0, {%1, %2};" : "=l"(d) : "f"(x), "f"(y));
    return d;
}
__device__ __forceinline__ void unpack2(unsigned long long p, float& lo, float& hi) {
    asm("mov.b64 {%0, %1}, %2;" : "=f"(lo), "=f"(hi) : "l"(p));
}

__device__ __forceinline__ float fast_sigmoid(float x) {
    return 1.f / (1.f + __expf(-x));
}
__device__ __forceinline__ float fast_tanh(float x) {
    float r;
    asm("tanh.approx.f32 %0, %1;" : "=f"(r) : "f"(x));
    return r;
}

// per-direction software grid barrier (graph-capturable)
__device__ __forceinline__ void dir_barrier(int dir, unsigned int nb) {
    __syncthreads();
    if (threadIdx.x == 0) {
        __threadfence();
        unsigned int gen = *(volatile unsigned int*)&g_barg[dir];
        unsigned int arrived = atomicAdd(&g_barc[dir], 1u);
        if (arrived == nb - 1u) {
            g_barc[dir] = 0u;
            __threadfence();
            atomicExch(&g_barg[dir], gen + 1u);
        } else {
            while (*(volatile unsigned int*)&g_barg[dir] == gen) { __nanosleep(20); }
        }
        __threadfence();
    }
    __syncthreads();
}

// ---------------- fused weight split: 8 jobs, all fp16 hi/lo ----------------
struct SplitJobs {
    const float* src[8];
    __half* hi[8];
    __half* lo[8];
    unsigned int n4[8];
};
__global__ void split_w_kernel(SplitJobs jobs) {
    const int j = blockIdx.y;
    const float4* s = (const float4*)jobs.src[j];
    ushort4* hi = (ushort4*)jobs.hi[j];
    ushort4* lo = (ushort4*)jobs.lo[j];
    const unsigned int n4 = jobs.n4[j];
    for (unsigned int i = blockIdx.x * blockDim.x + threadIdx.x; i < n4;
         i += gridDim.x * blockDim.x) {
        float4 v = s[i];
        __half h0 = __float2half(v.x), h1 = __float2half(v.y);
        __half h2 = __float2half(v.z), h3 = __float2half(v.w);
        ushort4 hv, lv;
        hv.x = __half_as_ushort(h0); hv.y = __half_as_ushort(h1);
        hv.z = __half_as_ushort(h2); hv.w = __half_as_ushort(h3);
        lv.x = __half_as_ushort(__float2half(v.x - __half2float(h0)));
        lv.y = __half_as_ushort(__float2half(v.y - __half2float(h1)));
        lv.z = __half_as_ushort(__float2half(v.z - __half2float(h2)));
        lv.w = __half_as_ushort(__float2half(v.w - __half2float(h3)));
        hi[i] = hv;
        lo[i] = lv;
    }
}

// ---------------- encoder FFMA2 GEMM (optional fused fp16 output) ----------------
__global__ void __launch_bounds__(256) gemm_nt_kernel(
    const float* __restrict__ A, const float* __restrict__ W,
    const float* __restrict__ bias, float* __restrict__ C,
    __half* __restrict__ Of16,
    int K, int ldc, int coff, int leaky)
{
    __shared__ float As[8][128];
    __shared__ float Bs[8][128];
    const int tid = threadIdx.x;
    const int bx = blockIdx.x, by = blockIdx.y;
    const int tx = tid & 15, ty = tid >> 4;
    const int r  = tid >> 1;
    const int cq = (tid & 1) * 4;
    const float* Ap = A + (size_t)(by * 128 + r) * K + cq;
    const float* Wp = W + (size_t)(bx * 128 + r) * K + cq;

    unsigned long long acc[8][4];
#pragma unroll
    for (int m = 0; m < 8; m++)
#pragma unroll
        for (int p = 0; p < 4; p++) acc[m][p] = 0ULL;

    const int nkt = K >> 3;
    for (int kt = 0; kt < nkt; kt++) {
        __syncthreads();
        float4 av = *(const float4*)(Ap + kt * 8);
        float4 wv = *(const float4*)(Wp + kt * 8);
        As[cq + 0][r] = av.x; As[cq + 1][r] = av.y; As[cq + 2][r] = av.z; As[cq + 3][r] = av.w;
        Bs[cq + 0][r] = wv.x; Bs[cq + 1][r] = wv.y; Bs[cq + 2][r] = wv.z; Bs[cq + 3][r] = wv.w;
        __syncthreads();
#pragma unroll
        for (int k = 0; k < 8; k++) {
            float4 a0 = *(const float4*)&As[k][ty * 8];
            float4 a1 = *(const float4*)&As[k][ty * 8 + 4];
            ulonglong2 bq0 = *(const ulonglong2*)&Bs[k][tx * 8];
            ulonglong2 bq1 = *(const ulonglong2*)&Bs[k][tx * 8 + 4];
            float a[8] = {a0.x, a0.y, a0.z, a0.w, a1.x, a1.y, a1.z, a1.w};
#pragma unroll
            for (int m = 0; m < 8; m++) {
                unsigned long long ap = pack2(a[m], a[m]);
                acc[m][0] = ffma2(ap, bq0.x, acc[m][0]);
                acc[m][1] = ffma2(ap, bq0.y, acc[m][1]);
                acc[m][2] = ffma2(ap, bq1.x, acc[m][2]);
                acc[m][3] = ffma2(ap, bq1.y, acc[m][3]);
            }
        }
    }
#pragma unroll
    for (int m = 0; m < 8; m++) {
        const int row = by * 128 + ty * 8 + m;
        const size_t rbase = (size_t)row * ldc + coff;
#pragma unroll
        for (int p = 0; p < 4; p++) {
            float lo, hi;
            unpack2(acc[m][p], lo, hi);
            const int nn = bx * 128 + tx * 8 + p * 2;
            float v0 = lo + bias[nn];
            float v1 = hi + bias[nn + 1];
            if (leaky) {
                v0 = (v0 >= 0.f) ? v0 : 0.2f * v0;
                v1 = (v1 >= 0.f) ? v1 : 0.2f * v1;
            }
            if (Of16) {
                Of16[rbase + nn]     = __float2half(v0);
                Of16[rbase + nn + 1] = __float2half(v1);
            } else {
                C[rbase + nn]     = v0;
                C[rbase + nn + 1] = v1;
            }
        }
    }
}

// ---------------- fp16x2 mma.sync GEMM, 512 thr, BK=32, 4-stage pipeline ----------------
#define GI_STAGE 30720                    // bytes per stage: 3 matrices x 10240
#define GI_SMEM  (4 * GI_STAGE)           // 122880
__global__ void __launch_bounds__(512) gemm_f16x2(
    const __half* __restrict__ Af, const __half* __restrict__ Whi,
    const __half* __restrict__ Wlo,
    const float* __restrict__ bias, float* __restrict__ C, int K, int ldc)
{
    extern __shared__ char smem[];
    const uint32_t sb = saddr(smem);

    const int tid = threadIdx.x, lane = tid & 31, warp = tid >> 5;
    const int wm = warp & 3, wn = warp >> 2;
    const int bx = blockIdx.x, by = blockIdx.y;

    float acc[2][4][4];
#pragma unroll
    for (int mt = 0; mt < 2; mt++)
#pragma unroll
        for (int nt = 0; nt < 4; nt++)
#pragma unroll
            for (int i = 0; i < 4; i++) acc[mt][nt][i] = 0.f;

    const int nkt = K >> 5;
    const int lrow = tid >> 2, lkc = tid & 3;
    const uint32_t so = (uint32_t)(lrow * 80 + lkc * 16);
    const __half* pa   = Af  + (size_t)(by * 128 + lrow) * K + lkc * 8;
    const __half* pb_h = Whi + (size_t)(bx * 128 + lrow) * K + lkc * 8;
    const __half* pb_l = Wlo + (size_t)(bx * 128 + lrow) * K + lkc * 8;

#define GI_LOAD(KT) do {                                   \
        const uint32_t st_ = sb + ((KT) & 3) * GI_STAGE;   \
        const int ko_ = (KT) * 32;                         \
        cpa16(st_ + so,          pa   + ko_);              \
        cpa16(st_ + 10240 + so,  pb_h + ko_);              \
        cpa16(st_ + 20480 + so,  pb_l + ko_);              \
    } while (0)

    GI_LOAD(0); cpa_commit();
    GI_LOAD(1); cpa_commit();
    GI_LOAD(2); cpa_commit();

    for (int kt = 0; kt < nkt; kt++) {
        cpa_wait2();
        __syncthreads();
        if (kt + 3 < nkt) GI_LOAD(kt + 3);
        cpa_commit();

        const uint32_t st = sb + (kt & 3) * GI_STAGE;
#pragma unroll
        for (int ks = 0; ks < 2; ks++) {
            const int kk = ks * 16;
            uint32_t ah[2][4];
#pragma unroll
            for (int mt = 0; mt < 2; mt++) {
                const int ar = wm * 32 + mt * 16 + (lane & 15);
                const int ac = kk + (lane >> 4) * 8;
                ldmx4(ah[mt], st + ar * 80 + ac * 2);
            }
            uint32_t bh[2][4], bl[2][4];
#pragma unroll
            for (int pr = 0; pr < 2; pr++) {
                const int br = wn * 32 + pr * 16 + (lane & 7) + ((lane >> 4) << 3);
                const int bc = kk + (((lane >> 3) & 1) << 3);
                ldmx4(bh[pr], st + 10240 + br * 80 + bc * 2);
                ldmx4(bl[pr], st + 20480 + br * 80 + bc * 2);
            }
#pragma unroll
            for (int mt = 0; mt < 2; mt++)
#pragma unroll
                for (int nt = 0; nt < 4; nt++) {
                    const uint32_t* bhp = &bh[nt >> 1][(nt & 1) * 2];
                    const uint32_t* blp = &bl[nt >> 1][(nt & 1) * 2];
                    mma_f16(acc[mt][nt], ah[mt], bhp);
                    mma_f16(acc[mt][nt], ah[mt], blp);
                }
        }
    }
#undef GI_LOAD

#pragma unroll
    for (int mt = 0; mt < 2; mt++) {
        const int r0 = by * 128 + wm * 32 + mt * 16 + (lane >> 2);
#pragma unroll
        for (int nt = 0; nt < 4; nt++) {
            const int c0 = bx * 128 + wn * 32 + nt * 8 + 2 * (lane & 3);
            const float b0 = bias[c0], b1 = bias[c0 + 1];
            C[(size_t)r0 * ldc + c0]           = acc[mt][nt][0] + b0;
            C[(size_t)r0 * ldc + c0 + 1]       = acc[mt][nt][1] + b1;
            C[(size_t)(r0 + 8) * ldc + c0]     = acc[mt][nt][2] + b0;
            C[(size_t)(r0 + 8) * ldc + c0 + 1] = acc[mt][nt][3] + b1;
        }
    }
}

// ---------------- zero hidden state ----------------
__global__ void zero_h_kernel() {
    const int n = 4 * BB * HH;
    float* pf = &g_hf[0][0][0];
    __half* ph = &g_h16[0][0][0];
    for (int i = blockIdx.x * blockDim.x + threadIdx.x; i < n;
         i += gridDim.x * blockDim.x) {
        pf[i] = 0.f;
        ph[i] = __float2half(0.f);
    }
}

// ---------------- persistent GRU layer: fp16x2, W resident, BK=64, 2-stage H ----------------
#define WLO_OFF 99072     // bytes (48 rows * 2064)
#define HST_BASE 198144   // bytes
#define HST_STAGE 8192    // single fp16 H buffer: 64 rows x 128B
#define GRU_SMEM_BYTES (HST_BASE + 2 * HST_STAGE)   // 214528
__global__ void __launch_bounds__(256, 1) gru_mma_kernel(
    const float* __restrict__ gif, const float* __restrict__ gib,
    const __half* __restrict__ whf_hi, const __half* __restrict__ whf_lo,
    const __half* __restrict__ whb_hi, const __half* __restrict__ whb_lo,
    const float* __restrict__ bhhf, const float* __restrict__ bhhb,
    float* __restrict__ y, __half* __restrict__ yf16)
{
    extern __shared__ char smem[];
    const uint32_t sb = saddr(smem);
    float* Cs = (float*)(smem + HST_BASE);

    const int tid = threadIdx.x, lane = tid & 31, warp = tid >> 5;
    const int dir = blockIdx.x >> 6;
    const int j0  = (blockIdx.x & 63) << 4;
    const int wm = warp & 3, wn = warp >> 2;
    const int m0 = wm * 16, n0 = wn * 24;

    const float* gi   = dir ? gib    : gif;
    const __half* whh = dir ? whb_hi : whf_hi;
    const __half* whl = dir ? whb_lo : whf_lo;
    const float* bhh  = dir ? bhhb   : bhhf;

    const int ep_b [4] = { tid >> 4, (tid + 256) >> 4, (tid + 512) >> 4, (tid + 768) >> 4 };
    const int ep_jj = tid & 15;
    const int ep_j  = j0 + ep_jj;
    const float bh_r = bhh[ep_j];
    const float bh_z = bhh[HH + ep_j];
    const float bh_n = bhh[2 * HH + ep_j];

    // ---- load W slice (fp16 hi+lo) into smem once ----
    for (int i = tid; i < 6144; i += 256) {
        const int row = i >> 7, kc = i & 127;
        const int grow = (row >> 4) * HH + j0 + (row & 15);
        const uint32_t dst = sb + (uint32_t)(row * 2064 + kc * 16);
        cpa16(dst,           whh + (size_t)grow * HH + kc * 8);
        cpa16(dst + WLO_OFF, whl + (size_t)grow * HH + kc * 8);
    }
    cpa_commit();
    cpa_wait0();
    __syncthreads();

    const uint32_t sWh = sb;
    const uint32_t sWl = sb + WLO_OFF;

    const int hl_b0 = tid >> 3;
    const int hl_c  = tid & 7;

    for (int s = 0; s < TT; s++) {
        const int t_idx = dir ? (TT - 1 - s) : s;
        const int rb = s & 1;
        const __half* h16 = g_h16[dir][rb];
        const float* hpf = g_hf[dir][rb];
        float* hnf = g_hf[dir][rb ^ 1];
        __half* hn16 = g_h16[dir][rb ^ 1];

        float pre_gr[4], pre_gz[4], pre_gn[4], pre_hp[4];
#pragma unroll
        for (int p = 0; p < 4; p++) {
            const size_t gbase = (size_t)(ep_b[p] * TT + t_idx) * G3;
            pre_gr[p] = __ldg(gi + gbase + ep_j);
            pre_gz[p] = __ldg(gi + gbase + HH + ep_j);
            pre_gn[p] = __ldg(gi + gbase + 2 * HH + ep_j);
            pre_hp[p] = __ldg(hpf + ep_b[p] * HH + ep_j);
        }

        float acc[3][4];
#pragma unroll
        for (int nt = 0; nt < 3; nt++)
#pragma unroll
            for (int i = 0; i < 4; i++) acc[nt][i] = 0.f;

#define H_LOAD(KT) do {                                                          \
        const uint32_t st_ = sb + HST_BASE + ((KT) & 1) * HST_STAGE;             \
        const int ko_ = (KT) * 64;                                               \
        _Pragma("unroll")                                                        \
        for (int i_ = 0; i_ < 2; i_++) {                                         \
            const int b_ = hl_b0 + i_ * 32;                                      \
            const uint32_t off_ = (uint32_t)(b_ * 128 +                          \
                                  ((hl_c * 16) ^ ((b_ & 7) << 4)));              \
            cpa16(st_ + off_, h16 + (size_t)b_ * HH + ko_ + hl_c * 8);           \
        }                                                                        \
    } while (0)

        H_LOAD(0);
        cpa_commit();

        for (int kt = 0; kt < 16; kt++) {
            if (kt + 1 < 16) {
                H_LOAD(kt + 1);
                cpa_commit();
                cpa_wait1();
            } else {
                cpa_wait0();
            }
            __syncthreads();          // PUBLISH stage kt across warps

            const uint32_t Hh = sb + HST_BASE + (kt & 1) * HST_STAGE;
#pragma unroll
            for (int ks = 0; ks < 4; ks++) {
                uint32_t ah[4];
                const int ar = m0 + (lane & 15);
                const uint32_t aoff = (uint32_t)(ar * 128 +
                    ((ks * 32 + (lane >> 4) * 16) ^ ((ar & 7) << 4)));
                ldmx4(ah, Hh + aoff);
                const int kcolg = kt * 64 + ks * 16 + (((lane >> 3) & 1) << 3);
                uint32_t bh4[4], bl4[4], bh2[2], bl2[2];
                {
                    const int brp = n0 + (lane & 7) + ((lane >> 4) << 3);
                    ldmx4(bh4, sWh + brp * 2064 + kcolg * 2);
                    ldmx4(bl4, sWl + brp * 2064 + kcolg * 2);
                    const int br2 = n0 + 16 + (lane & 7);
                    ldmx2(bh2, sWh + br2 * 2064 + kcolg * 2);
                    ldmx2(bl2, sWl + br2 * 2064 + kcolg * 2);
                }
                mma_f16(acc[0], ah, &bh4[0]);
                mma_f16(acc[0], ah, &bl4[0]);
                mma_f16(acc[1], ah, &bh4[2]);
                mma_f16(acc[1], ah, &bl4[2]);
                mma_f16(acc[2], ah, bh2);
                mma_f16(acc[2], ah, bl2);
            }
            __syncthreads();          // PROTECT buffer kt&1 before next H_LOAD(kt+2)
        }
#undef H_LOAD

#pragma unroll
        for (int nt = 0; nt < 3; nt++) {
            const int cr = m0 + (lane >> 2);
            const int cc = n0 + nt * 8 + 2 * (lane & 3);
            Cs[cr * 52 + cc]           = acc[nt][0];
            Cs[cr * 52 + cc + 1]       = acc[nt][1];
            Cs[(cr + 8) * 52 + cc]     = acc[nt][2];
            Cs[(cr + 8) * 52 + cc + 1] = acc[nt][3];
        }
        __syncthreads();

#pragma unroll
        for (int p = 0; p < 4; p++) {
            const int b = ep_b[p];
            const float cr = Cs[b * 52 + ep_jj]      + bh_r;
            const float cz = Cs[b * 52 + 16 + ep_jj] + bh_z;
            const float cn = Cs[b * 52 + 32 + ep_jj] + bh_n;
            const float rr = fast_sigmoid(pre_gr[p] + cr);
            const float zz = fast_sigmoid(pre_gz[p] + cz);
            const float nn = fast_tanh(pre_gn[p] + rr * cn);
            const float hp = pre_hp[p];
            const float hn = (1.f - zz) * nn + zz * hp;
            hnf[b * HH + ep_j] = hn;
            hn16[b * HH + ep_j] = __float2half(hn);
            const size_t yb = (size_t)(b * TT + t_idx) * (2 * HH) + dir * HH + ep_j;
            y[yb] = hn;
            yf16[yb] = __float2half(hn);
        }
        dir_barrier(dir, 64);
    }
}

// ---------------- final mean ----------------
__global__ void mean_kernel(const float* __restrict__ y, float* __restrict__ out) {
    const int b = blockIdx.x;
    const int tid = threadIdx.x;
    const size_t base = (size_t)b * TT * 2 * HH;
    float s = 0.f;
    for (int i = tid; i < TT * 2 * HH; i += 256) s += y[base + i];
    __shared__ float red[256];
    red[tid] = s;
    __syncthreads();
    for (int o = 128; o > 0; o >>= 1) {
        if (tid < o) red[tid] += red[tid + o];
        __syncthreads();
    }
    if (tid == 0) out[b] = red[0] / (float)(TT * 2 * HH);
}

// ---------------- launcher ----------------
extern "C" void kernel_launch(void* const* d_in, const int* in_sizes, int n_in,
                              void* d_out, int out_size)
{
    const float* cond     = (const float*)d_in[0];
    const float* input    = (const float*)d_in[1];
    const float* ce_w1    = (const float*)d_in[2];
    const float* ce_b1    = (const float*)d_in[3];
    const float* ce_w2    = (const float*)d_in[4];
    const float* ce_b2    = (const float*)d_in[5];
    const float* me_w1    = (const float*)d_in[6];
    const float* me_b1    = (const float*)d_in[7];
    const float* me_w2    = (const float*)d_in[8];
    const float* me_b2    = (const float*)d_in[9];
    const float* w_ih_l0f = (const float*)d_in[10];
    const float* w_hh_l0f = (const float*)d_in[11];
    const float* b_ih_l0f = (const float*)d_in[12];
    const float* b_hh_l0f = (const float*)d_in[13];
    const float* w_ih_l0b = (const float*)d_in[14];
    const float* w_hh_l0b = (const float*)d_in[15];
    const float* b_ih_l0b = (const float*)d_in[16];
    const float* b_hh_l0b = (const float*)d_in[17];
    const float* w_ih_l1f = (const float*)d_in[18];
    const float* w_hh_l1f = (const float*)d_in[19];
    const float* b_ih_l1f = (const float*)d_in[20];
    const float* b_hh_l1f = (const float*)d_in[21];
    const float* w_ih_l1b = (const float*)d_in[22];
    const float* w_hh_l1b = (const float*)d_in[23];
    const float* b_ih_l1b = (const float*)d_in[24];
    const float* b_hh_l1b = (const float*)d_in[25];
    float* out = (float*)d_out;

    void* p;
    cudaGetSymbolAddress(&p, g_h1);    float*  s_h1   = (float*)p;
    cudaGetSymbolAddress(&p, g_y);     float*  s_y    = (float*)p;
    cudaGetSymbolAddress(&p, g_xf16);  __half* s_xf16 = (__half*)p;
    cudaGetSymbolAddress(&p, g_yf16);  __half* s_yf16 = (__half*)p;
    cudaGetSymbolAddress(&p, g_gif);   float*  s_gif  = (float*)p;
    cudaGetSymbolAddress(&p, g_gib);   float*  s_gib  = (float*)p;
    cudaGetSymbolAddress(&p, g_wihh);  __half* s_wih_h = (__half*)p;
    cudaGetSymbolAddress(&p, g_wihl);  __half* s_wih_l = (__half*)p;
    cudaGetSymbolAddress(&p, g_whhh);  __half* s_whh_h = (__half*)p;
    cudaGetSymbolAddress(&p, g_whhl);  __half* s_whh_l = (__half*)p;

    cudaFuncSetAttribute(gemm_f16x2, cudaFuncAttributeMaxDynamicSharedMemorySize, GI_SMEM);
    cudaFuncSetAttribute(gru_mma_kernel, cudaFuncAttributeMaxDynamicSharedMemorySize, GRU_SMEM_BYTES);

    const size_t WIH0 = (size_t)G3 * HH;
    const size_t WHH  = (size_t)G3 * HH;

    SplitJobs jobs;
    jobs.src[0] = w_ih_l0f; jobs.hi[0] = s_wih_h;           jobs.lo[0] = s_wih_l;           jobs.n4[0] = (unsigned)(WIH0 >> 2);
    jobs.src[1] = w_ih_l0b; jobs.hi[1] = s_wih_h + WIH0;    jobs.lo[1] = s_wih_l + WIH0;    jobs.n4[1] = (unsigned)(WIH0 >> 2);
    jobs.src[2] = w_ih_l1f; jobs.hi[2] = s_wih_h + 2*WIH0;  jobs.lo[2] = s_wih_l + 2*WIH0;  jobs.n4[2] = (unsigned)(WIH0 >> 1);
    jobs.src[3] = w_ih_l1b; jobs.hi[3] = s_wih_h + 4*WIH0;  jobs.lo[3] = s_wih_l + 4*WIH0;  jobs.n4[3] = (unsigned)(WIH0 >> 1);
    jobs.src[4] = w_hh_l0f; jobs.hi[4] = s_whh_h;           jobs.lo[4] = s_whh_l;           jobs.n4[4] = (unsigned)(WHH >> 2);
    jobs.src[5] = w_hh_l0b; jobs.hi[5] = s_whh_h + WHH;     jobs.lo[5] = s_whh_l + WHH;     jobs.n4[5] = (unsigned)(WHH >> 2);
    jobs.src[6] = w_hh_l1f; jobs.hi[6] = s_whh_h + 2*WHH;   jobs.lo[6] = s_whh_l + 2*WHH;   jobs.n4[6] = (unsigned)(WHH >> 2);
    jobs.src[7] = w_hh_l1b; jobs.hi[7] = s_whh_h + 3*WHH;   jobs.lo[7] = s_whh_l + 3*WHH;   jobs.n4[7] = (unsigned)(WHH >> 2);
    split_w_kernel<<<dim3(160, 8), 256>>>(jobs);

    dim3 blk(256);
    gemm_nt_kernel<<<dim3(H4 / 128, MR / 128), blk>>>(cond,  ce_w1, ce_b1, s_h1, nullptr, CONDD, H4,  0,   1);
    gemm_nt_kernel<<<dim3(H2 / 128, MR / 128), blk>>>(s_h1,  ce_w2, ce_b2, nullptr, s_xf16, H4,   HH,  0,   0);
    gemm_nt_kernel<<<dim3(H4 / 128, MR / 128), blk>>>(input, me_w1, me_b1, s_h1, nullptr, OUTD,  H4,  0,   1);
    gemm_nt_kernel<<<dim3(H2 / 128, MR / 128), blk>>>(s_h1,  me_w2, me_b2, nullptr, s_xf16, H4,   HH,  512, 0);

    dim3 blk2(512);
    gemm_f16x2<<<dim3(G3 / 128, MR / 128), blk2, GI_SMEM>>>(
        s_xf16, s_wih_h, s_wih_l, b_ih_l0f, s_gif, HH, G3);
    gemm_f16x2<<<dim3(G3 / 128, MR / 128), blk2, GI_SMEM>>>(
        s_xf16, s_wih_h + WIH0, s_wih_l + WIH0, b_ih_l0b, s_gib, HH, G3);
    zero_h_kernel<<<64, 256>>>();
    gru_mma_kernel<<<128, 256, GRU_SMEM_BYTES>>>(
        s_gif, s_gib,
        s_whh_h, s_whh_l, s_whh_h + WHH, s_whh_l + WHH,
        b_hh_l0f, b_hh_l0b, s_y, s_yf16);

    gemm_f16x2<<<dim3(G3 / 128, MR / 128), blk2, GI_SMEM>>>(
        s_yf16, s_wih_h + 2*WIH0, s_wih_l + 2*WIH0, b_ih_l1f, s_gif, 2 * HH, G3);
    gemm_f16x2<<<dim3(G3 / 128, MR / 128), blk2, GI_SMEM>>>(
        s_yf16, s_wih_h + 4*WIH0, s_wih_l + 4*WIH0, b_ih_l1b, s_gib, 2 * HH, G3);
    zero_h_kernel<<<64, 256>>>();
    gru_mma_kernel<<<128, 256, GRU_SMEM_BYTES>>>(
        s_gif, s_gib,
        s_whh_h + 2*WHH, s_whh_l + 2*WHH, s_whh_h + 3*WHH, s_whh_l + 3*WHH,
        b_hh_l1f, b_hh_l1b, s_y, s_yf16);

    mean_kernel<<<BB, 256>>>(s_y, out);
}